// round 2
// baseline (speedup 1.0000x reference)
#include <cuda_runtime.h>
#include <math.h>

#define E_ 8
#define B_ 16384
#define NAG 64
#define H_ 512
#define A_ 8
#define D_ 64
#define EB (E_*B_)

// ---------------- scratch (device globals; no allocation allowed) ----------------
__device__ float g_encs[EB * H_];     // [E*B, 512]
__device__ float g_keys[EB * H_];     // [E*B, 512]  col c = a*64+d
__device__ float g_vals[EB * H_];     // [E*B, 512]
__device__ float g_pre[B_ * H_];      // [B, 512]
__device__ float g_sel[B_ * H_];      // [B, 512]    col c = a*64+d
__device__ float g_x[B_ * H_];        // [B, 512]
__device__ float g_Wkf[H_ * H_];      // [h, c] repacked Wk
__device__ float g_Wvf[H_ * H_];
__device__ float g_Wself[H_ * H_];
__device__ float g_part_sum[E_ * 32 * 64];
__device__ float g_part_sq[E_ * 32 * 64];
__device__ float g_mu[E_ * 64];
__device__ float g_rs[E_ * 64];

// ---------------- batchnorm stats ----------------
__global__ void bn_part_kernel(const float* __restrict__ states) {
    int e = blockIdx.x, ch = blockIdx.y;
    int n = threadIdx.x, ty = threadIdx.y;
    const float* base = states + ((size_t)e * B_ + (size_t)ch * 512) * 64;
    float s = 0.f, q = 0.f;
    for (int r = ty; r < 512; r += 4) {
        float v = base[(size_t)r * 64 + n];
        s += v; q += v * v;
    }
    __shared__ float ss[4][64], sq[4][64];
    ss[ty][n] = s; sq[ty][n] = q;
    __syncthreads();
    if (ty == 0) {
        s = ss[0][n] + ss[1][n] + ss[2][n] + ss[3][n];
        q = sq[0][n] + sq[1][n] + sq[2][n] + sq[3][n];
        g_part_sum[(e * 32 + ch) * 64 + n] = s;
        g_part_sq [(e * 32 + ch) * 64 + n] = q;
    }
}

__global__ void bn_final_kernel() {
    int i = threadIdx.x;            // 0..511 -> (e,n)
    int e = i >> 6, n = i & 63;
    float s = 0.f, q = 0.f;
    for (int j = 0; j < 32; j++) {
        s += g_part_sum[(e * 32 + j) * 64 + n];
        q += g_part_sq [(e * 32 + j) * 64 + n];
    }
    float mean = s * (1.f / B_);
    float var  = q * (1.f / B_) - mean * mean;
    g_mu[i] = mean;
    g_rs[i] = 1.f / sqrtf(var + 1e-5f);
}

// ---------------- weight repack: W[a][h][d] -> Wf[h][a*64+d] ----------------
__global__ void repack_kernel(const float* __restrict__ Wk,
                              const float* __restrict__ Wv,
                              const float* __restrict__ Wsel) {
    int i = blockIdx.x * 256 + threadIdx.x;   // over 512*512
    int h = i >> 9, c = i & 511;
    int a = c >> 6, dd = c & 63;
    int src = a * (H_ * D_) + h * D_ + dd;
    g_Wkf[i]   = Wk[src];
    g_Wvf[i]   = Wv[src];
    g_Wself[i] = Wsel[src];
}

// ---------------- generic tiled GEMM: C = act(A[M,K] @ W[K,NC] + bias) ----------------
// ACT: 0 none, 1 leaky(0.01), 2 relu, 3 clip[-20,2]
// NORM: A element (row in encoder e = m/B_) transformed by (v - mu[e*64+k]) * rs[...],
//       with W/bias advanced by e (per-encoder weights, W_enc layout [E,N,H]).
template<int ACT>
__device__ __forceinline__ float act_fn(float v) {
    if constexpr (ACT == 1) return v >= 0.f ? v : 0.01f * v;
    else if constexpr (ACT == 2) return fmaxf(v, 0.f);
    else if constexpr (ACT == 3) return fminf(fmaxf(v, -20.f), 2.f);
    else return v;
}

template<int ACT, bool HAS_BIAS, bool NORM>
__global__ __launch_bounds__(256) void gemm_kernel(
    const float* __restrict__ A, const float* __restrict__ W,
    const float* __restrict__ bias, float* __restrict__ C,
    int M, int K, int NC)
{
    __shared__ float As[16][128];
    __shared__ float Ws[16][64];
    const int tid = threadIdx.x;
    const int m0 = blockIdx.y * 128;
    const int n0 = blockIdx.x * 64;
    int e = 0;
    if constexpr (NORM) {
        e = m0 / B_;
        W += (size_t)e * K * NC;
        if constexpr (HAS_BIAS) bias += (size_t)e * NC;
    }
    const int tr = tid >> 4, tc = tid & 15;
    const int ar = tid >> 2, ac = (tid & 3) << 2;
    const int wr = tid >> 4, wc = (tid & 15) << 2;
    const float* Aptr  = A + (size_t)(m0 + ar) * K + ac;
    const float* Aptr2 = Aptr + (size_t)64 * K;
    const float* Wptr  = W + (size_t)wr * NC + n0 + wc;
    float acc[8][4] = {};
    float4 a0, a1, w0;

    auto loadTile = [&](int kt) {
        a0 = *(const float4*)(Aptr  + kt * 16);
        a1 = *(const float4*)(Aptr2 + kt * 16);
        if constexpr (NORM) {
            int kb = e * 64 + kt * 16 + ac;
            float m0v = g_mu[kb+0], r0v = g_rs[kb+0];
            float m1v = g_mu[kb+1], r1v = g_rs[kb+1];
            float m2v = g_mu[kb+2], r2v = g_rs[kb+2];
            float m3v = g_mu[kb+3], r3v = g_rs[kb+3];
            a0.x = (a0.x - m0v) * r0v; a0.y = (a0.y - m1v) * r1v;
            a0.z = (a0.z - m2v) * r2v; a0.w = (a0.w - m3v) * r3v;
            a1.x = (a1.x - m0v) * r0v; a1.y = (a1.y - m1v) * r1v;
            a1.z = (a1.z - m2v) * r2v; a1.w = (a1.w - m3v) * r3v;
        }
        w0 = *(const float4*)(Wptr + (size_t)kt * 16 * NC);
    };

    loadTile(0);
    const int KT = K >> 4;
    for (int kt = 0; kt < KT; kt++) {
        As[ac+0][ar] = a0.x; As[ac+1][ar] = a0.y; As[ac+2][ar] = a0.z; As[ac+3][ar] = a0.w;
        As[ac+0][ar+64] = a1.x; As[ac+1][ar+64] = a1.y; As[ac+2][ar+64] = a1.z; As[ac+3][ar+64] = a1.w;
        *(float4*)&Ws[wr][wc] = w0;
        __syncthreads();
        if (kt + 1 < KT) loadTile(kt + 1);
        #pragma unroll
        for (int kk = 0; kk < 16; kk++) {
            float4 t0 = *(const float4*)&As[kk][tr * 8];
            float4 t1 = *(const float4*)&As[kk][tr * 8 + 4];
            float4 tw = *(const float4*)&Ws[kk][tc * 4];
            float a_[8] = {t0.x, t0.y, t0.z, t0.w, t1.x, t1.y, t1.z, t1.w};
            float w_[4] = {tw.x, tw.y, tw.z, tw.w};
            #pragma unroll
            for (int i = 0; i < 8; i++)
                #pragma unroll
                for (int j = 0; j < 4; j++)
                    acc[i][j] = fmaf(a_[i], w_[j], acc[i][j]);
        }
        __syncthreads();
    }

    float b4[4] = {0.f, 0.f, 0.f, 0.f};
    if constexpr (HAS_BIAS) {
        b4[0] = bias[n0 + tc*4 + 0]; b4[1] = bias[n0 + tc*4 + 1];
        b4[2] = bias[n0 + tc*4 + 2]; b4[3] = bias[n0 + tc*4 + 3];
    }
    #pragma unroll
    for (int i = 0; i < 8; i++) {
        float4 o;
        o.x = act_fn<ACT>(acc[i][0] + b4[0]);
        o.y = act_fn<ACT>(acc[i][1] + b4[1]);
        o.z = act_fn<ACT>(acc[i][2] + b4[2]);
        o.w = act_fn<ACT>(acc[i][3] + b4[3]);
        *(float4*)(C + (size_t)(m0 + tr * 8 + i) * NC + n0 + tc * 4) = o;
    }
}

// ---------------- attention: logits -> softmax -> weighted sum of vals ----------------
// per block: 2 batch rows, 64 threads each. smem-resident sel/keys rows.
__global__ __launch_bounds__(128) void attn_kernel(float* __restrict__ actor_in) {
    __shared__ float sel_s[2][512];
    __shared__ float key_s[2][8][516];   // pad 516 to spread e over banks
    __shared__ float w_s[2][64];
    int tid = threadIdx.x;
    int r = tid >> 6;
    int j = tid & 63;
    size_t b = (size_t)blockIdx.x * 2 + r;

    #pragma unroll
    for (int m = 0; m < 8; m++)
        sel_s[r][m * 64 + j] = g_sel[b * 512 + m * 64 + j];
    #pragma unroll
    for (int e = 0; e < 8; e++)
        #pragma unroll
        for (int m = 0; m < 8; m++)
            key_s[r][e][m * 64 + j] = g_keys[((size_t)e * B_ + b) * 512 + m * 64 + j];
    __syncthreads();

    int a = j >> 3, e = j & 7;
    float lg = 0.f;
    const float* sp = &sel_s[r][a * 64];
    const float* kp = &key_s[r][e][a * 64];
    #pragma unroll
    for (int d = 0; d < 64; d++) lg += sp[d] * kp[d];
    lg *= 0.125f;   // 1/sqrt(64)

    // softmax over e: groups of 8 consecutive lanes
    float mx = lg;
    #pragma unroll
    for (int o = 4; o >= 1; o >>= 1) mx = fmaxf(mx, __shfl_xor_sync(0xffffffffu, mx, o));
    float ex = expf(lg - mx);
    float sm = ex;
    #pragma unroll
    for (int o = 4; o >= 1; o >>= 1) sm += __shfl_xor_sync(0xffffffffu, sm, o);
    w_s[r][j] = ex / sm;   // [a*8+e]
    __syncthreads();

    // attn[b, c=(a=m, d=j)] = sum_e w[m][e] * vals[e][b][c]
    #pragma unroll
    for (int m = 0; m < 8; m++) {
        int c = m * 64 + j;
        float acc = 0.f;
        #pragma unroll
        for (int ee = 0; ee < 8; ee++)
            acc += w_s[r][m * 8 + ee] * g_vals[((size_t)ee * B_ + b) * 512 + c];
        actor_in[b * 512 + c] = acc;
    }
}

// ---------------- launch ----------------
extern "C" void kernel_launch(void* const* d_in, const int* in_sizes, int n_in,
                              void* d_out, int out_size) {
    const float* states      = (const float*)d_in[0];
    const float* pre_actions = (const float*)d_in[1];
    const float* W_enc       = (const float*)d_in[2];
    const float* b_enc       = (const float*)d_in[3];
    const float* W_pre       = (const float*)d_in[4];
    const float* b_pre       = (const float*)d_in[5];
    const float* Wk          = (const float*)d_in[6];
    const float* Wsel        = (const float*)d_in[7];
    const float* Wv          = (const float*)d_in[8];
    const float* bv          = (const float*)d_in[9];
    const float* W_actor     = (const float*)d_in[10];
    const float* b_actor     = (const float*)d_in[11];
    const float* W_mean      = (const float*)d_in[12];
    const float* b_mean      = (const float*)d_in[13];
    const float* W_logstd    = (const float*)d_in[14];
    const float* b_logstd    = (const float*)d_in[15];

    float* out        = (float*)d_out;
    float* out_mean   = out;                       // [B, 64]
    float* out_logstd = out + (size_t)B_ * NAG;    // [B, 64]
    float* out_actor  = out + (size_t)2 * B_ * NAG;// [B, 512]

    float *encs, *keys, *vals, *pre, *sel, *xbuf, *Wkf, *Wvf, *Wself;
    cudaGetSymbolAddress((void**)&encs,  g_encs);
    cudaGetSymbolAddress((void**)&keys,  g_keys);
    cudaGetSymbolAddress((void**)&vals,  g_vals);
    cudaGetSymbolAddress((void**)&pre,   g_pre);
    cudaGetSymbolAddress((void**)&sel,   g_sel);
    cudaGetSymbolAddress((void**)&xbuf,  g_x);
    cudaGetSymbolAddress((void**)&Wkf,   g_Wkf);
    cudaGetSymbolAddress((void**)&Wvf,   g_Wvf);
    cudaGetSymbolAddress((void**)&Wself, g_Wself);

    // BN stats
    bn_part_kernel<<<dim3(E_, 32), dim3(64, 4)>>>(states);
    bn_final_kernel<<<1, 512>>>();
    // per-head weight repack
    repack_kernel<<<1024, 256>>>(Wk, Wv, Wsel);
    // encs = leaky(snorm @ W_enc + b_enc)   [E*B, 512], K=64 (normalize fused)
    gemm_kernel<1, true, true><<<dim3(8, 1024), 256>>>(states, W_enc, b_enc, encs, EB, 64, 512);
    // keys = encs @ Wkf
    gemm_kernel<0, false, false><<<dim3(8, 1024), 256>>>(encs, Wkf, nullptr, keys, EB, 512, 512);
    // vals = leaky(encs @ Wvf + bv)   (bv flattened layout matches col = a*64+d)
    gemm_kernel<1, true, false><<<dim3(8, 1024), 256>>>(encs, Wvf, bv, vals, EB, 512, 512);
    // pre = leaky(pre_actions @ W_pre + b_pre)
    gemm_kernel<1, true, false><<<dim3(8, 128), 256>>>(pre_actions, W_pre, b_pre, pre, B_, 512, 512);
    // sel = pre @ Wself
    gemm_kernel<0, false, false><<<dim3(8, 128), 256>>>(pre, Wself, nullptr, sel, B_, 512, 512);
    // attention -> actor_in (third output region)
    attn_kernel<<<B_ / 2, 128>>>(out_actor);
    // x = relu(actor_in @ W_actor + b_actor)
    gemm_kernel<2, true, false><<<dim3(8, 128), 256>>>(out_actor, W_actor, b_actor, xbuf, B_, 512, 512);
    // mean = x @ W_mean + b_mean
    gemm_kernel<0, true, false><<<dim3(1, 128), 256>>>(xbuf, W_mean, b_mean, out_mean, B_, 512, 64);
    // log_std = clip(x @ W_logstd + b_logstd)
    gemm_kernel<3, true, false><<<dim3(1, 128), 256>>>(xbuf, W_logstd, b_logstd, out_logstd, B_, 512, 64);
}

// round 3
// speedup vs baseline: 1.2660x; 1.2660x over previous
#include <cuda_runtime.h>
#include <math.h>

#define E_ 8
#define B_ 16384
#define NAG 64
#define H_ 512
#define A_ 8
#define D_ 64
#define EB (E_*B_)

// ---------------- scratch (device globals; no allocation allowed) ----------------
__device__ float g_encs[EB * H_];     // [E*B, 512]
__device__ float g_vals[EB * H_];     // [E*B, 512]  col c = a*64+d
__device__ float g_selk[(size_t)A_ * B_ * H_]; // [a][B][512]
__device__ float g_pre[B_ * H_];      // [B, 512]
__device__ float g_sel[B_ * H_];      // [B, 512]    col c = a*64+d
__device__ float g_x[B_ * H_];        // [B, 512]
__device__ float g_WkT[A_ * D_ * H_]; // [a][d][h]
__device__ float g_Wvf[H_ * H_];      // [h][a*64+d]
__device__ float g_Wself[H_ * H_];
__device__ float g_part_sum[E_ * 32 * 64];
__device__ float g_part_sq[E_ * 32 * 64];
__device__ float g_mu[E_ * 64];
__device__ float g_rs[E_ * 64];

// ---------------- batchnorm stats ----------------
__global__ void bn_part_kernel(const float* __restrict__ states) {
    int e = blockIdx.x, ch = blockIdx.y;
    int n = threadIdx.x, ty = threadIdx.y;
    const float* base = states + ((size_t)e * B_ + (size_t)ch * 512) * 64;
    float s = 0.f, q = 0.f;
    for (int r = ty; r < 512; r += 4) {
        float v = base[(size_t)r * 64 + n];
        s += v; q += v * v;
    }
    __shared__ float ss[4][64], sq[4][64];
    ss[ty][n] = s; sq[ty][n] = q;
    __syncthreads();
    if (ty == 0) {
        s = ss[0][n] + ss[1][n] + ss[2][n] + ss[3][n];
        q = sq[0][n] + sq[1][n] + sq[2][n] + sq[3][n];
        g_part_sum[(e * 32 + ch) * 64 + n] = s;
        g_part_sq [(e * 32 + ch) * 64 + n] = q;
    }
}

__global__ void bn_final_kernel() {
    int i = threadIdx.x;            // 0..511 -> (e,n)
    float s = 0.f, q = 0.f;
    for (int j = 0; j < 32; j++) {
        int e = i >> 6, n = i & 63;
        s += g_part_sum[(e * 32 + j) * 64 + n];
        q += g_part_sq [(e * 32 + j) * 64 + n];
    }
    float mean = s * (1.f / B_);
    float var  = q * (1.f / B_) - mean * mean;
    g_mu[i] = mean;
    g_rs[i] = 1.f / sqrtf(var + 1e-5f);
}

// ---------------- weight repack ----------------
// Wv/Wsel: [a][h][d] -> [h][a*64+d].  Wk: [a][h][d] -> WkT [a][d][h].
__global__ void repack_kernel(const float* __restrict__ Wk,
                              const float* __restrict__ Wv,
                              const float* __restrict__ Wsel) {
    int i = blockIdx.x * 256 + threadIdx.x;   // over 512*512
    int h = i >> 9, c = i & 511;
    int a = c >> 6, dd = c & 63;
    int src = a * (H_ * D_) + h * D_ + dd;
    g_Wvf[i]   = Wv[src];
    g_Wself[i] = Wsel[src];
    g_WkT[a * (D_ * H_) + dd * H_ + h] = Wk[src];
}

// ---------------- activations ----------------
template<int ACT>
__device__ __forceinline__ float act_fn(float v) {
    if constexpr (ACT == 1) return v >= 0.f ? v : 0.01f * v;
    else if constexpr (ACT == 2) return fmaxf(v, 0.f);
    else if constexpr (ACT == 3) return fminf(fmaxf(v, -20.f), 2.f);
    else return v;
}

// ---------------- 128x128 tiled GEMM: C = act(A[M,K](lda) @ W[K,NC] + bias) ----------------
// NORM: per-encoder batchnorm of A element + per-encoder W/bias (W_enc layout [E,K,NC])
// PERHEAD: blockIdx.z = head a; A += a*64 (col offset), W += a*K*NC, C += a*B_*NC
template<int ACT, bool HAS_BIAS, bool NORM, bool PERHEAD>
__global__ __launch_bounds__(256) void gemm128(
    const float* __restrict__ A, const float* __restrict__ W,
    const float* __restrict__ bias, float* __restrict__ C,
    int M, int K, int NC, int lda)
{
    __shared__ float As[16][132];
    __shared__ float Ws[16][128];
    const int tid = threadIdx.x;
    const int m0 = blockIdx.y * 128;
    const int n0 = blockIdx.x * 128;
    if constexpr (PERHEAD) {
        int z = blockIdx.z;
        A += z * 64;
        W += (size_t)z * K * NC;
        C += (size_t)z * B_ * NC;
    }
    int e = 0;
    if constexpr (NORM) {
        e = m0 / B_;
        W += (size_t)e * K * NC;
        if constexpr (HAS_BIAS) bias += (size_t)e * NC;
    }
    const int tr = tid >> 4, tc = tid & 15;        // 16x16 thread grid, 8x8 each
    const int ar = tid >> 1, ac = (tid & 1) * 8;   // A tile load: 128 rows x 16 k
    const int wr = tid >> 4, wc = (tid & 15) * 8;  // W tile load: 16 k x 128 cols
    const float* Aptr = A + (size_t)(m0 + ar) * lda + ac;
    const float* Wptr = W + (size_t)wr * NC + n0 + wc;
    float acc[8][8] = {};
    float4 a0, a1, w0, w1;

    auto loadTile = [&](int kt) {
        a0 = *(const float4*)(Aptr + kt * 16);
        a1 = *(const float4*)(Aptr + kt * 16 + 4);
        if constexpr (NORM) {
            int kb = e * 64 + kt * 16 + ac;
            a0.x = (a0.x - g_mu[kb+0]) * g_rs[kb+0];
            a0.y = (a0.y - g_mu[kb+1]) * g_rs[kb+1];
            a0.z = (a0.z - g_mu[kb+2]) * g_rs[kb+2];
            a0.w = (a0.w - g_mu[kb+3]) * g_rs[kb+3];
            a1.x = (a1.x - g_mu[kb+4]) * g_rs[kb+4];
            a1.y = (a1.y - g_mu[kb+5]) * g_rs[kb+5];
            a1.z = (a1.z - g_mu[kb+6]) * g_rs[kb+6];
            a1.w = (a1.w - g_mu[kb+7]) * g_rs[kb+7];
        }
        w0 = *(const float4*)(Wptr + (size_t)kt * 16 * NC);
        w1 = *(const float4*)(Wptr + (size_t)kt * 16 * NC + 4);
    };

    loadTile(0);
    const int KT = K >> 4;
    for (int kt = 0; kt < KT; kt++) {
        As[ac+0][ar] = a0.x; As[ac+1][ar] = a0.y; As[ac+2][ar] = a0.z; As[ac+3][ar] = a0.w;
        As[ac+4][ar] = a1.x; As[ac+5][ar] = a1.y; As[ac+6][ar] = a1.z; As[ac+7][ar] = a1.w;
        *(float4*)&Ws[wr][wc]     = w0;
        *(float4*)&Ws[wr][wc + 4] = w1;
        __syncthreads();
        if (kt + 1 < KT) loadTile(kt + 1);
        #pragma unroll
        for (int kk = 0; kk < 16; kk++) {
            float4 af0 = *(const float4*)&As[kk][tr * 8];
            float4 af1 = *(const float4*)&As[kk][tr * 8 + 4];
            float4 wf0 = *(const float4*)&Ws[kk][tc * 8];
            float4 wf1 = *(const float4*)&Ws[kk][tc * 8 + 4];
            float a_[8] = {af0.x, af0.y, af0.z, af0.w, af1.x, af1.y, af1.z, af1.w};
            float w_[8] = {wf0.x, wf0.y, wf0.z, wf0.w, wf1.x, wf1.y, wf1.z, wf1.w};
            #pragma unroll
            for (int i = 0; i < 8; i++)
                #pragma unroll
                for (int j = 0; j < 8; j++)
                    acc[i][j] = fmaf(a_[i], w_[j], acc[i][j]);
        }
        __syncthreads();
    }

    float bb[8] = {0.f,0.f,0.f,0.f,0.f,0.f,0.f,0.f};
    if constexpr (HAS_BIAS) {
        #pragma unroll
        for (int j = 0; j < 8; j++) bb[j] = bias[n0 + tc * 8 + j];
    }
    #pragma unroll
    for (int i = 0; i < 8; i++) {
        float4 o0, o1;
        o0.x = act_fn<ACT>(acc[i][0] + bb[0]); o0.y = act_fn<ACT>(acc[i][1] + bb[1]);
        o0.z = act_fn<ACT>(acc[i][2] + bb[2]); o0.w = act_fn<ACT>(acc[i][3] + bb[3]);
        o1.x = act_fn<ACT>(acc[i][4] + bb[4]); o1.y = act_fn<ACT>(acc[i][5] + bb[5]);
        o1.z = act_fn<ACT>(acc[i][6] + bb[6]); o1.w = act_fn<ACT>(acc[i][7] + bb[7]);
        float* Crow = C + (size_t)(m0 + tr * 8 + i) * NC + n0 + tc * 8;
        *(float4*)Crow       = o0;
        *(float4*)(Crow + 4) = o1;
    }
}

// ---------------- legacy 128x64 GEMM for NC=64 outputs ----------------
template<int ACT, bool HAS_BIAS>
__global__ __launch_bounds__(256) void gemm_small(
    const float* __restrict__ A, const float* __restrict__ W,
    const float* __restrict__ bias, float* __restrict__ C,
    int M, int K, int NC)
{
    __shared__ float As[16][128];
    __shared__ float Ws[16][64];
    const int tid = threadIdx.x;
    const int m0 = blockIdx.y * 128;
    const int n0 = blockIdx.x * 64;
    const int tr = tid >> 4, tc = tid & 15;
    const int ar = tid >> 2, ac = (tid & 3) << 2;
    const int wr = tid >> 4, wc = (tid & 15) << 2;
    const float* Aptr  = A + (size_t)(m0 + ar) * K + ac;
    const float* Aptr2 = Aptr + (size_t)64 * K;
    const float* Wptr  = W + (size_t)wr * NC + n0 + wc;
    float acc[8][4] = {};
    float4 a0, a1, w0;

    auto loadTile = [&](int kt) {
        a0 = *(const float4*)(Aptr  + kt * 16);
        a1 = *(const float4*)(Aptr2 + kt * 16);
        w0 = *(const float4*)(Wptr + (size_t)kt * 16 * NC);
    };

    loadTile(0);
    const int KT = K >> 4;
    for (int kt = 0; kt < KT; kt++) {
        As[ac+0][ar] = a0.x; As[ac+1][ar] = a0.y; As[ac+2][ar] = a0.z; As[ac+3][ar] = a0.w;
        As[ac+0][ar+64] = a1.x; As[ac+1][ar+64] = a1.y; As[ac+2][ar+64] = a1.z; As[ac+3][ar+64] = a1.w;
        *(float4*)&Ws[wr][wc] = w0;
        __syncthreads();
        if (kt + 1 < KT) loadTile(kt + 1);
        #pragma unroll
        for (int kk = 0; kk < 16; kk++) {
            float4 t0 = *(const float4*)&As[kk][tr * 8];
            float4 t1 = *(const float4*)&As[kk][tr * 8 + 4];
            float4 tw = *(const float4*)&Ws[kk][tc * 4];
            float a_[8] = {t0.x, t0.y, t0.z, t0.w, t1.x, t1.y, t1.z, t1.w};
            float w_[4] = {tw.x, tw.y, tw.z, tw.w};
            #pragma unroll
            for (int i = 0; i < 8; i++)
                #pragma unroll
                for (int j = 0; j < 4; j++)
                    acc[i][j] = fmaf(a_[i], w_[j], acc[i][j]);
        }
        __syncthreads();
    }

    float b4[4] = {0.f, 0.f, 0.f, 0.f};
    if constexpr (HAS_BIAS) {
        b4[0] = bias[n0 + tc*4 + 0]; b4[1] = bias[n0 + tc*4 + 1];
        b4[2] = bias[n0 + tc*4 + 2]; b4[3] = bias[n0 + tc*4 + 3];
    }
    #pragma unroll
    for (int i = 0; i < 8; i++) {
        float4 o;
        o.x = act_fn<ACT>(acc[i][0] + b4[0]);
        o.y = act_fn<ACT>(acc[i][1] + b4[1]);
        o.z = act_fn<ACT>(acc[i][2] + b4[2]);
        o.w = act_fn<ACT>(acc[i][3] + b4[3]);
        *(float4*)(C + (size_t)(m0 + tr * 8 + i) * NC + n0 + tc * 4) = o;
    }
}

// ---------------- attention: logits (selk . encs) -> softmax -> weighted sum of vals ----------------
// 1 batch row per block, 64 threads. logits[a][e] = sum_h selk[a][b][h] * encs[e][b][h].
__global__ __launch_bounds__(64) void attn_kernel(float* __restrict__ actor_in) {
    __shared__ float sk[8][516];   // pad 516: stride%32=4 -> e rows hit distinct banks
    __shared__ float en[8][516];
    __shared__ float w_s[64];
    int j = threadIdx.x;
    size_t b = blockIdx.x;

    #pragma unroll
    for (int a = 0; a < 8; a++)
        #pragma unroll
        for (int m = 0; m < 8; m++)
            sk[a][m * 64 + j] = g_selk[((size_t)a * B_ + b) * 512 + m * 64 + j];
    #pragma unroll
    for (int e = 0; e < 8; e++)
        #pragma unroll
        for (int m = 0; m < 8; m++)
            en[e][m * 64 + j] = g_encs[((size_t)e * B_ + b) * 512 + m * 64 + j];
    __syncthreads();

    int a = j >> 3, e = j & 7;
    float lg = 0.f;
    const float* sp = sk[a];
    const float* ep = en[e];
    #pragma unroll 8
    for (int h = 0; h < 512; h++) lg = fmaf(sp[h], ep[h], lg);
    lg *= 0.125f;   // 1/sqrt(64)

    // softmax over e: groups of 8 consecutive lanes
    float mx = lg;
    #pragma unroll
    for (int o = 4; o >= 1; o >>= 1) mx = fmaxf(mx, __shfl_xor_sync(0xffffffffu, mx, o));
    float ex = expf(lg - mx);
    float sm = ex;
    #pragma unroll
    for (int o = 4; o >= 1; o >>= 1) sm += __shfl_xor_sync(0xffffffffu, sm, o);
    w_s[j] = ex / sm;   // index a*8+e
    __syncthreads();

    // attn[b, c=(a=m)*64 + (d=j)] = sum_e w[m][e] * vals[e][b][c]
    #pragma unroll
    for (int m = 0; m < 8; m++) {
        int c = m * 64 + j;
        float acc = 0.f;
        #pragma unroll
        for (int ee = 0; ee < 8; ee++)
            acc = fmaf(w_s[m * 8 + ee], g_vals[((size_t)ee * B_ + b) * 512 + c], acc);
        actor_in[b * 512 + c] = acc;
    }
}

// ---------------- launch ----------------
extern "C" void kernel_launch(void* const* d_in, const int* in_sizes, int n_in,
                              void* d_out, int out_size) {
    const float* states      = (const float*)d_in[0];
    const float* pre_actions = (const float*)d_in[1];
    const float* W_enc       = (const float*)d_in[2];
    const float* b_enc       = (const float*)d_in[3];
    const float* W_pre       = (const float*)d_in[4];
    const float* b_pre       = (const float*)d_in[5];
    const float* Wk          = (const float*)d_in[6];
    const float* Wsel        = (const float*)d_in[7];
    const float* Wv          = (const float*)d_in[8];
    const float* bv          = (const float*)d_in[9];
    const float* W_actor     = (const float*)d_in[10];
    const float* b_actor     = (const float*)d_in[11];
    const float* W_mean      = (const float*)d_in[12];
    const float* b_mean      = (const float*)d_in[13];
    const float* W_logstd    = (const float*)d_in[14];
    const float* b_logstd    = (const float*)d_in[15];

    float* out        = (float*)d_out;
    float* out_mean   = out;                       // [B, 64]
    float* out_logstd = out + (size_t)B_ * NAG;    // [B, 64]
    float* out_actor  = out + (size_t)2 * B_ * NAG;// [B, 512]

    float *encs, *vals, *selk, *pre, *sel, *xbuf, *WkT, *Wvf, *Wself;
    cudaGetSymbolAddress((void**)&encs,  g_encs);
    cudaGetSymbolAddress((void**)&vals,  g_vals);
    cudaGetSymbolAddress((void**)&selk,  g_selk);
    cudaGetSymbolAddress((void**)&pre,   g_pre);
    cudaGetSymbolAddress((void**)&sel,   g_sel);
    cudaGetSymbolAddress((void**)&xbuf,  g_x);
    cudaGetSymbolAddress((void**)&WkT,   g_WkT);
    cudaGetSymbolAddress((void**)&Wvf,   g_Wvf);
    cudaGetSymbolAddress((void**)&Wself, g_Wself);

    // BN stats + weight repack
    bn_part_kernel<<<dim3(E_, 32), dim3(64, 4)>>>(states);
    bn_final_kernel<<<1, 512>>>();
    repack_kernel<<<1024, 256>>>(Wk, Wv, Wsel);

    // encs = leaky(snorm @ W_enc + b_enc)   [E*B, 512], K=64 (normalize fused)
    gemm128<1, true, true, false><<<dim3(4, 1024), 256>>>(states, W_enc, b_enc, encs, EB, 64, 512, 64);
    // pre = leaky(pre_actions @ W_pre + b_pre)
    gemm128<1, true, false, false><<<dim3(4, 128), 256>>>(pre_actions, W_pre, b_pre, pre, B_, 512, 512, 512);
    // sel = pre @ Wself   (col c = a*64+d)
    gemm128<0, false, false, false><<<dim3(4, 128), 256>>>(pre, Wself, nullptr, sel, B_, 512, 512, 512);
    // selk[a] = sel[:, a*64:(a+1)*64] @ WkT[a]   [B,512] per head, K=64
    gemm128<0, false, false, true><<<dim3(4, 128, 8), 256>>>(sel, WkT, nullptr, selk, B_, 64, 512, 512);
    // vals = leaky(encs @ Wvf + bv)
    gemm128<1, true, false, false><<<dim3(4, 1024), 256>>>(encs, Wvf, bv, vals, EB, 512, 512, 512);
    // attention: logits via selk.encs, softmax, combine vals -> actor_in
    attn_kernel<<<B_, 64>>>(out_actor);
    // x = relu(actor_in @ W_actor + b_actor)
    gemm128<2, true, false, false><<<dim3(4, 128), 256>>>(out_actor, W_actor, b_actor, xbuf, B_, 512, 512, 512);
    // mean = x @ W_mean + b_mean
    gemm_small<0, true><<<dim3(1, 128), 256>>>(xbuf, W_mean, b_mean, out_mean, B_, 512, 64);
    // log_std = clip(x @ W_logstd + b_logstd)
    gemm_small<3, true><<<dim3(1, 128), 256>>>(xbuf, W_logstd, b_logstd, out_logstd, B_, 512, 64);
}

// round 6
// speedup vs baseline: 2.3369x; 1.8459x over previous
#include <cuda_runtime.h>
#include <cuda_bf16.h>
#include <math.h>
#include <stdint.h>

#define E_ 8
#define B_ 16384
#define NAG 64
#define H_ 512
#define A_ 8
#define D_ 64
#define EB (E_*B_)

// ---------------- scratch (device globals; no allocation allowed) ----------------
__device__ float g_encs[(size_t)EB * H_];              // fp32 (attn logits)
__device__ __nv_bfloat16 g_encs_hi[(size_t)EB * H_];
__device__ __nv_bfloat16 g_encs_lo[(size_t)EB * H_];
__device__ float g_vals[(size_t)EB * H_];
__device__ float g_selk[(size_t)A_ * B_ * H_];
__device__ float g_x[(size_t)B_ * H_];
__device__ __nv_bfloat16 g_sn_hi[(size_t)EB * 64];     // normalized states
__device__ __nv_bfloat16 g_sn_lo[(size_t)EB * 64];
__device__ __nv_bfloat16 g_pa_hi[(size_t)B_ * H_];     // pre_actions
__device__ __nv_bfloat16 g_pa_lo[(size_t)B_ * H_];
__device__ __nv_bfloat16 g_pre_hi[(size_t)B_ * H_];
__device__ __nv_bfloat16 g_pre_lo[(size_t)B_ * H_];
__device__ __nv_bfloat16 g_sel_hi[(size_t)B_ * H_];
__device__ __nv_bfloat16 g_sel_lo[(size_t)B_ * H_];
__device__ __nv_bfloat16 g_attn_hi[(size_t)B_ * H_];
__device__ __nv_bfloat16 g_attn_lo[(size_t)B_ * H_];
// weights, all [n][k] k-major, bf16 hi/lo
__device__ __nv_bfloat16 g_WencT_hi[E_ * H_ * 64];     // [e][n=512][k=64]
__device__ __nv_bfloat16 g_WencT_lo[E_ * H_ * 64];
__device__ __nv_bfloat16 g_WpreT_hi[H_ * H_];
__device__ __nv_bfloat16 g_WpreT_lo[H_ * H_];
__device__ __nv_bfloat16 g_WselT_hi[H_ * H_];
__device__ __nv_bfloat16 g_WselT_lo[H_ * H_];
__device__ __nv_bfloat16 g_WvT_hi[H_ * H_];
__device__ __nv_bfloat16 g_WvT_lo[H_ * H_];
__device__ __nv_bfloat16 g_WactT_hi[H_ * H_];
__device__ __nv_bfloat16 g_WactT_lo[H_ * H_];
__device__ __nv_bfloat16 g_Wk_hi[A_ * H_ * D_];        // [a][n=h][k=d] (native layout)
__device__ __nv_bfloat16 g_Wk_lo[A_ * H_ * D_];
__device__ float g_part_sum[E_ * 32 * 64];
__device__ float g_part_sq[E_ * 32 * 64];
__device__ float g_mu[E_ * 64];
__device__ float g_rs[E_ * 64];

// ---------------- helpers ----------------
__device__ __forceinline__ uint32_t smem_u32(const void* p) {
    uint32_t a;
    asm("{ .reg .u64 t; cvta.to.shared.u64 t, %1; cvt.u32.u64 %0, t; }" : "=r"(a) : "l"(p));
    return a;
}
__device__ __forceinline__ void split2(float v, unsigned short& h, unsigned short& l) {
    __nv_bfloat16 bh = __float2bfloat16(v);
    __nv_bfloat16 bl = __float2bfloat16(v - __bfloat162float(bh));
    h = *(unsigned short*)&bh;
    l = *(unsigned short*)&bl;
}
template<int ACT>
__device__ __forceinline__ float act_fn(float v) {
    if constexpr (ACT == 1) return v >= 0.f ? v : 0.01f * v;
    else if constexpr (ACT == 2) return fmaxf(v, 0.f);
    else if constexpr (ACT == 3) return fminf(fmaxf(v, -20.f), 2.f);
    else return v;
}
#define CP16(dst, src) asm volatile("cp.async.cg.shared.global [%0], [%1], 16;" :: "r"(dst), "l"(src))
__device__ __forceinline__ void ldsm4(uint32_t* r, uint32_t a) {
    asm volatile("ldmatrix.sync.aligned.m8n8.x4.shared.b16 {%0,%1,%2,%3}, [%4];"
        : "=r"(r[0]), "=r"(r[1]), "=r"(r[2]), "=r"(r[3]) : "r"(a));
}
__device__ __forceinline__ void mma_bf16(float* d, const uint32_t* a, const uint32_t* b) {
    asm volatile("mma.sync.aligned.m16n8k16.row.col.f32.bf16.bf16.f32 "
        "{%0,%1,%2,%3}, {%4,%5,%6,%7}, {%8,%9}, {%0,%1,%2,%3};"
        : "+f"(d[0]), "+f"(d[1]), "+f"(d[2]), "+f"(d[3])
        : "r"(a[0]), "r"(a[1]), "r"(a[2]), "r"(a[3]), "r"(b[0]), "r"(b[1]));
}
// smem layout per [128 rows x 32 cols bf16] matrix: 64 lines of 128B;
// chunk (16B) index swizzled for conflict-free ldmatrix.
__device__ __forceinline__ uint32_t swz(int row, int g) {
    int l = row >> 1;
    int c = (g | ((row & 1) << 2)) ^ (l & 7);
    return (uint32_t)((l << 7) + (c << 4));
}

// ---------------- batchnorm stats ----------------
__global__ void bn_part_kernel(const float* __restrict__ states) {
    int e = blockIdx.x, ch = blockIdx.y;
    int n = threadIdx.x, ty = threadIdx.y;
    const float* base = states + ((size_t)e * B_ + (size_t)ch * 512) * 64;
    float s = 0.f, q = 0.f;
    for (int r = ty; r < 512; r += 4) {
        float v = base[(size_t)r * 64 + n];
        s += v; q += v * v;
    }
    __shared__ float ss[4][64], sq[4][64];
    ss[ty][n] = s; sq[ty][n] = q;
    __syncthreads();
    if (ty == 0) {
        s = ss[0][n] + ss[1][n] + ss[2][n] + ss[3][n];
        q = sq[0][n] + sq[1][n] + sq[2][n] + sq[3][n];
        g_part_sum[(e * 32 + ch) * 64 + n] = s;
        g_part_sq [(e * 32 + ch) * 64 + n] = q;
    }
}
__global__ void bn_final_kernel() {
    int i = threadIdx.x;
    int e = i >> 6, n = i & 63;
    float s = 0.f, q = 0.f;
    for (int j = 0; j < 32; j++) {
        s += g_part_sum[(e * 32 + j) * 64 + n];
        q += g_part_sq [(e * 32 + j) * 64 + n];
    }
    float mean = s * (1.f / B_);
    float var  = q * (1.f / B_) - mean * mean;
    g_mu[i] = mean;
    g_rs[i] = 1.f / sqrtf(var + 1e-5f);
}

// ---------------- converters ----------------
__global__ void cvt_pa_kernel(const float* __restrict__ src) {
    size_t i = (size_t)blockIdx.x * 256 + threadIdx.x;   // over B_*512/4
    float4 v = ((const float4*)src)[i];
    unsigned short hh[4], ll[4];
    split2(v.x, hh[0], ll[0]); split2(v.y, hh[1], ll[1]);
    split2(v.z, hh[2], ll[2]); split2(v.w, hh[3], ll[3]);
    *(uint2*)&g_pa_hi[i * 4] = *(uint2*)hh;
    *(uint2*)&g_pa_lo[i * 4] = *(uint2*)ll;
}
__global__ void snorm_kernel(const float* __restrict__ states) {
    size_t i = (size_t)blockIdx.x * 256 + threadIdx.x;   // over EB*64/4
    float4 v = ((const float4*)states)[i];
    size_t row = i >> 4;
    int n = (int)(i & 15) * 4;
    int kb = (int)(row >> 14) * 64 + n;
    v.x = (v.x - g_mu[kb + 0]) * g_rs[kb + 0];
    v.y = (v.y - g_mu[kb + 1]) * g_rs[kb + 1];
    v.z = (v.z - g_mu[kb + 2]) * g_rs[kb + 2];
    v.w = (v.w - g_mu[kb + 3]) * g_rs[kb + 3];
    unsigned short hh[4], ll[4];
    split2(v.x, hh[0], ll[0]); split2(v.y, hh[1], ll[1]);
    split2(v.z, hh[2], ll[2]); split2(v.w, hh[3], ll[3]);
    *(uint2*)&g_sn_hi[i * 4] = *(uint2*)hh;
    *(uint2*)&g_sn_lo[i * 4] = *(uint2*)ll;
}
__global__ void repack2_kernel(const float* __restrict__ Wk, const float* __restrict__ Wv,
                               const float* __restrict__ Wsel, const float* __restrict__ W_pre,
                               const float* __restrict__ W_actor, const float* __restrict__ W_enc) {
    int i = blockIdx.x * 256 + threadIdx.x;   // 262144
    int k = i >> 9, n = i & 511;
    unsigned short h, l;
    int dst = n * 512 + k;
    split2(W_pre[i], h, l);   g_WpreT_hi[dst] = *(__nv_bfloat16*)&h; g_WpreT_lo[dst] = *(__nv_bfloat16*)&l;
    split2(W_actor[i], h, l); g_WactT_hi[dst] = *(__nv_bfloat16*)&h; g_WactT_lo[dst] = *(__nv_bfloat16*)&l;
    int a = n >> 6, dd = n & 63;
    int srcv = a * 32768 + k * 64 + dd;
    split2(Wv[srcv], h, l);   g_WvT_hi[dst] = *(__nv_bfloat16*)&h;   g_WvT_lo[dst] = *(__nv_bfloat16*)&l;
    split2(Wsel[srcv], h, l); g_WselT_hi[dst] = *(__nv_bfloat16*)&h; g_WselT_lo[dst] = *(__nv_bfloat16*)&l;
    split2(Wk[i], h, l);      g_Wk_hi[i] = *(__nv_bfloat16*)&h;      g_Wk_lo[i] = *(__nv_bfloat16*)&l;
    // W_enc: [E][64][512] -> [e][n][k]
    int e2 = i >> 15, rem = i & 32767, ne = rem >> 6, ke = rem & 63;
    split2(W_enc[e2 * 32768 + ke * 512 + ne], h, l);
    g_WencT_hi[i] = *(__nv_bfloat16*)&h; g_WencT_lo[i] = *(__nv_bfloat16*)&l;
}

// ---------------- mma.sync bf16x3 GEMM: C[M,512] = act(A[M,K] @ B^T + bias) ----------------
// A: hi/lo, row stride lda; B: [n=512][k=K] hi/lo. CTA 128x128, warp 32x64.
// PERENC: e = m0/B_, B += e*512*K, bias += e*512 (enc layer).
// PERHEAD: z = blockIdx.z, A col offset z*64, B += z*512*K, outputs += z*B_*512.
template<int ACT, bool HAS_BIAS, bool WRITE_F32, bool EMIT, bool PERENC, bool PERHEAD>
__global__ __launch_bounds__(256) void mma_gemm(
    const __nv_bfloat16* __restrict__ Ahi, const __nv_bfloat16* __restrict__ Alo,
    const __nv_bfloat16* __restrict__ Bhi, const __nv_bfloat16* __restrict__ Blo,
    const float* __restrict__ bias,
    float* __restrict__ C, __nv_bfloat16* __restrict__ Chi, __nv_bfloat16* __restrict__ Clo,
    int K, int lda)
{
    extern __shared__ char smem[];
    const int tid = threadIdx.x;
    const int lane = tid & 31, wid = tid >> 5;
    const int m0 = blockIdx.y * 128, n0 = blockIdx.x * 128;
    const int wm = (wid & 3) * 32, wn = (wid >> 2) * 64;

    if constexpr (PERENC) {
        int e = m0 >> 14;
        Bhi += (size_t)e * 512 * K;
        Blo += (size_t)e * 512 * K;
        if constexpr (HAS_BIAS) bias += e * 512;
    }
    if constexpr (PERHEAD) {
        int z = blockIdx.z;
        Ahi += z * 64; Alo += z * 64;
        Bhi += (size_t)z * 512 * K;
        Blo += (size_t)z * 512 * K;
        size_t co = (size_t)z * B_ * 512;
        if constexpr (WRITE_F32) C += co;
        if constexpr (EMIT) { Chi += co; Clo += co; }
    }

    uint32_t sb = smem_u32(smem);
    const int prow = tid >> 1, ph = tid & 1;
    const __nv_bfloat16* pA0 = Ahi + (size_t)(m0 + prow) * lda + ph * 16;
    const __nv_bfloat16* pA1 = Alo + (size_t)(m0 + prow) * lda + ph * 16;
    const __nv_bfloat16* pB0 = Bhi + (size_t)(n0 + prow) * K + ph * 16;
    const __nv_bfloat16* pB1 = Blo + (size_t)(n0 + prow) * K + ph * 16;
    const uint32_t d0 = swz(prow, ph * 2), d1 = swz(prow, ph * 2 + 1);

    auto prefetch = [&](int buf, int kc) {
        uint32_t base = sb + buf * 32768;
        CP16(base + d0,          (const char*)(pA0 + kc * 32));
        CP16(base + d1,          (const char*)(pA0 + kc * 32 + 8));
        CP16(base + 8192 + d0,   (const char*)(pA1 + kc * 32));
        CP16(base + 8192 + d1,   (const char*)(pA1 + kc * 32 + 8));
        CP16(base + 16384 + d0,  (const char*)(pB0 + kc * 32));
        CP16(base + 16384 + d1,  (const char*)(pB0 + kc * 32 + 8));
        CP16(base + 24576 + d0,  (const char*)(pB1 + kc * 32));
        CP16(base + 24576 + d1,  (const char*)(pB1 + kc * 32 + 8));
        asm volatile("cp.async.commit_group;");
    };

    float d[2][8][4] = {};
    const int lrow = lane & 7, grp = lane >> 3;

    auto compute = [&](int buf) {
        uint32_t base = sb + buf * 32768;
        #pragma unroll
        for (int s = 0; s < 2; s++) {
            uint32_t ahi[2][4], alo[2][4], bhi[8][2], blo[8][2];
            #pragma unroll
            for (int i = 0; i < 2; i++) {
                // A x4 tile order: (r0-7,klo),(r8-15,klo),(r0-7,khi),(r8-15,khi)
                int row = wm + i * 16 + (grp & 1) * 8 + lrow;
                int g = s * 2 + (grp >> 1);
                uint32_t off = swz(row, g);
                ldsm4(ahi[i], base + off);
                ldsm4(alo[i], base + 8192 + off);
            }
            #pragma unroll
            for (int j = 0; j < 4; j++) {
                // B x4 tile order: (n0-7,klo),(n0-7,khi),(n8-15,klo),(n8-15,khi)
                int row = wn + j * 16 + (grp >> 1) * 8 + lrow;
                int g = s * 2 + (grp & 1);
                uint32_t off = swz(row, g);
                uint32_t t[4];
                ldsm4(t, base + 16384 + off);
                bhi[j*2][0] = t[0]; bhi[j*2][1] = t[1];
                bhi[j*2+1][0] = t[2]; bhi[j*2+1][1] = t[3];
                ldsm4(t, base + 24576 + off);
                blo[j*2][0] = t[0]; blo[j*2][1] = t[1];
                blo[j*2+1][0] = t[2]; blo[j*2+1][1] = t[3];
            }
            #pragma unroll
            for (int i = 0; i < 2; i++)
                #pragma unroll
                for (int j = 0; j < 8; j++)
                    mma_bf16(d[i][j], ahi[i], bhi[j]);
            #pragma unroll
            for (int i = 0; i < 2; i++)
                #pragma unroll
                for (int j = 0; j < 8; j++)
                    mma_bf16(d[i][j], ahi[i], blo[j]);
            #pragma unroll
            for (int i = 0; i < 2; i++)
                #pragma unroll
                for (int j = 0; j < 8; j++)
                    mma_bf16(d[i][j], alo[i], bhi[j]);
        }
    };

    const int NCH = K >> 5;
    prefetch(0, 0);
    for (int kc = 0; kc < NCH; kc++) {
        if (kc + 1 < NCH) {
            prefetch((kc + 1) & 1, kc + 1);
            asm volatile("cp.async.wait_group 1;");
        } else {
            asm volatile("cp.async.wait_group 0;");
        }
        __syncthreads();
        compute(kc & 1);
        __syncthreads();
    }

    // epilogue: frags -> smem stage -> coalesced global
    float* stage = (float*)smem;   // [128][132]
    #pragma unroll
    for (int i = 0; i < 2; i++)
        #pragma unroll
        for (int j = 0; j < 8; j++) {
            int r = wm + i * 16 + (lane >> 2);
            int cc = wn + j * 8 + (lane & 3) * 2;
            stage[r * 132 + cc]       = d[i][j][0];
            stage[r * 132 + cc + 1]   = d[i][j][1];
            stage[(r + 8) * 132 + cc]     = d[i][j][2];
            stage[(r + 8) * 132 + cc + 1] = d[i][j][3];
        }
    __syncthreads();
    #pragma unroll
    for (int k2 = 0; k2 < 16; k2++) {
        int s = tid + k2 * 256;
        int row = s >> 5, q = s & 31;
        float4 v = *(const float4*)&stage[row * 132 + q * 4];
        int col = n0 + q * 4;
        float o[4] = {v.x, v.y, v.z, v.w};
        if constexpr (HAS_BIAS) {
            o[0] += bias[col]; o[1] += bias[col + 1];
            o[2] += bias[col + 2]; o[3] += bias[col + 3];
        }
        #pragma unroll
        for (int c2 = 0; c2 < 4; c2++) o[c2] = act_fn<ACT>(o[c2]);
        size_t idx = (size_t)(m0 + row) * 512 + col;
        if constexpr (WRITE_F32)
            *(float4*)&C[idx] = make_float4(o[0], o[1], o[2], o[3]);
        if constexpr (EMIT) {
            unsigned short hh[4], ll[4];
            split2(o[0], hh[0], ll[0]); split2(o[1], hh[1], ll[1]);
            split2(o[2], hh[2], ll[2]); split2(o[3], hh[3], ll[3]);
            *(uint2*)&Chi[idx] = *(uint2*)hh;
            *(uint2*)&Clo[idx] = *(uint2*)ll;
        }
    }
}

// ---------------- small SIMT GEMM for NC=64 outputs ----------------
template<int ACT, bool HAS_BIAS>
__global__ __launch_bounds__(256) void gemm_small(
    const float* __restrict__ A, const float* __restrict__ W,
    const float* __restrict__ bias, float* __restrict__ C,
    int M, int K, int NC)
{
    __shared__ float As[16][128];
    __shared__ float Ws[16][64];
    const int tid = threadIdx.x;
    const int m0 = blockIdx.y * 128;
    const int n0 = blockIdx.x * 64;
    const int tr = tid >> 4, tc = tid & 15;
    const int ar = tid >> 2, ac = (tid & 3) << 2;
    const int wr = tid >> 4, wc = (tid & 15) << 2;
    const float* Aptr  = A + (size_t)(m0 + ar) * K + ac;
    const float* Aptr2 = Aptr + (size_t)64 * K;
    const float* Wptr  = W + (size_t)wr * NC + n0 + wc;
    float acc[8][4] = {};
    float4 a0, a1, w0;
    auto loadTile = [&](int kt) {
        a0 = *(const float4*)(Aptr  + kt * 16);
        a1 = *(const float4*)(Aptr2 + kt * 16);
        w0 = *(const float4*)(Wptr + (size_t)kt * 16 * NC);
    };
    loadTile(0);
    const int KT = K >> 4;
    for (int kt = 0; kt < KT; kt++) {
        As[ac+0][ar] = a0.x; As[ac+1][ar] = a0.y; As[ac+2][ar] = a0.z; As[ac+3][ar] = a0.w;
        As[ac+0][ar+64] = a1.x; As[ac+1][ar+64] = a1.y; As[ac+2][ar+64] = a1.z; As[ac+3][ar+64] = a1.w;
        *(float4*)&Ws[wr][wc] = w0;
        __syncthreads();
        if (kt + 1 < KT) loadTile(kt + 1);
        #pragma unroll
        for (int kk = 0; kk < 16; kk++) {
            float4 t0 = *(const float4*)&As[kk][tr * 8];
            float4 t1 = *(const float4*)&As[kk][tr * 8 + 4];
            float4 tw = *(const float4*)&Ws[kk][tc * 4];
            float a_[8] = {t0.x, t0.y, t0.z, t0.w, t1.x, t1.y, t1.z, t1.w};
            float w_[4] = {tw.x, tw.y, tw.z, tw.w};
            #pragma unroll
            for (int i = 0; i < 8; i++)
                #pragma unroll
                for (int j = 0; j < 4; j++)
                    acc[i][j] = fmaf(a_[i], w_[j], acc[i][j]);
        }
        __syncthreads();
    }
    float b4[4] = {0.f, 0.f, 0.f, 0.f};
    if constexpr (HAS_BIAS) {
        b4[0] = bias[n0 + tc*4 + 0]; b4[1] = bias[n0 + tc*4 + 1];
        b4[2] = bias[n0 + tc*4 + 2]; b4[3] = bias[n0 + tc*4 + 3];
    }
    #pragma unroll
    for (int i = 0; i < 8; i++) {
        float4 o;
        o.x = act_fn<ACT>(acc[i][0] + b4[0]);
        o.y = act_fn<ACT>(acc[i][1] + b4[1]);
        o.z = act_fn<ACT>(acc[i][2] + b4[2]);
        o.w = act_fn<ACT>(acc[i][3] + b4[3]);
        *(float4*)(C + (size_t)(m0 + tr * 8 + i) * NC + n0 + tc * 4) = o;
    }
}

// ---------------- attention: logits (selk . encs) -> softmax -> weighted vals ----------------
__global__ __launch_bounds__(64) void attn_kernel(float* __restrict__ actor_in) {
    __shared__ float sk[8][516];
    __shared__ float en[8][516];
    __shared__ float w_s[64];
    int j = threadIdx.x;
    size_t b = blockIdx.x;

    #pragma unroll
    for (int a = 0; a < 8; a++)
        #pragma unroll
        for (int m = 0; m < 8; m++)
            sk[a][m * 64 + j] = g_selk[((size_t)a * B_ + b) * 512 + m * 64 + j];
    #pragma unroll
    for (int e = 0; e < 8; e++)
        #pragma unroll
        for (int m = 0; m < 8; m++)
            en[e][m * 64 + j] = g_encs[((size_t)e * B_ + b) * 512 + m * 64 + j];
    __syncthreads();

    int a = j >> 3, e = j & 7;
    float lg = 0.f;
    const float* sp = sk[a];
    const float* ep = en[e];
    #pragma unroll 8
    for (int h = 0; h < 512; h++) lg = fmaf(sp[h], ep[h], lg);
    lg *= 0.125f;

    float mx = lg;
    #pragma unroll
    for (int o = 4; o >= 1; o >>= 1) mx = fmaxf(mx, __shfl_xor_sync(0xffffffffu, mx, o));
    float ex = expf(lg - mx);
    float sm = ex;
    #pragma unroll
    for (int o = 4; o >= 1; o >>= 1) sm += __shfl_xor_sync(0xffffffffu, sm, o);
    w_s[j] = ex / sm;
    __syncthreads();

    #pragma unroll
    for (int m = 0; m < 8; m++) {
        int c = m * 64 + j;
        float acc = 0.f;
        #pragma unroll
        for (int ee = 0; ee < 8; ee++)
            acc = fmaf(w_s[m * 8 + ee], g_vals[((size_t)ee * B_ + b) * 512 + c], acc);
        actor_in[b * 512 + c] = acc;
        unsigned short hh, ll;
        split2(acc, hh, ll);
        g_attn_hi[b * 512 + c] = *(__nv_bfloat16*)&hh;
        g_attn_lo[b * 512 + c] = *(__nv_bfloat16*)&ll;
    }
}

// ---------------- launch ----------------
#define MMA_SMEM 67584

extern "C" void kernel_launch(void* const* d_in, const int* in_sizes, int n_in,
                              void* d_out, int out_size) {
    const float* states      = (const float*)d_in[0];
    const float* pre_actions = (const float*)d_in[1];
    const float* W_enc       = (const float*)d_in[2];
    const float* b_enc       = (const float*)d_in[3];
    const float* W_pre       = (const float*)d_in[4];
    const float* b_pre       = (const float*)d_in[5];
    const float* Wk          = (const float*)d_in[6];
    const float* Wsel        = (const float*)d_in[7];
    const float* Wv          = (const float*)d_in[8];
    const float* bv          = (const float*)d_in[9];
    const float* W_actor     = (const float*)d_in[10];
    const float* b_actor     = (const float*)d_in[11];
    const float* W_mean      = (const float*)d_in[12];
    const float* b_mean      = (const float*)d_in[13];
    const float* W_logstd    = (const float*)d_in[14];
    const float* b_logstd    = (const float*)d_in[15];

    float* out        = (float*)d_out;
    float* out_mean   = out;
    float* out_logstd = out + (size_t)B_ * NAG;
    float* out_actor  = out + (size_t)2 * B_ * NAG;

    float *encs, *vals, *selk, *xbuf;
    __nv_bfloat16 *encs_hi, *encs_lo, *sn_hi, *sn_lo, *pa_hi, *pa_lo;
    __nv_bfloat16 *pre_hi, *pre_lo, *sel_hi, *sel_lo, *attn_hi, *attn_lo;
    __nv_bfloat16 *WencT_hi, *WencT_lo, *WpreT_hi, *WpreT_lo, *WselT_hi, *WselT_lo;
    __nv_bfloat16 *WvT_hi, *WvT_lo, *WactT_hi, *WactT_lo, *Wk_hi, *Wk_lo;
    cudaGetSymbolAddress((void**)&encs,    g_encs);
    cudaGetSymbolAddress((void**)&vals,    g_vals);
    cudaGetSymbolAddress((void**)&selk,    g_selk);
    cudaGetSymbolAddress((void**)&xbuf,    g_x);
    cudaGetSymbolAddress((void**)&encs_hi, g_encs_hi);
    cudaGetSymbolAddress((void**)&encs_lo, g_encs_lo);
    cudaGetSymbolAddress((void**)&sn_hi,   g_sn_hi);
    cudaGetSymbolAddress((void**)&sn_lo,   g_sn_lo);
    cudaGetSymbolAddress((void**)&pa_hi,   g_pa_hi);
    cudaGetSymbolAddress((void**)&pa_lo,   g_pa_lo);
    cudaGetSymbolAddress((void**)&pre_hi,  g_pre_hi);
    cudaGetSymbolAddress((void**)&pre_lo,  g_pre_lo);
    cudaGetSymbolAddress((void**)&sel_hi,  g_sel_hi);
    cudaGetSymbolAddress((void**)&sel_lo,  g_sel_lo);
    cudaGetSymbolAddress((void**)&attn_hi, g_attn_hi);
    cudaGetSymbolAddress((void**)&attn_lo, g_attn_lo);
    cudaGetSymbolAddress((void**)&WencT_hi, g_WencT_hi);
    cudaGetSymbolAddress((void**)&WencT_lo, g_WencT_lo);
    cudaGetSymbolAddress((void**)&WpreT_hi, g_WpreT_hi);
    cudaGetSymbolAddress((void**)&WpreT_lo, g_WpreT_lo);
    cudaGetSymbolAddress((void**)&WselT_hi, g_WselT_hi);
    cudaGetSymbolAddress((void**)&WselT_lo, g_WselT_lo);
    cudaGetSymbolAddress((void**)&WvT_hi,  g_WvT_hi);
    cudaGetSymbolAddress((void**)&WvT_lo,  g_WvT_lo);
    cudaGetSymbolAddress((void**)&WactT_hi, g_WactT_hi);
    cudaGetSymbolAddress((void**)&WactT_lo, g_WactT_lo);
    cudaGetSymbolAddress((void**)&Wk_hi,   g_Wk_hi);
    cudaGetSymbolAddress((void**)&Wk_lo,   g_Wk_lo);

    auto enc_k  = mma_gemm<1, true,  true,  true,  true,  false>;
    auto pre_k  = mma_gemm<1, true,  false, true,  false, false>;
    auto sel_k  = mma_gemm<0, false, false, true,  false, false>;
    auto selk_k = mma_gemm<0, false, true,  false, false, true>;
    auto vals_k = mma_gemm<1, true,  true,  false, false, false>;
    auto x_k    = mma_gemm<2, true,  true,  false, false, false>;
    cudaFuncSetAttribute(enc_k,  cudaFuncAttributeMaxDynamicSharedMemorySize, MMA_SMEM);
    cudaFuncSetAttribute(pre_k,  cudaFuncAttributeMaxDynamicSharedMemorySize, MMA_SMEM);
    cudaFuncSetAttribute(sel_k,  cudaFuncAttributeMaxDynamicSharedMemorySize, MMA_SMEM);
    cudaFuncSetAttribute(selk_k, cudaFuncAttributeMaxDynamicSharedMemorySize, MMA_SMEM);
    cudaFuncSetAttribute(vals_k, cudaFuncAttributeMaxDynamicSharedMemorySize, MMA_SMEM);
    cudaFuncSetAttribute(x_k,    cudaFuncAttributeMaxDynamicSharedMemorySize, MMA_SMEM);

    // stats + conversions + repacks
    bn_part_kernel<<<dim3(E_, 32), dim3(64, 4)>>>(states);
    bn_final_kernel<<<1, 512>>>();
    repack2_kernel<<<1024, 256>>>(Wk, Wv, Wsel, W_pre, W_actor, W_enc);
    cvt_pa_kernel<<<8192, 256>>>(pre_actions);
    snorm_kernel<<<8192, 256>>>(states);

    // encs = leaky(snorm @ W_enc + b_enc), K=64, per-encoder; emit fp32 + hi/lo
    enc_k<<<dim3(4, 1024), 256, MMA_SMEM>>>(sn_hi, sn_lo, WencT_hi, WencT_lo, b_enc,
                                            encs, encs_hi, encs_lo, 64, 64);
    // pre = leaky(pre_actions @ W_pre + b_pre), emit hi/lo only
    pre_k<<<dim3(4, 128), 256, MMA_SMEM>>>(pa_hi, pa_lo, WpreT_hi, WpreT_lo, b_pre,
                                           nullptr, pre_hi, pre_lo, 512, 512);
    // sel = pre @ Wsel, emit hi/lo only
    sel_k<<<dim3(4, 128), 256, MMA_SMEM>>>(pre_hi, pre_lo, WselT_hi, WselT_lo, nullptr,
                                           nullptr, sel_hi, sel_lo, 512, 512);
    // selk[a] = sel[:, a*64:+64] @ Wk[a]^T, K=64, per-head; fp32
    selk_k<<<dim3(4, 128, 8), 256, MMA_SMEM>>>(sel_hi, sel_lo, Wk_hi, Wk_lo, nullptr,
                                               selk, nullptr, nullptr, 64, 512);
    // vals = leaky(encs @ Wv + bv); fp32
    vals_k<<<dim3(4, 1024), 256, MMA_SMEM>>>(encs_hi, encs_lo, WvT_hi, WvT_lo, bv,
                                             vals, nullptr, nullptr, 512, 512);
    // attention -> actor_in (+ hi/lo for actor GEMM)
    attn_kernel<<<B_, 64>>>(out_actor);
    // x = relu(actor_in @ W_actor + b_actor); fp32
    x_k<<<dim3(4, 128), 256, MMA_SMEM>>>(attn_hi, attn_lo, WactT_hi, WactT_lo, b_actor,
                                         xbuf, nullptr, nullptr, 512, 512);
    // mean / log_std (SIMT, small)
    gemm_small<0, true><<<dim3(1, 128), 256>>>(xbuf, W_mean, b_mean, out_mean, B_, 512, 64);
    gemm_small<3, true><<<dim3(1, 128), 256>>>(xbuf, W_logstd, b_logstd, out_logstd, B_, 512, 64);
}

// round 7
// speedup vs baseline: 2.4253x; 1.0378x over previous
#include <cuda_runtime.h>
#include <cuda_bf16.h>
#include <math.h>
#include <stdint.h>

#define E_ 8
#define B_ 16384
#define NAG 64
#define H_ 512
#define A_ 8
#define D_ 64
#define EB (E_*B_)

// ---------------- scratch (device globals; no allocation allowed) ----------------
__device__ __nv_bfloat16 g_encs_hi[(size_t)EB * H_];
__device__ __nv_bfloat16 g_encs_lo[(size_t)EB * H_];
__device__ float g_vals[(size_t)EB * H_];
__device__ float g_selk[(size_t)A_ * B_ * H_];
__device__ __nv_bfloat16 g_x_hi[(size_t)B_ * H_];
__device__ __nv_bfloat16 g_x_lo[(size_t)B_ * H_];
__device__ __nv_bfloat16 g_sn_hi[(size_t)EB * 64];     // normalized states
__device__ __nv_bfloat16 g_sn_lo[(size_t)EB * 64];
__device__ __nv_bfloat16 g_pa_hi[(size_t)B_ * H_];     // pre_actions
__device__ __nv_bfloat16 g_pa_lo[(size_t)B_ * H_];
__device__ __nv_bfloat16 g_pre_hi[(size_t)B_ * H_];
__device__ __nv_bfloat16 g_pre_lo[(size_t)B_ * H_];
__device__ __nv_bfloat16 g_sel_hi[(size_t)B_ * H_];
__device__ __nv_bfloat16 g_sel_lo[(size_t)B_ * H_];
__device__ __nv_bfloat16 g_attn_hi[(size_t)B_ * H_];
__device__ __nv_bfloat16 g_attn_lo[(size_t)B_ * H_];
// weights, all [n][k] k-major, bf16 hi/lo
__device__ __nv_bfloat16 g_WencT_hi[E_ * H_ * 64];     // [e][n=512][k=64]
__device__ __nv_bfloat16 g_WencT_lo[E_ * H_ * 64];
__device__ __nv_bfloat16 g_WpreT_hi[H_ * H_];
__device__ __nv_bfloat16 g_WpreT_lo[H_ * H_];
__device__ __nv_bfloat16 g_WselT_hi[H_ * H_];
__device__ __nv_bfloat16 g_WselT_lo[H_ * H_];
__device__ __nv_bfloat16 g_WvT_hi[H_ * H_];
__device__ __nv_bfloat16 g_WvT_lo[H_ * H_];
__device__ __nv_bfloat16 g_WactT_hi[H_ * H_];
__device__ __nv_bfloat16 g_WactT_lo[H_ * H_];
__device__ __nv_bfloat16 g_Wk_hi[A_ * H_ * D_];        // [a][n=h][k=d]
__device__ __nv_bfloat16 g_Wk_lo[A_ * H_ * D_];
__device__ __nv_bfloat16 g_WmlT_hi[128 * H_];          // [n=128][k=512] (mean|logstd)
__device__ __nv_bfloat16 g_WmlT_lo[128 * H_];
__device__ float g_bias_ml[128];
__device__ float g_part_sum[E_ * 32 * 64];
__device__ float g_part_sq[E_ * 32 * 64];
__device__ float g_mu[E_ * 64];
__device__ float g_rs[E_ * 64];

// ---------------- helpers ----------------
__device__ __forceinline__ uint32_t smem_u32(const void* p) {
    uint32_t a;
    asm("{ .reg .u64 t; cvta.to.shared.u64 t, %1; cvt.u32.u64 %0, t; }" : "=r"(a) : "l"(p));
    return a;
}
__device__ __forceinline__ void split2(float v, unsigned short& h, unsigned short& l) {
    __nv_bfloat16 bh = __float2bfloat16(v);
    __nv_bfloat16 bl = __float2bfloat16(v - __bfloat162float(bh));
    h = *(unsigned short*)&bh;
    l = *(unsigned short*)&bl;
}
template<int ACT>
__device__ __forceinline__ float act_fn(float v) {
    if constexpr (ACT == 1) return v >= 0.f ? v : 0.01f * v;
    else if constexpr (ACT == 2) return fmaxf(v, 0.f);
    else if constexpr (ACT == 3) return fminf(fmaxf(v, -20.f), 2.f);
    else return v;
}
#define CP16(dst, src) asm volatile("cp.async.cg.shared.global [%0], [%1], 16;" :: "r"(dst), "l"(src))
__device__ __forceinline__ void ldsm4(uint32_t* r, uint32_t a) {
    asm volatile("ldmatrix.sync.aligned.m8n8.x4.shared.b16 {%0,%1,%2,%3}, [%4];"
        : "=r"(r[0]), "=r"(r[1]), "=r"(r[2]), "=r"(r[3]) : "r"(a));
}
__device__ __forceinline__ void mma_bf16(float* d, const uint32_t* a, const uint32_t* b) {
    asm volatile("mma.sync.aligned.m16n8k16.row.col.f32.bf16.bf16.f32 "
        "{%0,%1,%2,%3}, {%4,%5,%6,%7}, {%8,%9}, {%0,%1,%2,%3};"
        : "+f"(d[0]), "+f"(d[1]), "+f"(d[2]), "+f"(d[3])
        : "r"(a[0]), "r"(a[1]), "r"(a[2]), "r"(a[3]), "r"(b[0]), "r"(b[1]));
}
// smem layout per [128 rows x 32 cols bf16] matrix: swizzled 16B chunks.
__device__ __forceinline__ uint32_t swz(int row, int g) {
    int l = row >> 1;
    int c = (g | ((row & 1) << 2)) ^ (l & 7);
    return (uint32_t)((l << 7) + (c << 4));
}

// ---------------- batchnorm stats ----------------
__global__ void bn_part_kernel(const float* __restrict__ states) {
    int e = blockIdx.x, ch = blockIdx.y;
    int n = threadIdx.x, ty = threadIdx.y;
    const float* base = states + ((size_t)e * B_ + (size_t)ch * 512) * 64;
    float s = 0.f, q = 0.f;
    for (int r = ty; r < 512; r += 4) {
        float v = base[(size_t)r * 64 + n];
        s += v; q += v * v;
    }
    __shared__ float ss[4][64], sq[4][64];
    ss[ty][n] = s; sq[ty][n] = q;
    __syncthreads();
    if (ty == 0) {
        s = ss[0][n] + ss[1][n] + ss[2][n] + ss[3][n];
        q = sq[0][n] + sq[1][n] + sq[2][n] + sq[3][n];
        g_part_sum[(e * 32 + ch) * 64 + n] = s;
        g_part_sq [(e * 32 + ch) * 64 + n] = q;
    }
}
__global__ void bn_final_kernel() {
    int i = threadIdx.x;
    int e = i >> 6, n = i & 63;
    float s = 0.f, q = 0.f;
    for (int j = 0; j < 32; j++) {
        s += g_part_sum[(e * 32 + j) * 64 + n];
        q += g_part_sq [(e * 32 + j) * 64 + n];
    }
    float mean = s * (1.f / B_);
    float var  = q * (1.f / B_) - mean * mean;
    g_mu[i] = mean;
    g_rs[i] = 1.f / sqrtf(var + 1e-5f);
}

// ---------------- converters ----------------
__global__ void cvt_pa_kernel(const float* __restrict__ src) {
    size_t i = (size_t)blockIdx.x * 256 + threadIdx.x;   // over B_*512/4
    float4 v = ((const float4*)src)[i];
    unsigned short hh[4], ll[4];
    split2(v.x, hh[0], ll[0]); split2(v.y, hh[1], ll[1]);
    split2(v.z, hh[2], ll[2]); split2(v.w, hh[3], ll[3]);
    *(uint2*)&g_pa_hi[i * 4] = *(uint2*)hh;
    *(uint2*)&g_pa_lo[i * 4] = *(uint2*)ll;
}
__global__ void snorm_kernel(const float* __restrict__ states) {
    size_t i = (size_t)blockIdx.x * 256 + threadIdx.x;   // over EB*64/4
    float4 v = ((const float4*)states)[i];
    size_t row = i >> 4;
    int n = (int)(i & 15) * 4;
    int kb = (int)(row >> 14) * 64 + n;
    v.x = (v.x - g_mu[kb + 0]) * g_rs[kb + 0];
    v.y = (v.y - g_mu[kb + 1]) * g_rs[kb + 1];
    v.z = (v.z - g_mu[kb + 2]) * g_rs[kb + 2];
    v.w = (v.w - g_mu[kb + 3]) * g_rs[kb + 3];
    unsigned short hh[4], ll[4];
    split2(v.x, hh[0], ll[0]); split2(v.y, hh[1], ll[1]);
    split2(v.z, hh[2], ll[2]); split2(v.w, hh[3], ll[3]);
    *(uint2*)&g_sn_hi[i * 4] = *(uint2*)hh;
    *(uint2*)&g_sn_lo[i * 4] = *(uint2*)ll;
}
__global__ void repack2_kernel(const float* __restrict__ Wk, const float* __restrict__ Wv,
                               const float* __restrict__ Wsel, const float* __restrict__ W_pre,
                               const float* __restrict__ W_actor, const float* __restrict__ W_enc,
                               const float* __restrict__ W_mean, const float* __restrict__ W_logstd,
                               const float* __restrict__ b_mean, const float* __restrict__ b_logstd) {
    int i = blockIdx.x * 256 + threadIdx.x;   // 262144
    int k = i >> 9, n = i & 511;
    unsigned short h, l;
    int dst = n * 512 + k;
    split2(W_pre[i], h, l);   g_WpreT_hi[dst] = *(__nv_bfloat16*)&h; g_WpreT_lo[dst] = *(__nv_bfloat16*)&l;
    split2(W_actor[i], h, l); g_WactT_hi[dst] = *(__nv_bfloat16*)&h; g_WactT_lo[dst] = *(__nv_bfloat16*)&l;
    int a = n >> 6, dd = n & 63;
    int srcv = a * 32768 + k * 64 + dd;
    split2(Wv[srcv], h, l);   g_WvT_hi[dst] = *(__nv_bfloat16*)&h;   g_WvT_lo[dst] = *(__nv_bfloat16*)&l;
    split2(Wsel[srcv], h, l); g_WselT_hi[dst] = *(__nv_bfloat16*)&h; g_WselT_lo[dst] = *(__nv_bfloat16*)&l;
    split2(Wk[i], h, l);      g_Wk_hi[i] = *(__nv_bfloat16*)&h;      g_Wk_lo[i] = *(__nv_bfloat16*)&l;
    // W_enc: [E][64][512] -> [e][n][k]
    int e2 = i >> 15, rem = i & 32767, ne = rem >> 6, ke = rem & 63;
    split2(W_enc[e2 * 32768 + ke * 512 + ne], h, l);
    g_WencT_hi[i] = *(__nv_bfloat16*)&h; g_WencT_lo[i] = *(__nv_bfloat16*)&l;
    // W_mean|W_logstd: [512][64] each -> combined [n2=128][k2=512]
    if (i < 128 * 512) {
        int n2 = i & 127, k2 = i >> 7;
        float v = (n2 < 64) ? W_mean[k2 * 64 + n2] : W_logstd[k2 * 64 + (n2 - 64)];
        split2(v, h, l);
        g_WmlT_hi[n2 * 512 + k2] = *(__nv_bfloat16*)&h;
        g_WmlT_lo[n2 * 512 + k2] = *(__nv_bfloat16*)&l;
    }
    if (i < 128) g_bias_ml[i] = (i < 64) ? b_mean[i] : b_logstd[i - 64];
}

// ---------------- mma.sync bf16x3 GEMM: C[M,512] = act(A[M,K] @ B^T + bias) ----------------
// CTA 128x128, 8 warps each 32x64, cp.async double-buffered k32 chunks.
// PERENC: per-encoder weights/bias. PERHEAD: per-head A-col/B/C offsets.
// HEADOUT: N=128 combined mean|logstd; writes mean -> C, clip(logstd) -> C2.
template<int ACT, bool HAS_BIAS, bool WRITE_F32, bool EMIT, bool PERENC, bool PERHEAD, bool HEADOUT>
__global__ __launch_bounds__(256) void mma_gemm(
    const __nv_bfloat16* __restrict__ Ahi, const __nv_bfloat16* __restrict__ Alo,
    const __nv_bfloat16* __restrict__ Bhi, const __nv_bfloat16* __restrict__ Blo,
    const float* __restrict__ bias,
    float* __restrict__ C, float* __restrict__ C2,
    __nv_bfloat16* __restrict__ Chi, __nv_bfloat16* __restrict__ Clo,
    int K, int lda)
{
    extern __shared__ char smem[];
    const int tid = threadIdx.x;
    const int lane = tid & 31, wid = tid >> 5;
    const int m0 = blockIdx.y * 128, n0 = blockIdx.x * 128;
    const int wm = (wid & 3) * 32, wn = (wid >> 2) * 64;

    if constexpr (PERENC) {
        int e = m0 >> 14;
        Bhi += (size_t)e * 512 * K;
        Blo += (size_t)e * 512 * K;
        if constexpr (HAS_BIAS) bias += e * 512;
    }
    if constexpr (PERHEAD) {
        int z = blockIdx.z;
        Ahi += z * 64; Alo += z * 64;
        Bhi += (size_t)z * 512 * K;
        Blo += (size_t)z * 512 * K;
        size_t co = (size_t)z * B_ * 512;
        if constexpr (WRITE_F32) C += co;
        if constexpr (EMIT) { Chi += co; Clo += co; }
    }

    uint32_t sb = smem_u32(smem);
    const int prow = tid >> 1, ph = tid & 1;
    const __nv_bfloat16* pA0 = Ahi + (size_t)(m0 + prow) * lda + ph * 16;
    const __nv_bfloat16* pA1 = Alo + (size_t)(m0 + prow) * lda + ph * 16;
    const __nv_bfloat16* pB0 = Bhi + (size_t)(n0 + prow) * K + ph * 16;
    const __nv_bfloat16* pB1 = Blo + (size_t)(n0 + prow) * K + ph * 16;
    const uint32_t d0 = swz(prow, ph * 2), d1 = swz(prow, ph * 2 + 1);

    auto prefetch = [&](int buf, int kc) {
        uint32_t base = sb + buf * 32768;
        CP16(base + d0,          (const char*)(pA0 + kc * 32));
        CP16(base + d1,          (const char*)(pA0 + kc * 32 + 8));
        CP16(base + 8192 + d0,   (const char*)(pA1 + kc * 32));
        CP16(base + 8192 + d1,   (const char*)(pA1 + kc * 32 + 8));
        CP16(base + 16384 + d0,  (const char*)(pB0 + kc * 32));
        CP16(base + 16384 + d1,  (const char*)(pB0 + kc * 32 + 8));
        CP16(base + 24576 + d0,  (const char*)(pB1 + kc * 32));
        CP16(base + 24576 + d1,  (const char*)(pB1 + kc * 32 + 8));
        asm volatile("cp.async.commit_group;");
    };

    float d[2][8][4] = {};
    const int lrow = lane & 7, grp = lane >> 3;

    auto compute = [&](int buf) {
        uint32_t base = sb + buf * 32768;
        #pragma unroll
        for (int s = 0; s < 2; s++) {
            uint32_t ahi[2][4], alo[2][4], bhi[8][2], blo[8][2];
            #pragma unroll
            for (int i = 0; i < 2; i++) {
                int row = wm + i * 16 + (grp & 1) * 8 + lrow;
                int g = s * 2 + (grp >> 1);
                uint32_t off = swz(row, g);
                ldsm4(ahi[i], base + off);
                ldsm4(alo[i], base + 8192 + off);
            }
            #pragma unroll
            for (int j = 0; j < 4; j++) {
                int row = wn + j * 16 + (grp >> 1) * 8 + lrow;
                int g = s * 2 + (grp & 1);
                uint32_t off = swz(row, g);
                uint32_t t[4];
                ldsm4(t, base + 16384 + off);
                bhi[j*2][0] = t[0]; bhi[j*2][1] = t[1];
                bhi[j*2+1][0] = t[2]; bhi[j*2+1][1] = t[3];
                ldsm4(t, base + 24576 + off);
                blo[j*2][0] = t[0]; blo[j*2][1] = t[1];
                blo[j*2+1][0] = t[2]; blo[j*2+1][1] = t[3];
            }
            #pragma unroll
            for (int i = 0; i < 2; i++)
                #pragma unroll
                for (int j = 0; j < 8; j++)
                    mma_bf16(d[i][j], ahi[i], bhi[j]);
            #pragma unroll
            for (int i = 0; i < 2; i++)
                #pragma unroll
                for (int j = 0; j < 8; j++)
                    mma_bf16(d[i][j], ahi[i], blo[j]);
            #pragma unroll
            for (int i = 0; i < 2; i++)
                #pragma unroll
                for (int j = 0; j < 8; j++)
                    mma_bf16(d[i][j], alo[i], bhi[j]);
        }
    };

    const int NCH = K >> 5;
    prefetch(0, 0);
    for (int kc = 0; kc < NCH; kc++) {
        if (kc + 1 < NCH) {
            prefetch((kc + 1) & 1, kc + 1);
            asm volatile("cp.async.wait_group 1;");
        } else {
            asm volatile("cp.async.wait_group 0;");
        }
        __syncthreads();
        compute(kc & 1);
        __syncthreads();
    }

    // epilogue: frags -> smem stage -> coalesced global
    float* stage = (float*)smem;   // [128][132]
    #pragma unroll
    for (int i = 0; i < 2; i++)
        #pragma unroll
        for (int j = 0; j < 8; j++) {
            int r = wm + i * 16 + (lane >> 2);
            int cc = wn + j * 8 + (lane & 3) * 2;
            stage[r * 132 + cc]       = d[i][j][0];
            stage[r * 132 + cc + 1]   = d[i][j][1];
            stage[(r + 8) * 132 + cc]     = d[i][j][2];
            stage[(r + 8) * 132 + cc + 1] = d[i][j][3];
        }
    __syncthreads();
    #pragma unroll
    for (int k2 = 0; k2 < 16; k2++) {
        int s = tid + k2 * 256;
        int row = s >> 5, q = s & 31;
        float4 v = *(const float4*)&stage[row * 132 + q * 4];
        int col = n0 + q * 4;
        float o[4] = {v.x, v.y, v.z, v.w};
        if constexpr (HAS_BIAS) {
            o[0] += bias[col]; o[1] += bias[col + 1];
            o[2] += bias[col + 2]; o[3] += bias[col + 3];
        }
        if constexpr (HEADOUT) {
            size_t r = (size_t)(m0 + row);
            if (col < 64) {
                *(float4*)&C[r * 64 + col] = make_float4(o[0], o[1], o[2], o[3]);
            } else {
                #pragma unroll
                for (int c2 = 0; c2 < 4; c2++) o[c2] = fminf(fmaxf(o[c2], -20.f), 2.f);
                *(float4*)&C2[r * 64 + col - 64] = make_float4(o[0], o[1], o[2], o[3]);
            }
        } else {
            #pragma unroll
            for (int c2 = 0; c2 < 4; c2++) o[c2] = act_fn<ACT>(o[c2]);
            size_t idx = (size_t)(m0 + row) * 512 + col;
            if constexpr (WRITE_F32)
                *(float4*)&C[idx] = make_float4(o[0], o[1], o[2], o[3]);
            if constexpr (EMIT) {
                unsigned short hh[4], ll[4];
                split2(o[0], hh[0], ll[0]); split2(o[1], hh[1], ll[1]);
                split2(o[2], hh[2], ll[2]); split2(o[3], hh[3], ll[3]);
                *(uint2*)&Chi[idx] = *(uint2*)hh;
                *(uint2*)&Clo[idx] = *(uint2*)ll;
            }
        }
    }
}

// ---------------- attention: logits (selk . encs) -> softmax -> weighted vals ----------------
__global__ __launch_bounds__(64) void attn_kernel(float* __restrict__ actor_in) {
    __shared__ float sk[8][516];
    __shared__ float en[8][516];
    __shared__ float w_s[64];
    int j = threadIdx.x;
    size_t b = blockIdx.x;

    #pragma unroll
    for (int a = 0; a < 8; a++)
        #pragma unroll
        for (int m = 0; m < 8; m++)
            sk[a][m * 64 + j] = g_selk[((size_t)a * B_ + b) * 512 + m * 64 + j];
    #pragma unroll
    for (int e = 0; e < 8; e++)
        #pragma unroll
        for (int m = 0; m < 8; m++) {
            size_t idx = ((size_t)e * B_ + b) * 512 + m * 64 + j;
            en[e][m * 64 + j] = __bfloat162float(g_encs_hi[idx]) + __bfloat162float(g_encs_lo[idx]);
        }
    __syncthreads();

    int a = j >> 3, e = j & 7;
    float lg = 0.f;
    const float* sp = sk[a];
    const float* ep = en[e];
    #pragma unroll 8
    for (int h = 0; h < 512; h++) lg = fmaf(sp[h], ep[h], lg);
    lg *= 0.125f;

    float mx = lg;
    #pragma unroll
    for (int o = 4; o >= 1; o >>= 1) mx = fmaxf(mx, __shfl_xor_sync(0xffffffffu, mx, o));
    float ex = expf(lg - mx);
    float sm = ex;
    #pragma unroll
    for (int o = 4; o >= 1; o >>= 1) sm += __shfl_xor_sync(0xffffffffu, sm, o);
    w_s[j] = ex / sm;
    __syncthreads();

    #pragma unroll
    for (int m = 0; m < 8; m++) {
        int c = m * 64 + j;
        float acc = 0.f;
        #pragma unroll
        for (int ee = 0; ee < 8; ee++)
            acc = fmaf(w_s[m * 8 + ee], g_vals[((size_t)ee * B_ + b) * 512 + c], acc);
        actor_in[b * 512 + c] = acc;
        unsigned short hh, ll;
        split2(acc, hh, ll);
        g_attn_hi[b * 512 + c] = *(__nv_bfloat16*)&hh;
        g_attn_lo[b * 512 + c] = *(__nv_bfloat16*)&ll;
    }
}

// ---------------- launch ----------------
#define MMA_SMEM 67584

extern "C" void kernel_launch(void* const* d_in, const int* in_sizes, int n_in,
                              void* d_out, int out_size) {
    const float* states      = (const float*)d_in[0];
    const float* pre_actions = (const float*)d_in[1];
    const float* W_enc       = (const float*)d_in[2];
    const float* b_enc       = (const float*)d_in[3];
    const float* W_pre       = (const float*)d_in[4];
    const float* b_pre       = (const float*)d_in[5];
    const float* Wk          = (const float*)d_in[6];
    const float* Wsel        = (const float*)d_in[7];
    const float* Wv          = (const float*)d_in[8];
    const float* bv          = (const float*)d_in[9];
    const float* W_actor     = (const float*)d_in[10];
    const float* b_actor     = (const float*)d_in[11];
    const float* W_mean      = (const float*)d_in[12];
    const float* b_mean      = (const float*)d_in[13];
    const float* W_logstd    = (const float*)d_in[14];
    const float* b_logstd    = (const float*)d_in[15];

    float* out        = (float*)d_out;
    float* out_mean   = out;
    float* out_logstd = out + (size_t)B_ * NAG;
    float* out_actor  = out + (size_t)2 * B_ * NAG;

    float *vals, *selk, *bias_ml;
    __nv_bfloat16 *encs_hi, *encs_lo, *sn_hi, *sn_lo, *pa_hi, *pa_lo;
    __nv_bfloat16 *pre_hi, *pre_lo, *sel_hi, *sel_lo, *attn_hi, *attn_lo, *x_hi, *x_lo;
    __nv_bfloat16 *WencT_hi, *WencT_lo, *WpreT_hi, *WpreT_lo, *WselT_hi, *WselT_lo;
    __nv_bfloat16 *WvT_hi, *WvT_lo, *WactT_hi, *WactT_lo, *Wk_hi, *Wk_lo, *WmlT_hi, *WmlT_lo;
    cudaGetSymbolAddress((void**)&vals,    g_vals);
    cudaGetSymbolAddress((void**)&selk,    g_selk);
    cudaGetSymbolAddress((void**)&bias_ml, g_bias_ml);
    cudaGetSymbolAddress((void**)&encs_hi, g_encs_hi);
    cudaGetSymbolAddress((void**)&encs_lo, g_encs_lo);
    cudaGetSymbolAddress((void**)&sn_hi,   g_sn_hi);
    cudaGetSymbolAddress((void**)&sn_lo,   g_sn_lo);
    cudaGetSymbolAddress((void**)&pa_hi,   g_pa_hi);
    cudaGetSymbolAddress((void**)&pa_lo,   g_pa_lo);
    cudaGetSymbolAddress((void**)&pre_hi,  g_pre_hi);
    cudaGetSymbolAddress((void**)&pre_lo,  g_pre_lo);
    cudaGetSymbolAddress((void**)&sel_hi,  g_sel_hi);
    cudaGetSymbolAddress((void**)&sel_lo,  g_sel_lo);
    cudaGetSymbolAddress((void**)&attn_hi, g_attn_hi);
    cudaGetSymbolAddress((void**)&attn_lo, g_attn_lo);
    cudaGetSymbolAddress((void**)&x_hi,    g_x_hi);
    cudaGetSymbolAddress((void**)&x_lo,    g_x_lo);
    cudaGetSymbolAddress((void**)&WencT_hi, g_WencT_hi);
    cudaGetSymbolAddress((void**)&WencT_lo, g_WencT_lo);
    cudaGetSymbolAddress((void**)&WpreT_hi, g_WpreT_hi);
    cudaGetSymbolAddress((void**)&WpreT_lo, g_WpreT_lo);
    cudaGetSymbolAddress((void**)&WselT_hi, g_WselT_hi);
    cudaGetSymbolAddress((void**)&WselT_lo, g_WselT_lo);
    cudaGetSymbolAddress((void**)&WvT_hi,  g_WvT_hi);
    cudaGetSymbolAddress((void**)&WvT_lo,  g_WvT_lo);
    cudaGetSymbolAddress((void**)&WactT_hi, g_WactT_hi);
    cudaGetSymbolAddress((void**)&WactT_lo, g_WactT_lo);
    cudaGetSymbolAddress((void**)&Wk_hi,   g_Wk_hi);
    cudaGetSymbolAddress((void**)&Wk_lo,   g_Wk_lo);
    cudaGetSymbolAddress((void**)&WmlT_hi, g_WmlT_hi);
    cudaGetSymbolAddress((void**)&WmlT_lo, g_WmlT_lo);

    auto enc_k  = mma_gemm<1, true,  false, true,  true,  false, false>;
    auto pre_k  = mma_gemm<1, true,  false, true,  false, false, false>;
    auto sel_k  = mma_gemm<0, false, false, true,  false, false, false>;
    auto selk_k = mma_gemm<0, false, true,  false, false, true,  false>;
    auto vals_k = mma_gemm<1, true,  true,  false, false, false, false>;
    auto x_k    = mma_gemm<2, true,  false, true,  false, false, false>;
    auto ml_k   = mma_gemm<0, true,  false, false, false, false, true>;
    cudaFuncSetAttribute(enc_k,  cudaFuncAttributeMaxDynamicSharedMemorySize, MMA_SMEM);
    cudaFuncSetAttribute(pre_k,  cudaFuncAttributeMaxDynamicSharedMemorySize, MMA_SMEM);
    cudaFuncSetAttribute(sel_k,  cudaFuncAttributeMaxDynamicSharedMemorySize, MMA_SMEM);
    cudaFuncSetAttribute(selk_k, cudaFuncAttributeMaxDynamicSharedMemorySize, MMA_SMEM);
    cudaFuncSetAttribute(vals_k, cudaFuncAttributeMaxDynamicSharedMemorySize, MMA_SMEM);
    cudaFuncSetAttribute(x_k,    cudaFuncAttributeMaxDynamicSharedMemorySize, MMA_SMEM);
    cudaFuncSetAttribute(ml_k,   cudaFuncAttributeMaxDynamicSharedMemorySize, MMA_SMEM);

    // stats + conversions + repacks
    bn_part_kernel<<<dim3(E_, 32), dim3(64, 4)>>>(states);
    bn_final_kernel<<<1, 512>>>();
    repack2_kernel<<<1024, 256>>>(Wk, Wv, Wsel, W_pre, W_actor, W_enc,
                                  W_mean, W_logstd, b_mean, b_logstd);
    cvt_pa_kernel<<<8192, 256>>>(pre_actions);
    snorm_kernel<<<8192, 256>>>(states);

    // encs = leaky(snorm @ W_enc + b_enc), K=64, per-encoder; emit hi/lo only
    enc_k<<<dim3(4, 1024), 256, MMA_SMEM>>>(sn_hi, sn_lo, WencT_hi, WencT_lo, b_enc,
                                            nullptr, nullptr, encs_hi, encs_lo, 64, 64);
    // pre = leaky(pre_actions @ W_pre + b_pre), emit hi/lo
    pre_k<<<dim3(4, 128), 256, MMA_SMEM>>>(pa_hi, pa_lo, WpreT_hi, WpreT_lo, b_pre,
                                           nullptr, nullptr, pre_hi, pre_lo, 512, 512);
    // sel = pre @ Wsel, emit hi/lo
    sel_k<<<dim3(4, 128), 256, MMA_SMEM>>>(pre_hi, pre_lo, WselT_hi, WselT_lo, nullptr,
                                           nullptr, nullptr, sel_hi, sel_lo, 512, 512);
    // selk[a] = sel[:, a*64:+64] @ Wk[a]^T, K=64, per-head; fp32
    selk_k<<<dim3(4, 128, 8), 256, MMA_SMEM>>>(sel_hi, sel_lo, Wk_hi, Wk_lo, nullptr,
                                               selk, nullptr, nullptr, nullptr, 64, 512);
    // vals = leaky(encs @ Wv + bv); fp32
    vals_k<<<dim3(4, 1024), 256, MMA_SMEM>>>(encs_hi, encs_lo, WvT_hi, WvT_lo, bv,
                                             vals, nullptr, nullptr, nullptr, 512, 512);
    // attention -> actor_in (+ hi/lo for actor GEMM)
    attn_kernel<<<B_, 64>>>(out_actor);
    // x = relu(actor_in @ W_actor + b_actor); emit hi/lo
    x_k<<<dim3(4, 128), 256, MMA_SMEM>>>(attn_hi, attn_lo, WactT_hi, WactT_lo, b_actor,
                                         nullptr, nullptr, x_hi, x_lo, 512, 512);
    // mean | log_std fused, N=128, K=512
    ml_k<<<dim3(1, 128), 256, MMA_SMEM>>>(x_hi, x_lo, WmlT_hi, WmlT_lo, bias_ml,
                                          out_mean, out_logstd, nullptr, nullptr, 512, 512);
}

// round 8
// speedup vs baseline: 2.8411x; 1.1715x over previous
#include <cuda_runtime.h>
#include <cuda_bf16.h>
#include <math.h>
#include <stdint.h>

#define E_ 8
#define B_ 16384
#define NAG 64
#define H_ 512
#define A_ 8
#define D_ 64
#define EB (E_*B_)

// ---------------- scratch (device globals; no allocation allowed) ----------------
__device__ __nv_bfloat16 g_encs_hi[(size_t)EB * H_];
__device__ __nv_bfloat16 g_encs_lo[(size_t)EB * H_];
__device__ float g_vals[(size_t)EB * H_];
__device__ float g_selk[(size_t)A_ * B_ * H_];
__device__ __nv_bfloat16 g_x_hi[(size_t)B_ * H_];
__device__ __nv_bfloat16 g_x_lo[(size_t)B_ * H_];
__device__ __nv_bfloat16 g_sn_hi[(size_t)EB * 64];     // normalized states
__device__ __nv_bfloat16 g_sn_lo[(size_t)EB * 64];
__device__ __nv_bfloat16 g_pa_hi[(size_t)B_ * H_];     // pre_actions
__device__ __nv_bfloat16 g_pa_lo[(size_t)B_ * H_];
__device__ __nv_bfloat16 g_pre_hi[(size_t)B_ * H_];
__device__ __nv_bfloat16 g_pre_lo[(size_t)B_ * H_];
__device__ __nv_bfloat16 g_sel_hi[(size_t)B_ * H_];
__device__ __nv_bfloat16 g_sel_lo[(size_t)B_ * H_];
__device__ __nv_bfloat16 g_attn_hi[(size_t)B_ * H_];
__device__ __nv_bfloat16 g_attn_lo[(size_t)B_ * H_];
// weights, all [n][k] k-major, bf16 hi/lo
__device__ __nv_bfloat16 g_WencT_hi[E_ * H_ * 64];     // [e][n=512][k=64]
__device__ __nv_bfloat16 g_WencT_lo[E_ * H_ * 64];
__device__ __nv_bfloat16 g_WpreT_hi[H_ * H_];
__device__ __nv_bfloat16 g_WpreT_lo[H_ * H_];
__device__ __nv_bfloat16 g_WselT_hi[H_ * H_];
__device__ __nv_bfloat16 g_WselT_lo[H_ * H_];
__device__ __nv_bfloat16 g_WvT_hi[H_ * H_];
__device__ __nv_bfloat16 g_WvT_lo[H_ * H_];
__device__ __nv_bfloat16 g_WactT_hi[H_ * H_];
__device__ __nv_bfloat16 g_WactT_lo[H_ * H_];
__device__ __nv_bfloat16 g_Wk_hi[A_ * H_ * D_];        // [a][n=h][k=d]
__device__ __nv_bfloat16 g_Wk_lo[A_ * H_ * D_];
__device__ __nv_bfloat16 g_WmlT_hi[128 * H_];          // [n=128][k=512] (mean|logstd)
__device__ __nv_bfloat16 g_WmlT_lo[128 * H_];
__device__ float g_bias_ml[128];
__device__ float g_part_sum[E_ * 32 * 64];
__device__ float g_part_sq[E_ * 32 * 64];
__device__ float g_mu[E_ * 64];
__device__ float g_rs[E_ * 64];

// ---------------- helpers ----------------
__device__ __forceinline__ uint32_t smem_u32(const void* p) {
    uint32_t a;
    asm("{ .reg .u64 t; cvta.to.shared.u64 t, %1; cvt.u32.u64 %0, t; }" : "=r"(a) : "l"(p));
    return a;
}
__device__ __forceinline__ void split2(float v, unsigned short& h, unsigned short& l) {
    __nv_bfloat16 bh = __float2bfloat16(v);
    __nv_bfloat16 bl = __float2bfloat16(v - __bfloat162float(bh));
    h = *(unsigned short*)&bh;
    l = *(unsigned short*)&bl;
}
template<int ACT>
__device__ __forceinline__ float act_fn(float v) {
    if constexpr (ACT == 1) return v >= 0.f ? v : 0.01f * v;
    else if constexpr (ACT == 2) return fmaxf(v, 0.f);
    else if constexpr (ACT == 3) return fminf(fmaxf(v, -20.f), 2.f);
    else return v;
}
#define CP16(dst, src) asm volatile("cp.async.cg.shared.global [%0], [%1], 16;" :: "r"(dst), "l"(src))
__device__ __forceinline__ void ldsm4(uint32_t* r, uint32_t a) {
    asm volatile("ldmatrix.sync.aligned.m8n8.x4.shared.b16 {%0,%1,%2,%3}, [%4];"
        : "=r"(r[0]), "=r"(r[1]), "=r"(r[2]), "=r"(r[3]) : "r"(a));
}
__device__ __forceinline__ void mma_bf16(float* d, const uint32_t* a, const uint32_t* b) {
    asm volatile("mma.sync.aligned.m16n8k16.row.col.f32.bf16.bf16.f32 "
        "{%0,%1,%2,%3}, {%4,%5,%6,%7}, {%8,%9}, {%0,%1,%2,%3};"
        : "+f"(d[0]), "+f"(d[1]), "+f"(d[2]), "+f"(d[3])
        : "r"(a[0]), "r"(a[1]), "r"(a[2]), "r"(a[3]), "r"(b[0]), "r"(b[1]));
}
// smem layout per [128 rows x 32 cols bf16] matrix: swizzled 16B chunks.
__device__ __forceinline__ uint32_t swz(int row, int g) {
    int l = row >> 1;
    int c = (g | ((row & 1) << 2)) ^ (l & 7);
    return (uint32_t)((l << 7) + (c << 4));
}

// ---------------- batchnorm stats ----------------
__global__ void bn_part_kernel(const float* __restrict__ states) {
    int e = blockIdx.x, ch = blockIdx.y;
    int n = threadIdx.x, ty = threadIdx.y;
    const float* base = states + ((size_t)e * B_ + (size_t)ch * 512) * 64;
    float s = 0.f, q = 0.f;
    for (int r = ty; r < 512; r += 4) {
        float v = base[(size_t)r * 64 + n];
        s += v; q += v * v;
    }
    __shared__ float ss[4][64], sq[4][64];
    ss[ty][n] = s; sq[ty][n] = q;
    __syncthreads();
    if (ty == 0) {
        s = ss[0][n] + ss[1][n] + ss[2][n] + ss[3][n];
        q = sq[0][n] + sq[1][n] + sq[2][n] + sq[3][n];
        g_part_sum[(e * 32 + ch) * 64 + n] = s;
        g_part_sq [(e * 32 + ch) * 64 + n] = q;
    }
}
__global__ void bn_final_kernel() {
    int i = threadIdx.x;
    int e = i >> 6, n = i & 63;
    float s = 0.f, q = 0.f;
    for (int j = 0; j < 32; j++) {
        s += g_part_sum[(e * 32 + j) * 64 + n];
        q += g_part_sq [(e * 32 + j) * 64 + n];
    }
    float mean = s * (1.f / B_);
    float var  = q * (1.f / B_) - mean * mean;
    g_mu[i] = mean;
    g_rs[i] = 1.f / sqrtf(var + 1e-5f);
}

// ---------------- converters ----------------
__global__ void cvt_pa_kernel(const float* __restrict__ src) {
    size_t i = (size_t)blockIdx.x * 256 + threadIdx.x;   // over B_*512/4
    float4 v = ((const float4*)src)[i];
    unsigned short hh[4], ll[4];
    split2(v.x, hh[0], ll[0]); split2(v.y, hh[1], ll[1]);
    split2(v.z, hh[2], ll[2]); split2(v.w, hh[3], ll[3]);
    *(uint2*)&g_pa_hi[i * 4] = *(uint2*)hh;
    *(uint2*)&g_pa_lo[i * 4] = *(uint2*)ll;
}
__global__ void snorm_kernel(const float* __restrict__ states) {
    size_t i = (size_t)blockIdx.x * 256 + threadIdx.x;   // over EB*64/4
    float4 v = ((const float4*)states)[i];
    size_t row = i >> 4;
    int n = (int)(i & 15) * 4;
    int kb = (int)(row >> 14) * 64 + n;
    v.x = (v.x - g_mu[kb + 0]) * g_rs[kb + 0];
    v.y = (v.y - g_mu[kb + 1]) * g_rs[kb + 1];
    v.z = (v.z - g_mu[kb + 2]) * g_rs[kb + 2];
    v.w = (v.w - g_mu[kb + 3]) * g_rs[kb + 3];
    unsigned short hh[4], ll[4];
    split2(v.x, hh[0], ll[0]); split2(v.y, hh[1], ll[1]);
    split2(v.z, hh[2], ll[2]); split2(v.w, hh[3], ll[3]);
    *(uint2*)&g_sn_hi[i * 4] = *(uint2*)hh;
    *(uint2*)&g_sn_lo[i * 4] = *(uint2*)ll;
}
__global__ void repack2_kernel(const float* __restrict__ Wk, const float* __restrict__ Wv,
                               const float* __restrict__ Wsel, const float* __restrict__ W_pre,
                               const float* __restrict__ W_actor, const float* __restrict__ W_enc,
                               const float* __restrict__ W_mean, const float* __restrict__ W_logstd,
                               const float* __restrict__ b_mean, const float* __restrict__ b_logstd) {
    int i = blockIdx.x * 256 + threadIdx.x;   // 262144
    int k = i >> 9, n = i & 511;
    unsigned short h, l;
    int dst = n * 512 + k;
    split2(W_pre[i], h, l);   g_WpreT_hi[dst] = *(__nv_bfloat16*)&h; g_WpreT_lo[dst] = *(__nv_bfloat16*)&l;
    split2(W_actor[i], h, l); g_WactT_hi[dst] = *(__nv_bfloat16*)&h; g_WactT_lo[dst] = *(__nv_bfloat16*)&l;
    int a = n >> 6, dd = n & 63;
    int srcv = a * 32768 + k * 64 + dd;
    split2(Wv[srcv], h, l);   g_WvT_hi[dst] = *(__nv_bfloat16*)&h;   g_WvT_lo[dst] = *(__nv_bfloat16*)&l;
    split2(Wsel[srcv], h, l); g_WselT_hi[dst] = *(__nv_bfloat16*)&h; g_WselT_lo[dst] = *(__nv_bfloat16*)&l;
    split2(Wk[i], h, l);      g_Wk_hi[i] = *(__nv_bfloat16*)&h;      g_Wk_lo[i] = *(__nv_bfloat16*)&l;
    // W_enc: [E][64][512] -> [e][n][k]
    int e2 = i >> 15, rem = i & 32767, ne = rem >> 6, ke = rem & 63;
    split2(W_enc[e2 * 32768 + ke * 512 + ne], h, l);
    g_WencT_hi[i] = *(__nv_bfloat16*)&h; g_WencT_lo[i] = *(__nv_bfloat16*)&l;
    // W_mean|W_logstd: [512][64] each -> combined [n2=128][k2=512]
    if (i < 128 * 512) {
        int n2 = i & 127, k2 = i >> 7;
        float v = (n2 < 64) ? W_mean[k2 * 64 + n2] : W_logstd[k2 * 64 + (n2 - 64)];
        split2(v, h, l);
        g_WmlT_hi[n2 * 512 + k2] = *(__nv_bfloat16*)&h;
        g_WmlT_lo[n2 * 512 + k2] = *(__nv_bfloat16*)&l;
    }
    if (i < 128) g_bias_ml[i] = (i < 64) ? b_mean[i] : b_logstd[i - 64];
}

// ---------------- mma.sync bf16x3 GEMM: C[M,512] = act(A[M,K] @ B^T + bias) ----------------
// CTA 128x128, 8 warps each 32x64, cp.async double-buffered k32 chunks.
// B frags loaded per-j and consumed immediately -> ~120 live regs -> 2 CTAs/SM.
template<int ACT, bool HAS_BIAS, bool WRITE_F32, bool EMIT, bool PERENC, bool PERHEAD, bool HEADOUT>
__global__ __launch_bounds__(256, 2) void mma_gemm(
    const __nv_bfloat16* __restrict__ Ahi, const __nv_bfloat16* __restrict__ Alo,
    const __nv_bfloat16* __restrict__ Bhi, const __nv_bfloat16* __restrict__ Blo,
    const float* __restrict__ bias,
    float* __restrict__ C, float* __restrict__ C2,
    __nv_bfloat16* __restrict__ Chi, __nv_bfloat16* __restrict__ Clo,
    int K, int lda)
{
    extern __shared__ char smem[];
    const int tid = threadIdx.x;
    const int lane = tid & 31, wid = tid >> 5;
    const int m0 = blockIdx.y * 128, n0 = blockIdx.x * 128;
    const int wm = (wid & 3) * 32, wn = (wid >> 2) * 64;

    if constexpr (PERENC) {
        int e = m0 >> 14;
        Bhi += (size_t)e * 512 * K;
        Blo += (size_t)e * 512 * K;
        if constexpr (HAS_BIAS) bias += e * 512;
    }
    if constexpr (PERHEAD) {
        int z = blockIdx.z;
        Ahi += z * 64; Alo += z * 64;
        Bhi += (size_t)z * 512 * K;
        Blo += (size_t)z * 512 * K;
        size_t co = (size_t)z * B_ * 512;
        if constexpr (WRITE_F32) C += co;
        if constexpr (EMIT) { Chi += co; Clo += co; }
    }

    uint32_t sb = smem_u32(smem);
    const int prow = tid >> 1, ph = tid & 1;
    const __nv_bfloat16* pA0 = Ahi + (size_t)(m0 + prow) * lda + ph * 16;
    const __nv_bfloat16* pA1 = Alo + (size_t)(m0 + prow) * lda + ph * 16;
    const __nv_bfloat16* pB0 = Bhi + (size_t)(n0 + prow) * K + ph * 16;
    const __nv_bfloat16* pB1 = Blo + (size_t)(n0 + prow) * K + ph * 16;
    const uint32_t d0 = swz(prow, ph * 2), d1 = swz(prow, ph * 2 + 1);

    auto prefetch = [&](int buf, int kc) {
        uint32_t base = sb + buf * 32768;
        CP16(base + d0,          (const char*)(pA0 + kc * 32));
        CP16(base + d1,          (const char*)(pA0 + kc * 32 + 8));
        CP16(base + 8192 + d0,   (const char*)(pA1 + kc * 32));
        CP16(base + 8192 + d1,   (const char*)(pA1 + kc * 32 + 8));
        CP16(base + 16384 + d0,  (const char*)(pB0 + kc * 32));
        CP16(base + 16384 + d1,  (const char*)(pB0 + kc * 32 + 8));
        CP16(base + 24576 + d0,  (const char*)(pB1 + kc * 32));
        CP16(base + 24576 + d1,  (const char*)(pB1 + kc * 32 + 8));
        asm volatile("cp.async.commit_group;");
    };

    float d[2][8][4] = {};
    const int lrow = lane & 7, grp = lane >> 3;

    auto compute = [&](int buf) {
        uint32_t base = sb + buf * 32768;
        #pragma unroll
        for (int s = 0; s < 2; s++) {
            uint32_t ahi[2][4], alo[2][4];
            #pragma unroll
            for (int i = 0; i < 2; i++) {
                int row = wm + i * 16 + (grp & 1) * 8 + lrow;
                int g = s * 2 + (grp >> 1);
                uint32_t off = swz(row, g);
                ldsm4(ahi[i], base + off);
                ldsm4(alo[i], base + 8192 + off);
            }
            #pragma unroll
            for (int j = 0; j < 4; j++) {
                int row = wn + j * 16 + (grp >> 1) * 8 + lrow;
                int g = s * 2 + (grp & 1);
                uint32_t off = swz(row, g);
                uint32_t bh[4], bl[4];
                ldsm4(bh, base + 16384 + off);   // -> b cols j*16.. as two n8 frags
                #pragma unroll
                for (int i = 0; i < 2; i++) {
                    mma_bf16(d[i][j*2],     ahi[i], bh);
                    mma_bf16(d[i][j*2 + 1], ahi[i], bh + 2);
                    mma_bf16(d[i][j*2],     alo[i], bh);
                    mma_bf16(d[i][j*2 + 1], alo[i], bh + 2);
                }
                ldsm4(bl, base + 24576 + off);
                #pragma unroll
                for (int i = 0; i < 2; i++) {
                    mma_bf16(d[i][j*2],     ahi[i], bl);
                    mma_bf16(d[i][j*2 + 1], ahi[i], bl + 2);
                }
            }
        }
    };

    const int NCH = K >> 5;
    prefetch(0, 0);
    for (int kc = 0; kc < NCH; kc++) {
        if (kc + 1 < NCH) {
            prefetch((kc + 1) & 1, kc + 1);
            asm volatile("cp.async.wait_group 1;");
        } else {
            asm volatile("cp.async.wait_group 0;");
        }
        __syncthreads();
        compute(kc & 1);
        __syncthreads();
    }

    // epilogue: frags -> smem stage -> coalesced global
    float* stage = (float*)smem;   // [128][132]
    #pragma unroll
    for (int i = 0; i < 2; i++)
        #pragma unroll
        for (int j = 0; j < 8; j++) {
            int r = wm + i * 16 + (lane >> 2);
            int cc = wn + j * 8 + (lane & 3) * 2;
            stage[r * 132 + cc]       = d[i][j][0];
            stage[r * 132 + cc + 1]   = d[i][j][1];
            stage[(r + 8) * 132 + cc]     = d[i][j][2];
            stage[(r + 8) * 132 + cc + 1] = d[i][j][3];
        }
    __syncthreads();
    #pragma unroll
    for (int k2 = 0; k2 < 16; k2++) {
        int s = tid + k2 * 256;
        int row = s >> 5, q = s & 31;
        float4 v = *(const float4*)&stage[row * 132 + q * 4];
        int col = n0 + q * 4;
        float o[4] = {v.x, v.y, v.z, v.w};
        if constexpr (HAS_BIAS) {
            o[0] += bias[col]; o[1] += bias[col + 1];
            o[2] += bias[col + 2]; o[3] += bias[col + 3];
        }
        if constexpr (HEADOUT) {
            size_t r = (size_t)(m0 + row);
            if (col < 64) {
                *(float4*)&C[r * 64 + col] = make_float4(o[0], o[1], o[2], o[3]);
            } else {
                #pragma unroll
                for (int c2 = 0; c2 < 4; c2++) o[c2] = fminf(fmaxf(o[c2], -20.f), 2.f);
                *(float4*)&C2[r * 64 + col - 64] = make_float4(o[0], o[1], o[2], o[3]);
            }
        } else {
            #pragma unroll
            for (int c2 = 0; c2 < 4; c2++) o[c2] = act_fn<ACT>(o[c2]);
            size_t idx = (size_t)(m0 + row) * 512 + col;
            if constexpr (WRITE_F32)
                *(float4*)&C[idx] = make_float4(o[0], o[1], o[2], o[3]);
            if constexpr (EMIT) {
                unsigned short hh[4], ll[4];
                split2(o[0], hh[0], ll[0]); split2(o[1], hh[1], ll[1]);
                split2(o[2], hh[2], ll[2]); split2(o[3], hh[3], ll[3]);
                *(uint2*)&Chi[idx] = *(uint2*)hh;
                *(uint2*)&Clo[idx] = *(uint2*)ll;
            }
        }
    }
}

// ---------------- attention: logits (selk . encs) -> softmax -> weighted vals ----------------
__global__ __launch_bounds__(64) void attn_kernel(float* __restrict__ actor_in) {
    __shared__ float sk[8][516];
    __shared__ float en[8][516];
    __shared__ float w_s[64];
    int j = threadIdx.x;
    size_t b = blockIdx.x;

    #pragma unroll
    for (int a = 0; a < 8; a++)
        #pragma unroll
        for (int m = 0; m < 8; m++)
            sk[a][m * 64 + j] = g_selk[((size_t)a * B_ + b) * 512 + m * 64 + j];
    #pragma unroll
    for (int e = 0; e < 8; e++)
        #pragma unroll
        for (int m = 0; m < 8; m++) {
            size_t idx = ((size_t)e * B_ + b) * 512 + m * 64 + j;
            en[e][m * 64 + j] = __bfloat162float(g_encs_hi[idx]) + __bfloat162float(g_encs_lo[idx]);
        }
    __syncthreads();

    int a = j >> 3, e = j & 7;
    float lg = 0.f;
    const float* sp = sk[a];
    const float* ep = en[e];
    #pragma unroll 8
    for (int h = 0; h < 512; h++) lg = fmaf(sp[h], ep[h], lg);
    lg *= 0.125f;

    float mx = lg;
    #pragma unroll
    for (int o = 4; o >= 1; o >>= 1) mx = fmaxf(mx, __shfl_xor_sync(0xffffffffu, mx, o));
    float ex = expf(lg - mx);
    float sm = ex;
    #pragma unroll
    for (int o = 4; o >= 1; o >>= 1) sm += __shfl_xor_sync(0xffffffffu, sm, o);
    w_s[j] = ex / sm;
    __syncthreads();

    #pragma unroll
    for (int m = 0; m < 8; m++) {
        int c = m * 64 + j;
        float acc = 0.f;
        #pragma unroll
        for (int ee = 0; ee < 8; ee++)
            acc = fmaf(w_s[m * 8 + ee], g_vals[((size_t)ee * B_ + b) * 512 + c], acc);
        actor_in[b * 512 + c] = acc;
        unsigned short hh, ll;
        split2(acc, hh, ll);
        g_attn_hi[b * 512 + c] = *(__nv_bfloat16*)&hh;
        g_attn_lo[b * 512 + c] = *(__nv_bfloat16*)&ll;
    }
}

// ---------------- launch ----------------
#define MMA_SMEM 67584

extern "C" void kernel_launch(void* const* d_in, const int* in_sizes, int n_in,
                              void* d_out, int out_size) {
    const float* states      = (const float*)d_in[0];
    const float* pre_actions = (const float*)d_in[1];
    const float* W_enc       = (const float*)d_in[2];
    const float* b_enc       = (const float*)d_in[3];
    const float* W_pre       = (const float*)d_in[4];
    const float* b_pre       = (const float*)d_in[5];
    const float* Wk          = (const float*)d_in[6];
    const float* Wsel        = (const float*)d_in[7];
    const float* Wv          = (const float*)d_in[8];
    const float* bv          = (const float*)d_in[9];
    const float* W_actor     = (const float*)d_in[10];
    const float* b_actor     = (const float*)d_in[11];
    const float* W_mean      = (const float*)d_in[12];
    const float* b_mean      = (const float*)d_in[13];
    const float* W_logstd    = (const float*)d_in[14];
    const float* b_logstd    = (const float*)d_in[15];

    float* out        = (float*)d_out;
    float* out_mean   = out;
    float* out_logstd = out + (size_t)B_ * NAG;
    float* out_actor  = out + (size_t)2 * B_ * NAG;

    float *vals, *selk, *bias_ml;
    __nv_bfloat16 *encs_hi, *encs_lo, *sn_hi, *sn_lo, *pa_hi, *pa_lo;
    __nv_bfloat16 *pre_hi, *pre_lo, *sel_hi, *sel_lo, *attn_hi, *attn_lo, *x_hi, *x_lo;
    __nv_bfloat16 *WencT_hi, *WencT_lo, *WpreT_hi, *WpreT_lo, *WselT_hi, *WselT_lo;
    __nv_bfloat16 *WvT_hi, *WvT_lo, *WactT_hi, *WactT_lo, *Wk_hi, *Wk_lo, *WmlT_hi, *WmlT_lo;
    cudaGetSymbolAddress((void**)&vals,    g_vals);
    cudaGetSymbolAddress((void**)&selk,    g_selk);
    cudaGetSymbolAddress((void**)&bias_ml, g_bias_ml);
    cudaGetSymbolAddress((void**)&encs_hi, g_encs_hi);
    cudaGetSymbolAddress((void**)&encs_lo, g_encs_lo);
    cudaGetSymbolAddress((void**)&sn_hi,   g_sn_hi);
    cudaGetSymbolAddress((void**)&sn_lo,   g_sn_lo);
    cudaGetSymbolAddress((void**)&pa_hi,   g_pa_hi);
    cudaGetSymbolAddress((void**)&pa_lo,   g_pa_lo);
    cudaGetSymbolAddress((void**)&pre_hi,  g_pre_hi);
    cudaGetSymbolAddress((void**)&pre_lo,  g_pre_lo);
    cudaGetSymbolAddress((void**)&sel_hi,  g_sel_hi);
    cudaGetSymbolAddress((void**)&sel_lo,  g_sel_lo);
    cudaGetSymbolAddress((void**)&attn_hi, g_attn_hi);
    cudaGetSymbolAddress((void**)&attn_lo, g_attn_lo);
    cudaGetSymbolAddress((void**)&x_hi,    g_x_hi);
    cudaGetSymbolAddress((void**)&x_lo,    g_x_lo);
    cudaGetSymbolAddress((void**)&WencT_hi, g_WencT_hi);
    cudaGetSymbolAddress((void**)&WencT_lo, g_WencT_lo);
    cudaGetSymbolAddress((void**)&WpreT_hi, g_WpreT_hi);
    cudaGetSymbolAddress((void**)&WpreT_lo, g_WpreT_lo);
    cudaGetSymbolAddress((void**)&WselT_hi, g_WselT_hi);
    cudaGetSymbolAddress((void**)&WselT_lo, g_WselT_lo);
    cudaGetSymbolAddress((void**)&WvT_hi,  g_WvT_hi);
    cudaGetSymbolAddress((void**)&WvT_lo,  g_WvT_lo);
    cudaGetSymbolAddress((void**)&WactT_hi, g_WactT_hi);
    cudaGetSymbolAddress((void**)&WactT_lo, g_WactT_lo);
    cudaGetSymbolAddress((void**)&Wk_hi,   g_Wk_hi);
    cudaGetSymbolAddress((void**)&Wk_lo,   g_Wk_lo);
    cudaGetSymbolAddress((void**)&WmlT_hi, g_WmlT_hi);
    cudaGetSymbolAddress((void**)&WmlT_lo, g_WmlT_lo);

    auto enc_k  = mma_gemm<1, true,  false, true,  true,  false, false>;
    auto pre_k  = mma_gemm<1, true,  false, true,  false, false, false>;
    auto sel_k  = mma_gemm<0, false, false, true,  false, false, false>;
    auto selk_k = mma_gemm<0, false, true,  false, false, true,  false>;
    auto vals_k = mma_gemm<1, true,  true,  false, false, false, false>;
    auto x_k    = mma_gemm<2, true,  false, true,  false, false, false>;
    auto ml_k   = mma_gemm<0, true,  false, false, false, false, true>;
    cudaFuncSetAttribute(enc_k,  cudaFuncAttributeMaxDynamicSharedMemorySize, MMA_SMEM);
    cudaFuncSetAttribute(pre_k,  cudaFuncAttributeMaxDynamicSharedMemorySize, MMA_SMEM);
    cudaFuncSetAttribute(sel_k,  cudaFuncAttributeMaxDynamicSharedMemorySize, MMA_SMEM);
    cudaFuncSetAttribute(selk_k, cudaFuncAttributeMaxDynamicSharedMemorySize, MMA_SMEM);
    cudaFuncSetAttribute(vals_k, cudaFuncAttributeMaxDynamicSharedMemorySize, MMA_SMEM);
    cudaFuncSetAttribute(x_k,    cudaFuncAttributeMaxDynamicSharedMemorySize, MMA_SMEM);
    cudaFuncSetAttribute(ml_k,   cudaFuncAttributeMaxDynamicSharedMemorySize, MMA_SMEM);

    // stats + conversions + repacks
    bn_part_kernel<<<dim3(E_, 32), dim3(64, 4)>>>(states);
    bn_final_kernel<<<1, 512>>>();
    repack2_kernel<<<1024, 256>>>(Wk, Wv, Wsel, W_pre, W_actor, W_enc,
                                  W_mean, W_logstd, b_mean, b_logstd);
    cvt_pa_kernel<<<8192, 256>>>(pre_actions);
    snorm_kernel<<<8192, 256>>>(states);

    // encs = leaky(snorm @ W_enc + b_enc), K=64, per-encoder; emit hi/lo only
    enc_k<<<dim3(4, 1024), 256, MMA_SMEM>>>(sn_hi, sn_lo, WencT_hi, WencT_lo, b_enc,
                                            nullptr, nullptr, encs_hi, encs_lo, 64, 64);
    // pre = leaky(pre_actions @ W_pre + b_pre), emit hi/lo
    pre_k<<<dim3(4, 128), 256, MMA_SMEM>>>(pa_hi, pa_lo, WpreT_hi, WpreT_lo, b_pre,
                                           nullptr, nullptr, pre_hi, pre_lo, 512, 512);
    // sel = pre @ Wsel, emit hi/lo
    sel_k<<<dim3(4, 128), 256, MMA_SMEM>>>(pre_hi, pre_lo, WselT_hi, WselT_lo, nullptr,
                                           nullptr, nullptr, sel_hi, sel_lo, 512, 512);
    // selk[a] = sel[:, a*64:+64] @ Wk[a]^T, K=64, per-head; fp32
    selk_k<<<dim3(4, 128, 8), 256, MMA_SMEM>>>(sel_hi, sel_lo, Wk_hi, Wk_lo, nullptr,
                                               selk, nullptr, nullptr, nullptr, 64, 512);
    // vals = leaky(encs @ Wv + bv); fp32
    vals_k<<<dim3(4, 1024), 256, MMA_SMEM>>>(encs_hi, encs_lo, WvT_hi, WvT_lo, bv,
                                             vals, nullptr, nullptr, nullptr, 512, 512);
    // attention -> actor_in (+ hi/lo for actor GEMM)
    attn_kernel<<<B_, 64>>>(out_actor);
    // x = relu(actor_in @ W_actor + b_actor); emit hi/lo
    x_k<<<dim3(4, 128), 256, MMA_SMEM>>>(attn_hi, attn_lo, WactT_hi, WactT_lo, b_actor,
                                         nullptr, nullptr, x_hi, x_lo, 512, 512);
    // mean | log_std fused, N=128, K=512
    ml_k<<<dim3(1, 128), 256, MMA_SMEM>>>(x_hi, x_lo, WmlT_hi, WmlT_lo, bias_ml,
                                          out_mean, out_logstd, nullptr, nullptr, 512, 512);
}

// round 11
// speedup vs baseline: 2.8711x; 1.0106x over previous
#include <cuda_runtime.h>
#include <cuda_bf16.h>
#include <math.h>
#include <stdint.h>

#define E_ 8
#define B_ 16384
#define NAG 64
#define H_ 512
#define A_ 8
#define D_ 64
#define EB (E_*B_)

// ---------------- scratch (device globals; no allocation allowed) ----------------
__device__ __nv_bfloat16 g_encs_hi[(size_t)EB * H_];
__device__ __nv_bfloat16 g_encs_lo[(size_t)EB * H_];
__device__ float g_vals[(size_t)EB * H_];
__device__ float g_selk[(size_t)A_ * B_ * H_];
__device__ __nv_bfloat16 g_x_hi[(size_t)B_ * H_];
__device__ __nv_bfloat16 g_x_lo[(size_t)B_ * H_];
__device__ __nv_bfloat16 g_sn_hi[(size_t)EB * 64];     // normalized states
__device__ __nv_bfloat16 g_sn_lo[(size_t)EB * 64];
__device__ __nv_bfloat16 g_pa_hi[(size_t)B_ * H_];     // pre_actions
__device__ __nv_bfloat16 g_pa_lo[(size_t)B_ * H_];
__device__ __nv_bfloat16 g_pre_hi[(size_t)B_ * H_];
__device__ __nv_bfloat16 g_pre_lo[(size_t)B_ * H_];
__device__ __nv_bfloat16 g_sel_hi[(size_t)B_ * H_];
__device__ __nv_bfloat16 g_sel_lo[(size_t)B_ * H_];
__device__ __nv_bfloat16 g_attn_hi[(size_t)B_ * H_];
__device__ __nv_bfloat16 g_attn_lo[(size_t)B_ * H_];
// weights, all [n][k] k-major, bf16 hi/lo
__device__ __nv_bfloat16 g_WencT_hi[E_ * H_ * 64];     // [e][n=512][k=64]
__device__ __nv_bfloat16 g_WencT_lo[E_ * H_ * 64];
__device__ __nv_bfloat16 g_WpreT_hi[H_ * H_];
__device__ __nv_bfloat16 g_WpreT_lo[H_ * H_];
__device__ __nv_bfloat16 g_WselT_hi[H_ * H_];
__device__ __nv_bfloat16 g_WselT_lo[H_ * H_];
__device__ __nv_bfloat16 g_WvT_hi[H_ * H_];
__device__ __nv_bfloat16 g_WvT_lo[H_ * H_];
__device__ __nv_bfloat16 g_WactT_hi[H_ * H_];
__device__ __nv_bfloat16 g_WactT_lo[H_ * H_];
__device__ __nv_bfloat16 g_Wk_hi[A_ * H_ * D_];        // [a][n=h][k=d]
__device__ __nv_bfloat16 g_Wk_lo[A_ * H_ * D_];
__device__ __nv_bfloat16 g_WmlT_hi[128 * H_];          // [n=128][k=512] (mean|logstd)
__device__ __nv_bfloat16 g_WmlT_lo[128 * H_];
__device__ float g_bias_ml[128];
__device__ float g_part_sum[E_ * 32 * 64];
__device__ float g_part_sq[E_ * 32 * 64];
__device__ float g_mu[E_ * 64];
__device__ float g_rs[E_ * 64];

// ---------------- helpers ----------------
__device__ __forceinline__ uint32_t smem_u32(const void* p) {
    uint32_t a;
    asm("{ .reg .u64 t; cvta.to.shared.u64 t, %1; cvt.u32.u64 %0, t; }" : "=r"(a) : "l"(p));
    return a;
}
__device__ __forceinline__ void split2(float v, unsigned short& h, unsigned short& l) {
    __nv_bfloat16 bh = __float2bfloat16(v);
    __nv_bfloat16 bl = __float2bfloat16(v - __bfloat162float(bh));
    h = *(unsigned short*)&bh;
    l = *(unsigned short*)&bl;
}
template<int ACT>
__device__ __forceinline__ float act_fn(float v) {
    if constexpr (ACT == 1) return v >= 0.f ? v : 0.01f * v;
    else if constexpr (ACT == 2) return fmaxf(v, 0.f);
    else if constexpr (ACT == 3) return fminf(fmaxf(v, -20.f), 2.f);
    else return v;
}
#define CP16(dst, src) asm volatile("cp.async.cg.shared.global [%0], [%1], 16;" :: "r"(dst), "l"(src))
__device__ __forceinline__ void ldsm4(uint32_t* r, uint32_t a) {
    asm volatile("ldmatrix.sync.aligned.m8n8.x4.shared.b16 {%0,%1,%2,%3}, [%4];"
        : "=r"(r[0]), "=r"(r[1]), "=r"(r[2]), "=r"(r[3]) : "r"(a));
}
__device__ __forceinline__ void mma_bf16(float* d, const uint32_t* a, const uint32_t* b) {
    asm volatile("mma.sync.aligned.m16n8k16.row.col.f32.bf16.bf16.f32 "
        "{%0,%1,%2,%3}, {%4,%5,%6,%7}, {%8,%9}, {%0,%1,%2,%3};"
        : "+f"(d[0]), "+f"(d[1]), "+f"(d[2]), "+f"(d[3])
        : "r"(a[0]), "r"(a[1]), "r"(a[2]), "r"(a[3]), "r"(b[0]), "r"(b[1]));
}
// smem layout per [128 rows x 32 cols bf16] matrix: swizzled 16B chunks.
__device__ __forceinline__ uint32_t swz(int row, int g) {
    int l = row >> 1;
    int c = (g | ((row & 1) << 2)) ^ (l & 7);
    return (uint32_t)((l << 7) + (c << 4));
}

// ---------------- batchnorm stats ----------------
__global__ void bn_part_kernel(const float* __restrict__ states) {
    int e = blockIdx.x, ch = blockIdx.y;
    int n = threadIdx.x, ty = threadIdx.y;
    const float* base = states + ((size_t)e * B_ + (size_t)ch * 512) * 64;
    float s = 0.f, q = 0.f;
    for (int r = ty; r < 512; r += 4) {
        float v = base[(size_t)r * 64 + n];
        s += v; q += v * v;
    }
    __shared__ float ss[4][64], sq[4][64];
    ss[ty][n] = s; sq[ty][n] = q;
    __syncthreads();
    if (ty == 0) {
        s = ss[0][n] + ss[1][n] + ss[2][n] + ss[3][n];
        q = sq[0][n] + sq[1][n] + sq[2][n] + sq[3][n];
        g_part_sum[(e * 32 + ch) * 64 + n] = s;
        g_part_sq [(e * 32 + ch) * 64 + n] = q;
    }
}
__global__ void bn_final_kernel() {
    int i = threadIdx.x;
    int e = i >> 6, n = i & 63;
    float s = 0.f, q = 0.f;
    for (int j = 0; j < 32; j++) {
        s += g_part_sum[(e * 32 + j) * 64 + n];
        q += g_part_sq [(e * 32 + j) * 64 + n];
    }
    float mean = s * (1.f / B_);
    float var  = q * (1.f / B_) - mean * mean;
    g_mu[i] = mean;
    g_rs[i] = 1.f / sqrtf(var + 1e-5f);
}

// ---------------- converters ----------------
__global__ void cvt_pa_kernel(const float* __restrict__ src) {
    size_t i = (size_t)blockIdx.x * 256 + threadIdx.x;   // over B_*512/4
    float4 v = ((const float4*)src)[i];
    unsigned short hh[4], ll[4];
    split2(v.x, hh[0], ll[0]); split2(v.y, hh[1], ll[1]);
    split2(v.z, hh[2], ll[2]); split2(v.w, hh[3], ll[3]);
    *(uint2*)&g_pa_hi[i * 4] = *(uint2*)hh;
    *(uint2*)&g_pa_lo[i * 4] = *(uint2*)ll;
}
__global__ void snorm_kernel(const float* __restrict__ states) {
    size_t i = (size_t)blockIdx.x * 256 + threadIdx.x;   // over EB*64/4
    float4 v = ((const float4*)states)[i];
    size_t row = i >> 4;
    int n = (int)(i & 15) * 4;
    int kb = (int)(row >> 14) * 64 + n;
    v.x = (v.x - g_mu[kb + 0]) * g_rs[kb + 0];
    v.y = (v.y - g_mu[kb + 1]) * g_rs[kb + 1];
    v.z = (v.z - g_mu[kb + 2]) * g_rs[kb + 2];
    v.w = (v.w - g_mu[kb + 3]) * g_rs[kb + 3];
    unsigned short hh[4], ll[4];
    split2(v.x, hh[0], ll[0]); split2(v.y, hh[1], ll[1]);
    split2(v.z, hh[2], ll[2]); split2(v.w, hh[3], ll[3]);
    *(uint2*)&g_sn_hi[i * 4] = *(uint2*)hh;
    *(uint2*)&g_sn_lo[i * 4] = *(uint2*)ll;
}
__global__ void repack2_kernel(const float* __restrict__ Wk, const float* __restrict__ Wv,
                               const float* __restrict__ Wsel, const float* __restrict__ W_pre,
                               const float* __restrict__ W_actor, const float* __restrict__ W_enc,
                               const float* __restrict__ W_mean, const float* __restrict__ W_logstd,
                               const float* __restrict__ b_mean, const float* __restrict__ b_logstd) {
    int i = blockIdx.x * 256 + threadIdx.x;   // 262144
    int k = i >> 9, n = i & 511;
    unsigned short h, l;
    int dst = n * 512 + k;
    split2(W_pre[i], h, l);   g_WpreT_hi[dst] = *(__nv_bfloat16*)&h; g_WpreT_lo[dst] = *(__nv_bfloat16*)&l;
    split2(W_actor[i], h, l); g_WactT_hi[dst] = *(__nv_bfloat16*)&h; g_WactT_lo[dst] = *(__nv_bfloat16*)&l;
    int a = n >> 6, dd = n & 63;
    int srcv = a * 32768 + k * 64 + dd;
    split2(Wv[srcv], h, l);   g_WvT_hi[dst] = *(__nv_bfloat16*)&h;   g_WvT_lo[dst] = *(__nv_bfloat16*)&l;
    split2(Wsel[srcv], h, l); g_WselT_hi[dst] = *(__nv_bfloat16*)&h; g_WselT_lo[dst] = *(__nv_bfloat16*)&l;
    split2(Wk[i], h, l);      g_Wk_hi[i] = *(__nv_bfloat16*)&h;      g_Wk_lo[i] = *(__nv_bfloat16*)&l;
    // W_enc: [E][64][512] -> [e][n][k]
    int e2 = i >> 15, rem = i & 32767, ne = rem >> 6, ke = rem & 63;
    split2(W_enc[e2 * 32768 + ke * 512 + ne], h, l);
    g_WencT_hi[i] = *(__nv_bfloat16*)&h; g_WencT_lo[i] = *(__nv_bfloat16*)&l;
    // W_mean|W_logstd: [512][64] each -> combined [n2=128][k2=512]
    if (i < 128 * 512) {
        int n2 = i & 127, k2 = i >> 7;
        float v = (n2 < 64) ? W_mean[k2 * 64 + n2] : W_logstd[k2 * 64 + (n2 - 64)];
        split2(v, h, l);
        g_WmlT_hi[n2 * 512 + k2] = *(__nv_bfloat16*)&h;
        g_WmlT_lo[n2 * 512 + k2] = *(__nv_bfloat16*)&l;
    }
    if (i < 128) g_bias_ml[i] = (i < 64) ? b_mean[i] : b_logstd[i - 64];
}

// ---------------- mma.sync bf16x3 GEMM: C[M,512] = act(A[M,K] @ B^T + bias) ----------------
// CTA 128x128, 8 warps each 32x64, cp.async 3-stage ring, one barrier per chunk.
template<int ACT, bool HAS_BIAS, bool WRITE_F32, bool EMIT, bool PERENC, bool PERHEAD, bool HEADOUT>
__global__ __launch_bounds__(256, 2) void mma_gemm(
    const __nv_bfloat16* __restrict__ Ahi, const __nv_bfloat16* __restrict__ Alo,
    const __nv_bfloat16* __restrict__ Bhi, const __nv_bfloat16* __restrict__ Blo,
    const float* __restrict__ bias,
    float* __restrict__ C, float* __restrict__ C2,
    __nv_bfloat16* __restrict__ Chi, __nv_bfloat16* __restrict__ Clo,
    int K, int lda)
{
    extern __shared__ char smem[];
    const int tid = threadIdx.x;
    const int lane = tid & 31, wid = tid >> 5;
    const int m0 = blockIdx.y * 128, n0 = blockIdx.x * 128;
    const int wm = (wid & 3) * 32, wn = (wid >> 2) * 64;

    if constexpr (PERENC) {
        int e = m0 >> 14;
        Bhi += (size_t)e * 512 * K;
        Blo += (size_t)e * 512 * K;
        if constexpr (HAS_BIAS) bias += e * 512;
    }
    if constexpr (PERHEAD) {
        int z = blockIdx.z;
        Ahi += z * 64; Alo += z * 64;
        Bhi += (size_t)z * 512 * K;
        Blo += (size_t)z * 512 * K;
        size_t co = (size_t)z * B_ * 512;
        if constexpr (WRITE_F32) C += co;
        if constexpr (EMIT) { Chi += co; Clo += co; }
    }

    uint32_t sb = smem_u32(smem);
    const int prow = tid >> 1, ph = tid & 1;
    const __nv_bfloat16* pA0 = Ahi + (size_t)(m0 + prow) * lda + ph * 16;
    const __nv_bfloat16* pA1 = Alo + (size_t)(m0 + prow) * lda + ph * 16;
    const __nv_bfloat16* pB0 = Bhi + (size_t)(n0 + prow) * K + ph * 16;
    const __nv_bfloat16* pB1 = Blo + (size_t)(n0 + prow) * K + ph * 16;
    const uint32_t d0 = swz(prow, ph * 2), d1 = swz(prow, ph * 2 + 1);

    auto prefetch = [&](int buf, int kc) {
        uint32_t base = sb + buf * 32768;
        CP16(base + d0,          (const char*)(pA0 + kc * 32));
        CP16(base + d1,          (const char*)(pA0 + kc * 32 + 8));
        CP16(base + 8192 + d0,   (const char*)(pA1 + kc * 32));
        CP16(base + 8192 + d1,   (const char*)(pA1 + kc * 32 + 8));
        CP16(base + 16384 + d0,  (const char*)(pB0 + kc * 32));
        CP16(base + 16384 + d1,  (const char*)(pB0 + kc * 32 + 8));
        CP16(base + 24576 + d0,  (const char*)(pB1 + kc * 32));
        CP16(base + 24576 + d1,  (const char*)(pB1 + kc * 32 + 8));
        asm volatile("cp.async.commit_group;");
    };

    float d[2][8][4] = {};
    const int lrow = lane & 7, grp = lane >> 3;

    auto compute = [&](int buf) {
        uint32_t base = sb + buf * 32768;
        #pragma unroll
        for (int s = 0; s < 2; s++) {
            uint32_t ahi[2][4], alo[2][4];
            #pragma unroll
            for (int i = 0; i < 2; i++) {
                int row = wm + i * 16 + (grp & 1) * 8 + lrow;
                int g = s * 2 + (grp >> 1);
                uint32_t off = swz(row, g);
                ldsm4(ahi[i], base + off);
                ldsm4(alo[i], base + 8192 + off);
            }
            #pragma unroll
            for (int j = 0; j < 4; j++) {
                int row = wn + j * 16 + (grp >> 1) * 8 + lrow;
                int g = s * 2 + (grp & 1);
                uint32_t off = swz(row, g);
                uint32_t bh[4], bl[4];
                ldsm4(bh, base + 16384 + off);
                #pragma unroll
                for (int i = 0; i < 2; i++) {
                    mma_bf16(d[i][j*2],     ahi[i], bh);
                    mma_bf16(d[i][j*2 + 1], ahi[i], bh + 2);
                    mma_bf16(d[i][j*2],     alo[i], bh);
                    mma_bf16(d[i][j*2 + 1], alo[i], bh + 2);
                }
                ldsm4(bl, base + 24576 + off);
                #pragma unroll
                for (int i = 0; i < 2; i++) {
                    mma_bf16(d[i][j*2],     ahi[i], bl);
                    mma_bf16(d[i][j*2 + 1], ahi[i], bl + 2);
                }
            }
        }
    };

    // 3-stage ring: prefetch distance 2, ONE barrier per chunk.
    const int NCH = K >> 5;
    prefetch(0, 0);
    if (NCH > 1) prefetch(1, 1);
    for (int kc = 0; kc < NCH; kc++) {
        if (kc + 1 < NCH) asm volatile("cp.async.wait_group 1;");
        else              asm volatile("cp.async.wait_group 0;");
        __syncthreads();          // all warps: chunk kc data visible, chunk kc-1 compute done
        if (kc + 2 < NCH) prefetch((kc + 2) % 3, kc + 2);
        compute(kc % 3);
    }
    __syncthreads();

    // epilogue: frags -> smem stage -> coalesced global
    float* stage = (float*)smem;   // [128][132]
    #pragma unroll
    for (int i = 0; i < 2; i++)
        #pragma unroll
        for (int j = 0; j < 8; j++) {
            int r = wm + i * 16 + (lane >> 2);
            int cc = wn + j * 8 + (lane & 3) * 2;
            stage[r * 132 + cc]       = d[i][j][0];
            stage[r * 132 + cc + 1]   = d[i][j][1];
            stage[(r + 8) * 132 + cc]     = d[i][j][2];
            stage[(r + 8) * 132 + cc + 1] = d[i][j][3];
        }
    __syncthreads();
    #pragma unroll
    for (int k2 = 0; k2 < 16; k2++) {
        int s = tid + k2 * 256;
        int row = s >> 5, q = s & 31;
        float4 v = *(const float4*)&stage[row * 132 + q * 4];
        int col = n0 + q * 4;
        float o[4] = {v.x, v.y, v.z, v.w};
        if constexpr (HAS_BIAS) {
            o[0] += bias[col]; o[1] += bias[col + 1];
            o[2] += bias[col + 2]; o[3] += bias[col + 3];
        }
        if constexpr (HEADOUT) {
            size_t r = (size_t)(m0 + row);
            if (col < 64) {
                *(float4*)&C[r * 64 + col] = make_float4(o[0], o[1], o[2], o[3]);
            } else {
                #pragma unroll
                for (int c2 = 0; c2 < 4; c2++) o[c2] = fminf(fmaxf(o[c2], -20.f), 2.f);
                *(float4*)&C2[r * 64 + col - 64] = make_float4(o[0], o[1], o[2], o[3]);
            }
        } else {
            #pragma unroll
            for (int c2 = 0; c2 < 4; c2++) o[c2] = act_fn<ACT>(o[c2]);
            size_t idx = (size_t)(m0 + row) * 512 + col;
            if constexpr (WRITE_F32)
                *(float4*)&C[idx] = make_float4(o[0], o[1], o[2], o[3]);
            if constexpr (EMIT) {
                unsigned short hh[4], ll[4];
                split2(o[0], hh[0], ll[0]); split2(o[1], hh[1], ll[1]);
                split2(o[2], hh[2], ll[2]); split2(o[3], hh[3], ll[3]);
                *(uint2*)&Chi[idx] = *(uint2*)hh;
                *(uint2*)&Clo[idx] = *(uint2*)ll;
            }
        }
    }
}

// ---------------- attention: logits (selk . encs) -> softmax -> weighted vals ----------------
__global__ __launch_bounds__(64) void attn_kernel(float* __restrict__ actor_in) {
    __shared__ float sk[8][516];
    __shared__ float en[8][516];
    __shared__ float w_s[64];
    int j = threadIdx.x;
    size_t b = blockIdx.x;

    #pragma unroll
    for (int a = 0; a < 8; a++)
        #pragma unroll
        for (int m = 0; m < 8; m++)
            sk[a][m * 64 + j] = g_selk[((size_t)a * B_ + b) * 512 + m * 64 + j];
    #pragma unroll
    for (int e = 0; e < 8; e++)
        #pragma unroll
        for (int m = 0; m < 8; m++) {
            size_t idx = ((size_t)e * B_ + b) * 512 + m * 64 + j;
            en[e][m * 64 + j] = __bfloat162float(g_encs_hi[idx]) + __bfloat162float(g_encs_lo[idx]);
        }
    __syncthreads();

    int a = j >> 3, e = j & 7;
    float lg = 0.f;
    const float* sp = sk[a];
    const float* ep = en[e];
    #pragma unroll 8
    for (int h = 0; h < 512; h++) lg = fmaf(sp[h], ep[h], lg);
    lg *= 0.125f;

    float mx = lg;
    #pragma unroll
    for (int o = 4; o >= 1; o >>= 1) mx = fmaxf(mx, __shfl_xor_sync(0xffffffffu, mx, o));
    float ex = expf(lg - mx);
    float sm = ex;
    #pragma unroll
    for (int o = 4; o >= 1; o >>= 1) sm += __shfl_xor_sync(0xffffffffu, sm, o);
    w_s[j] = ex / sm;
    __syncthreads();

    #pragma unroll
    for (int m = 0; m < 8; m++) {
        int c = m * 64 + j;
        float acc = 0.f;
        #pragma unroll
        for (int ee = 0; ee < 8; ee++)
            acc = fmaf(w_s[m * 8 + ee], g_vals[((size_t)ee * B_ + b) * 512 + c], acc);
        actor_in[b * 512 + c] = acc;
        unsigned short hh, ll;
        split2(acc, hh, ll);
        g_attn_hi[b * 512 + c] = *(__nv_bfloat16*)&hh;
        g_attn_lo[b * 512 + c] = *(__nv_bfloat16*)&ll;
    }
}

// ---------------- launch ----------------
#define MMA_SMEM 98304

extern "C" void kernel_launch(void* const* d_in, const int* in_sizes, int n_in,
                              void* d_out, int out_size) {
    const float* states      = (const float*)d_in[0];
    const float* pre_actions = (const float*)d_in[1];
    const float* W_enc       = (const float*)d_in[2];
    const float* b_enc       = (const float*)d_in[3];
    const float* W_pre       = (const float*)d_in[4];
    const float* b_pre       = (const float*)d_in[5];
    const float* Wk          = (const float*)d_in[6];
    const float* Wsel        = (const float*)d_in[7];
    const float* Wv          = (const float*)d_in[8];
    const float* bv          = (const float*)d_in[9];
    const float* W_actor     = (const float*)d_in[10];
    const float* b_actor     = (const float*)d_in[11];
    const float* W_mean      = (const float*)d_in[12];
    const float* b_mean      = (const float*)d_in[13];
    const float* W_logstd    = (const float*)d_in[14];
    const float* b_logstd    = (const float*)d_in[15];

    float* out        = (float*)d_out;
    float* out_mean   = out;
    float* out_logstd = out + (size_t)B_ * NAG;
    float* out_actor  = out + (size_t)2 * B_ * NAG;

    float *vals, *selk, *bias_ml;
    __nv_bfloat16 *encs_hi, *encs_lo, *sn_hi, *sn_lo, *pa_hi, *pa_lo;
    __nv_bfloat16 *pre_hi, *pre_lo, *sel_hi, *sel_lo, *attn_hi, *attn_lo, *x_hi, *x_lo;
    __nv_bfloat16 *WencT_hi, *WencT_lo, *WpreT_hi, *WpreT_lo, *WselT_hi, *WselT_lo;
    __nv_bfloat16 *WvT_hi, *WvT_lo, *WactT_hi, *WactT_lo, *Wk_hi, *Wk_lo, *WmlT_hi, *WmlT_lo;
    cudaGetSymbolAddress((void**)&vals,    g_vals);
    cudaGetSymbolAddress((void**)&selk,    g_selk);
    cudaGetSymbolAddress((void**)&bias_ml, g_bias_ml);
    cudaGetSymbolAddress((void**)&encs_hi, g_encs_hi);
    cudaGetSymbolAddress((void**)&encs_lo, g_encs_lo);
    cudaGetSymbolAddress((void**)&sn_hi,   g_sn_hi);
    cudaGetSymbolAddress((void**)&sn_lo,   g_sn_lo);
    cudaGetSymbolAddress((void**)&pa_hi,   g_pa_hi);
    cudaGetSymbolAddress((void**)&pa_lo,   g_pa_lo);
    cudaGetSymbolAddress((void**)&pre_hi,  g_pre_hi);
    cudaGetSymbolAddress((void**)&pre_lo,  g_pre_lo);
    cudaGetSymbolAddress((void**)&sel_hi,  g_sel_hi);
    cudaGetSymbolAddress((void**)&sel_lo,  g_sel_lo);
    cudaGetSymbolAddress((void**)&attn_hi, g_attn_hi);
    cudaGetSymbolAddress((void**)&attn_lo, g_attn_lo);
    cudaGetSymbolAddress((void**)&x_hi,    g_x_hi);
    cudaGetSymbolAddress((void**)&x_lo,    g_x_lo);
    cudaGetSymbolAddress((void**)&WencT_hi, g_WencT_hi);
    cudaGetSymbolAddress((void**)&WencT_lo, g_WencT_lo);
    cudaGetSymbolAddress((void**)&WpreT_hi, g_WpreT_hi);
    cudaGetSymbolAddress((void**)&WpreT_lo, g_WpreT_lo);
    cudaGetSymbolAddress((void**)&WselT_hi, g_WselT_hi);
    cudaGetSymbolAddress((void**)&WselT_lo, g_WselT_lo);
    cudaGetSymbolAddress((void**)&WvT_hi,  g_WvT_hi);
    cudaGetSymbolAddress((void**)&WvT_lo,  g_WvT_lo);
    cudaGetSymbolAddress((void**)&WactT_hi, g_WactT_hi);
    cudaGetSymbolAddress((void**)&WactT_lo, g_WactT_lo);
    cudaGetSymbolAddress((void**)&Wk_hi,   g_Wk_hi);
    cudaGetSymbolAddress((void**)&Wk_lo,   g_Wk_lo);
    cudaGetSymbolAddress((void**)&WmlT_hi, g_WmlT_hi);
    cudaGetSymbolAddress((void**)&WmlT_lo, g_WmlT_lo);

    auto enc_k  = mma_gemm<1, true,  false, true,  true,  false, false>;
    auto pre_k  = mma_gemm<1, true,  false, true,  false, false, false>;
    auto sel_k  = mma_gemm<0, false, false, true,  false, false, false>;
    auto selk_k = mma_gemm<0, false, true,  false, false, true,  false>;
    auto vals_k = mma_gemm<1, true,  true,  false, false, false, false>;
    auto x_k    = mma_gemm<2, true,  false, true,  false, false, false>;
    auto ml_k   = mma_gemm<0, true,  false, false, false, false, true>;
    cudaFuncSetAttribute(enc_k,  cudaFuncAttributeMaxDynamicSharedMemorySize, MMA_SMEM);
    cudaFuncSetAttribute(pre_k,  cudaFuncAttributeMaxDynamicSharedMemorySize, MMA_SMEM);
    cudaFuncSetAttribute(sel_k,  cudaFuncAttributeMaxDynamicSharedMemorySize, MMA_SMEM);
    cudaFuncSetAttribute(selk_k, cudaFuncAttributeMaxDynamicSharedMemorySize, MMA_SMEM);
    cudaFuncSetAttribute(vals_k, cudaFuncAttributeMaxDynamicSharedMemorySize, MMA_SMEM);
    cudaFuncSetAttribute(x_k,    cudaFuncAttributeMaxDynamicSharedMemorySize, MMA_SMEM);
    cudaFuncSetAttribute(ml_k,   cudaFuncAttributeMaxDynamicSharedMemorySize, MMA_SMEM);

    // stats + conversions + repacks
    bn_part_kernel<<<dim3(E_, 32), dim3(64, 4)>>>(states);
    bn_final_kernel<<<1, 512>>>();
    repack2_kernel<<<1024, 256>>>(Wk, Wv, Wsel, W_pre, W_actor, W_enc,
                                  W_mean, W_logstd, b_mean, b_logstd);
    cvt_pa_kernel<<<8192, 256>>>(pre_actions);
    snorm_kernel<<<8192, 256>>>(states);

    // encs = leaky(snorm @ W_enc + b_enc), K=64, per-encoder; emit hi/lo only
    enc_k<<<dim3(4, 1024), 256, MMA_SMEM>>>(sn_hi, sn_lo, WencT_hi, WencT_lo, b_enc,
                                            nullptr, nullptr, encs_hi, encs_lo, 64, 64);
    // pre = leaky(pre_actions @ W_pre + b_pre), emit hi/lo
    pre_k<<<dim3(4, 128), 256, MMA_SMEM>>>(pa_hi, pa_lo, WpreT_hi, WpreT_lo, b_pre,
                                           nullptr, nullptr, pre_hi, pre_lo, 512, 512);
    // sel = pre @ Wsel, emit hi/lo
    sel_k<<<dim3(4, 128), 256, MMA_SMEM>>>(pre_hi, pre_lo, WselT_hi, WselT_lo, nullptr,
                                           nullptr, nullptr, sel_hi, sel_lo, 512, 512);
    // selk[a] = sel[:, a*64:+64] @ Wk[a]^T, K=64, per-head; fp32
    selk_k<<<dim3(4, 128, 8), 256, MMA_SMEM>>>(sel_hi, sel_lo, Wk_hi, Wk_lo, nullptr,
                                               selk, nullptr, nullptr, nullptr, 64, 512);
    // vals = leaky(encs @ Wv + bv); fp32
    vals_k<<<dim3(4, 1024), 256, MMA_SMEM>>>(encs_hi, encs_lo, WvT_hi, WvT_lo, bv,
                                             vals, nullptr, nullptr, nullptr, 512, 512);
    // attention -> actor_in (+ hi/lo for actor GEMM)
    attn_kernel<<<B_, 64>>>(out_actor);
    // x = relu(actor_in @ W_actor + b_actor); emit hi/lo
    x_k<<<dim3(4, 128), 256, MMA_SMEM>>>(attn_hi, attn_lo, WactT_hi, WactT_lo, b_actor,
                                         nullptr, nullptr, x_hi, x_lo, 512, 512);
    // mean | log_std fused, N=128, K=512
    ml_k<<<dim3(1, 128), 256, MMA_SMEM>>>(x_hi, x_lo, WmlT_hi, WmlT_lo, bias_ml,
                                          out_mean, out_logstd, nullptr, nullptr, 512, 512);
}

// round 12
// speedup vs baseline: 2.9872x; 1.0404x over previous
#include <cuda_runtime.h>
#include <cuda_bf16.h>
#include <math.h>
#include <stdint.h>

#define E_ 8
#define B_ 16384
#define NAG 64
#define H_ 512
#define A_ 8
#define D_ 64
#define EB (E_*B_)

// ---------------- scratch (device globals; no allocation allowed) ----------------
__device__ __nv_bfloat16 g_encs_hi[(size_t)EB * H_];
__device__ __nv_bfloat16 g_encs_lo[(size_t)EB * H_];
__device__ float g_vals[(size_t)EB * H_];
__device__ float g_selk[(size_t)A_ * B_ * H_];
__device__ __nv_bfloat16 g_x_hi[(size_t)B_ * H_];
__device__ __nv_bfloat16 g_x_lo[(size_t)B_ * H_];
__device__ __nv_bfloat16 g_sn_hi[(size_t)EB * 64];     // normalized states
__device__ __nv_bfloat16 g_sn_lo[(size_t)EB * 64];
__device__ __nv_bfloat16 g_pa_hi[(size_t)B_ * H_];     // pre_actions
__device__ __nv_bfloat16 g_pa_lo[(size_t)B_ * H_];
__device__ __nv_bfloat16 g_pre_hi[(size_t)B_ * H_];
__device__ __nv_bfloat16 g_pre_lo[(size_t)B_ * H_];
__device__ __nv_bfloat16 g_sel_hi[(size_t)B_ * H_];
__device__ __nv_bfloat16 g_sel_lo[(size_t)B_ * H_];
__device__ __nv_bfloat16 g_attn_hi[(size_t)B_ * H_];
__device__ __nv_bfloat16 g_attn_lo[(size_t)B_ * H_];
// weights, all [n][k] k-major, bf16 hi/lo
__device__ __nv_bfloat16 g_WencT_hi[E_ * H_ * 64];     // [e][n=512][k=64]
__device__ __nv_bfloat16 g_WencT_lo[E_ * H_ * 64];
__device__ __nv_bfloat16 g_WpreT_hi[H_ * H_];
__device__ __nv_bfloat16 g_WpreT_lo[H_ * H_];
__device__ __nv_bfloat16 g_WselT_hi[H_ * H_];
__device__ __nv_bfloat16 g_WselT_lo[H_ * H_];
__device__ __nv_bfloat16 g_WvT_hi[H_ * H_];
__device__ __nv_bfloat16 g_WvT_lo[H_ * H_];
__device__ __nv_bfloat16 g_WactT_hi[H_ * H_];
__device__ __nv_bfloat16 g_WactT_lo[H_ * H_];
__device__ __nv_bfloat16 g_Wk_hi[A_ * H_ * D_];        // [a][n=h][k=d]
__device__ __nv_bfloat16 g_Wk_lo[A_ * H_ * D_];
__device__ __nv_bfloat16 g_WmlT_hi[128 * H_];          // [n=128][k=512] (mean|logstd)
__device__ __nv_bfloat16 g_WmlT_lo[128 * H_];
__device__ float g_bias_ml[128];
__device__ float g_part_sum[E_ * 32 * 64];
__device__ float g_part_sq[E_ * 32 * 64];
__device__ float g_mu[E_ * 64];
__device__ float g_rs[E_ * 64];

// ---------------- helpers ----------------
__device__ __forceinline__ uint32_t smem_u32(const void* p) {
    uint32_t a;
    asm("{ .reg .u64 t; cvta.to.shared.u64 t, %1; cvt.u32.u64 %0, t; }" : "=r"(a) : "l"(p));
    return a;
}
__device__ __forceinline__ void split2(float v, unsigned short& h, unsigned short& l) {
    __nv_bfloat16 bh = __float2bfloat16(v);
    __nv_bfloat16 bl = __float2bfloat16(v - __bfloat162float(bh));
    h = *(unsigned short*)&bh;
    l = *(unsigned short*)&bl;
}
template<int ACT>
__device__ __forceinline__ float act_fn(float v) {
    if constexpr (ACT == 1) return v >= 0.f ? v : 0.01f * v;
    else if constexpr (ACT == 2) return fmaxf(v, 0.f);
    else if constexpr (ACT == 3) return fminf(fmaxf(v, -20.f), 2.f);
    else return v;
}
#define CP16(dst, src) asm volatile("cp.async.cg.shared.global [%0], [%1], 16;" :: "r"(dst), "l"(src))
__device__ __forceinline__ void ldsm4(uint32_t* r, uint32_t a) {
    asm volatile("ldmatrix.sync.aligned.m8n8.x4.shared.b16 {%0,%1,%2,%3}, [%4];"
        : "=r"(r[0]), "=r"(r[1]), "=r"(r[2]), "=r"(r[3]) : "r"(a));
}
__device__ __forceinline__ void mma_bf16(float* d, const uint32_t* a, const uint32_t* b) {
    asm volatile("mma.sync.aligned.m16n8k16.row.col.f32.bf16.bf16.f32 "
        "{%0,%1,%2,%3}, {%4,%5,%6,%7}, {%8,%9}, {%0,%1,%2,%3};"
        : "+f"(d[0]), "+f"(d[1]), "+f"(d[2]), "+f"(d[3])
        : "r"(a[0]), "r"(a[1]), "r"(a[2]), "r"(a[3]), "r"(b[0]), "r"(b[1]));
}
// smem layout per [128 rows x 32 cols bf16] matrix: swizzled 16B chunks.
__device__ __forceinline__ uint32_t swz(int row, int g) {
    int l = row >> 1;
    int c = (g | ((row & 1) << 2)) ^ (l & 7);
    return (uint32_t)((l << 7) + (c << 4));
}

// ---------------- batchnorm stats ----------------
__global__ void bn_part_kernel(const float* __restrict__ states) {
    int e = blockIdx.x, ch = blockIdx.y;
    int n = threadIdx.x, ty = threadIdx.y;
    const float* base = states + ((size_t)e * B_ + (size_t)ch * 512) * 64;
    float s = 0.f, q = 0.f;
    for (int r = ty; r < 512; r += 4) {
        float v = base[(size_t)r * 64 + n];
        s += v; q += v * v;
    }
    __shared__ float ss[4][64], sq[4][64];
    ss[ty][n] = s; sq[ty][n] = q;
    __syncthreads();
    if (ty == 0) {
        s = ss[0][n] + ss[1][n] + ss[2][n] + ss[3][n];
        q = sq[0][n] + sq[1][n] + sq[2][n] + sq[3][n];
        g_part_sum[(e * 32 + ch) * 64 + n] = s;
        g_part_sq [(e * 32 + ch) * 64 + n] = q;
    }
}
__global__ void bn_final_kernel() {
    int i = threadIdx.x;
    int e = i >> 6, n = i & 63;
    float s = 0.f, q = 0.f;
    for (int j = 0; j < 32; j++) {
        s += g_part_sum[(e * 32 + j) * 64 + n];
        q += g_part_sq [(e * 32 + j) * 64 + n];
    }
    float mean = s * (1.f / B_);
    float var  = q * (1.f / B_) - mean * mean;
    g_mu[i] = mean;
    g_rs[i] = 1.f / sqrtf(var + 1e-5f);
}

// ---------------- converters ----------------
__global__ void cvt_pa_kernel(const float* __restrict__ src) {
    size_t i = (size_t)blockIdx.x * 256 + threadIdx.x;   // over B_*512/4
    float4 v = ((const float4*)src)[i];
    unsigned short hh[4], ll[4];
    split2(v.x, hh[0], ll[0]); split2(v.y, hh[1], ll[1]);
    split2(v.z, hh[2], ll[2]); split2(v.w, hh[3], ll[3]);
    *(uint2*)&g_pa_hi[i * 4] = *(uint2*)hh;
    *(uint2*)&g_pa_lo[i * 4] = *(uint2*)ll;
}
__global__ void snorm_kernel(const float* __restrict__ states) {
    size_t i = (size_t)blockIdx.x * 256 + threadIdx.x;   // over EB*64/4
    float4 v = ((const float4*)states)[i];
    size_t row = i >> 4;
    int n = (int)(i & 15) * 4;
    int kb = (int)(row >> 14) * 64 + n;
    v.x = (v.x - g_mu[kb + 0]) * g_rs[kb + 0];
    v.y = (v.y - g_mu[kb + 1]) * g_rs[kb + 1];
    v.z = (v.z - g_mu[kb + 2]) * g_rs[kb + 2];
    v.w = (v.w - g_mu[kb + 3]) * g_rs[kb + 3];
    unsigned short hh[4], ll[4];
    split2(v.x, hh[0], ll[0]); split2(v.y, hh[1], ll[1]);
    split2(v.z, hh[2], ll[2]); split2(v.w, hh[3], ll[3]);
    *(uint2*)&g_sn_hi[i * 4] = *(uint2*)hh;
    *(uint2*)&g_sn_lo[i * 4] = *(uint2*)ll;
}
__global__ void repack2_kernel(const float* __restrict__ Wk, const float* __restrict__ Wv,
                               const float* __restrict__ Wsel, const float* __restrict__ W_pre,
                               const float* __restrict__ W_actor, const float* __restrict__ W_enc,
                               const float* __restrict__ W_mean, const float* __restrict__ W_logstd,
                               const float* __restrict__ b_mean, const float* __restrict__ b_logstd) {
    int i = blockIdx.x * 256 + threadIdx.x;   // 262144
    int k = i >> 9, n = i & 511;
    unsigned short h, l;
    int dst = n * 512 + k;
    split2(W_pre[i], h, l);   g_WpreT_hi[dst] = *(__nv_bfloat16*)&h; g_WpreT_lo[dst] = *(__nv_bfloat16*)&l;
    split2(W_actor[i], h, l); g_WactT_hi[dst] = *(__nv_bfloat16*)&h; g_WactT_lo[dst] = *(__nv_bfloat16*)&l;
    int a = n >> 6, dd = n & 63;
    int srcv = a * 32768 + k * 64 + dd;
    split2(Wv[srcv], h, l);   g_WvT_hi[dst] = *(__nv_bfloat16*)&h;   g_WvT_lo[dst] = *(__nv_bfloat16*)&l;
    split2(Wsel[srcv], h, l); g_WselT_hi[dst] = *(__nv_bfloat16*)&h; g_WselT_lo[dst] = *(__nv_bfloat16*)&l;
    split2(Wk[i], h, l);      g_Wk_hi[i] = *(__nv_bfloat16*)&h;      g_Wk_lo[i] = *(__nv_bfloat16*)&l;
    // W_enc: [E][64][512] -> [e][n][k]
    int e2 = i >> 15, rem = i & 32767, ne = rem >> 6, ke = rem & 63;
    split2(W_enc[e2 * 32768 + ke * 512 + ne], h, l);
    g_WencT_hi[i] = *(__nv_bfloat16*)&h; g_WencT_lo[i] = *(__nv_bfloat16*)&l;
    // W_mean|W_logstd: [512][64] each -> combined [n2=128][k2=512]
    if (i < 128 * 512) {
        int n2 = i & 127, k2 = i >> 7;
        float v = (n2 < 64) ? W_mean[k2 * 64 + n2] : W_logstd[k2 * 64 + (n2 - 64)];
        split2(v, h, l);
        g_WmlT_hi[n2 * 512 + k2] = *(__nv_bfloat16*)&h;
        g_WmlT_lo[n2 * 512 + k2] = *(__nv_bfloat16*)&l;
    }
    if (i < 128) g_bias_ml[i] = (i < 64) ? b_mean[i] : b_logstd[i - 64];
}

// ---------------- mma.sync bf16x3 GEMM: C[M,512] = act(A[M,K] @ B^T + bias) ----------------
// CTA 128x128, 8 warps each 32x64, cp.async 3-stage ring, one barrier per chunk.
template<int ACT, bool HAS_BIAS, bool WRITE_F32, bool EMIT, bool PERENC, bool PERHEAD, bool HEADOUT>
__global__ __launch_bounds__(256, 2) void mma_gemm(
    const __nv_bfloat16* __restrict__ Ahi, const __nv_bfloat16* __restrict__ Alo,
    const __nv_bfloat16* __restrict__ Bhi, const __nv_bfloat16* __restrict__ Blo,
    const float* __restrict__ bias,
    float* __restrict__ C, float* __restrict__ C2,
    __nv_bfloat16* __restrict__ Chi, __nv_bfloat16* __restrict__ Clo,
    int K, int lda)
{
    extern __shared__ char smem[];
    const int tid = threadIdx.x;
    const int lane = tid & 31, wid = tid >> 5;
    const int m0 = blockIdx.y * 128, n0 = blockIdx.x * 128;
    const int wm = (wid & 3) * 32, wn = (wid >> 2) * 64;

    if constexpr (PERENC) {
        int e = m0 >> 14;
        Bhi += (size_t)e * 512 * K;
        Blo += (size_t)e * 512 * K;
        if constexpr (HAS_BIAS) bias += e * 512;
    }
    if constexpr (PERHEAD) {
        int z = blockIdx.z;
        Ahi += z * 64; Alo += z * 64;
        Bhi += (size_t)z * 512 * K;
        Blo += (size_t)z * 512 * K;
        size_t co = (size_t)z * B_ * 512;
        if constexpr (WRITE_F32) C += co;
        if constexpr (EMIT) { Chi += co; Clo += co; }
    }

    uint32_t sb = smem_u32(smem);
    const int prow = tid >> 1, ph = tid & 1;
    const __nv_bfloat16* pA0 = Ahi + (size_t)(m0 + prow) * lda + ph * 16;
    const __nv_bfloat16* pA1 = Alo + (size_t)(m0 + prow) * lda + ph * 16;
    const __nv_bfloat16* pB0 = Bhi + (size_t)(n0 + prow) * K + ph * 16;
    const __nv_bfloat16* pB1 = Blo + (size_t)(n0 + prow) * K + ph * 16;
    const uint32_t d0 = swz(prow, ph * 2), d1 = swz(prow, ph * 2 + 1);

    auto prefetch = [&](int buf, int kc) {
        uint32_t base = sb + buf * 32768;
        CP16(base + d0,          (const char*)(pA0 + kc * 32));
        CP16(base + d1,          (const char*)(pA0 + kc * 32 + 8));
        CP16(base + 8192 + d0,   (const char*)(pA1 + kc * 32));
        CP16(base + 8192 + d1,   (const char*)(pA1 + kc * 32 + 8));
        CP16(base + 16384 + d0,  (const char*)(pB0 + kc * 32));
        CP16(base + 16384 + d1,  (const char*)(pB0 + kc * 32 + 8));
        CP16(base + 24576 + d0,  (const char*)(pB1 + kc * 32));
        CP16(base + 24576 + d1,  (const char*)(pB1 + kc * 32 + 8));
        asm volatile("cp.async.commit_group;");
    };

    float d[2][8][4] = {};
    const int lrow = lane & 7, grp = lane >> 3;

    auto compute = [&](int buf) {
        uint32_t base = sb + buf * 32768;
        #pragma unroll
        for (int s = 0; s < 2; s++) {
            uint32_t ahi[2][4], alo[2][4];
            #pragma unroll
            for (int i = 0; i < 2; i++) {
                int row = wm + i * 16 + (grp & 1) * 8 + lrow;
                int g = s * 2 + (grp >> 1);
                uint32_t off = swz(row, g);
                ldsm4(ahi[i], base + off);
                ldsm4(alo[i], base + 8192 + off);
            }
            #pragma unroll
            for (int j = 0; j < 4; j++) {
                int row = wn + j * 16 + (grp >> 1) * 8 + lrow;
                int g = s * 2 + (grp & 1);
                uint32_t off = swz(row, g);
                uint32_t bh[4], bl[4];
                ldsm4(bh, base + 16384 + off);
                #pragma unroll
                for (int i = 0; i < 2; i++) {
                    mma_bf16(d[i][j*2],     ahi[i], bh);
                    mma_bf16(d[i][j*2 + 1], ahi[i], bh + 2);
                    mma_bf16(d[i][j*2],     alo[i], bh);
                    mma_bf16(d[i][j*2 + 1], alo[i], bh + 2);
                }
                ldsm4(bl, base + 24576 + off);
                #pragma unroll
                for (int i = 0; i < 2; i++) {
                    mma_bf16(d[i][j*2],     ahi[i], bl);
                    mma_bf16(d[i][j*2 + 1], ahi[i], bl + 2);
                }
            }
        }
    };

    // 3-stage ring: prefetch distance 2, ONE barrier per chunk.
    const int NCH = K >> 5;
    prefetch(0, 0);
    if (NCH > 1) prefetch(1, 1);
    for (int kc = 0; kc < NCH; kc++) {
        if (kc + 1 < NCH) asm volatile("cp.async.wait_group 1;");
        else              asm volatile("cp.async.wait_group 0;");
        __syncthreads();          // all warps: chunk kc data visible, chunk kc-1 compute done
        if (kc + 2 < NCH) prefetch((kc + 2) % 3, kc + 2);
        compute(kc % 3);
    }
    __syncthreads();

    // epilogue: frags -> smem stage -> coalesced global
    float* stage = (float*)smem;   // [128][132]
    #pragma unroll
    for (int i = 0; i < 2; i++)
        #pragma unroll
        for (int j = 0; j < 8; j++) {
            int r = wm + i * 16 + (lane >> 2);
            int cc = wn + j * 8 + (lane & 3) * 2;
            stage[r * 132 + cc]       = d[i][j][0];
            stage[r * 132 + cc + 1]   = d[i][j][1];
            stage[(r + 8) * 132 + cc]     = d[i][j][2];
            stage[(r + 8) * 132 + cc + 1] = d[i][j][3];
        }
    __syncthreads();
    #pragma unroll
    for (int k2 = 0; k2 < 16; k2++) {
        int s = tid + k2 * 256;
        int row = s >> 5, q = s & 31;
        float4 v = *(const float4*)&stage[row * 132 + q * 4];
        int col = n0 + q * 4;
        float o[4] = {v.x, v.y, v.z, v.w};
        if constexpr (HAS_BIAS) {
            o[0] += bias[col]; o[1] += bias[col + 1];
            o[2] += bias[col + 2]; o[3] += bias[col + 3];
        }
        if constexpr (HEADOUT) {
            size_t r = (size_t)(m0 + row);
            if (col < 64) {
                *(float4*)&C[r * 64 + col] = make_float4(o[0], o[1], o[2], o[3]);
            } else {
                #pragma unroll
                for (int c2 = 0; c2 < 4; c2++) o[c2] = fminf(fmaxf(o[c2], -20.f), 2.f);
                *(float4*)&C2[r * 64 + col - 64] = make_float4(o[0], o[1], o[2], o[3]);
            }
        } else {
            #pragma unroll
            for (int c2 = 0; c2 < 4; c2++) o[c2] = act_fn<ACT>(o[c2]);
            size_t idx = (size_t)(m0 + row) * 512 + col;
            if constexpr (WRITE_F32)
                *(float4*)&C[idx] = make_float4(o[0], o[1], o[2], o[3]);
            if constexpr (EMIT) {
                unsigned short hh[4], ll[4];
                split2(o[0], hh[0], ll[0]); split2(o[1], hh[1], ll[1]);
                split2(o[2], hh[2], ll[2]); split2(o[3], hh[3], ll[3]);
                *(uint2*)&Chi[idx] = *(uint2*)hh;
                *(uint2*)&Clo[idx] = *(uint2*)ll;
            }
        }
    }
}

// ---------------- attention: register-blocked logits + softmax + weighted vals ----------------
// grid B_/2, 128 threads = 4 warps. Warp w: batch row (w>>1), heads (w&1)*4..+3.
// Logits as per-warp 4x8x512 register GEMM from GLOBAL (no smem staging, no LDS dots).
__global__ __launch_bounds__(128) void attn_kernel(float* __restrict__ actor_in) {
    __shared__ float w_s[2][64];
    const int tid = threadIdx.x;
    const int wid = tid >> 5, lane = tid & 31;
    const int br = wid >> 1;            // warp's batch row within block
    const int ha = (wid & 1) * 4;       // head base
    const size_t b = (size_t)blockIdx.x * 2 + br;

    float acc[4][8];
    #pragma unroll
    for (int r = 0; r < 4; r++)
        #pragma unroll
        for (int e = 0; e < 8; e++) acc[r][e] = 0.f;

    #pragma unroll
    for (int it = 0; it < 4; it++) {
        const int h0 = it * 128 + lane * 4;
        float4 S[4];
        #pragma unroll
        for (int r = 0; r < 4; r++)
            S[r] = *(const float4*)&g_selk[((size_t)(ha + r) * B_ + b) * 512 + h0];
        #pragma unroll
        for (int e = 0; e < 8; e++) {
            size_t idx = ((size_t)e * B_ + b) * 512 + h0;
            uint2 uh = *(const uint2*)&g_encs_hi[idx];
            uint2 ul = *(const uint2*)&g_encs_lo[idx];
            __nv_bfloat162 h01 = *(__nv_bfloat162*)&uh.x;
            __nv_bfloat162 h23 = *(__nv_bfloat162*)&uh.y;
            __nv_bfloat162 l01 = *(__nv_bfloat162*)&ul.x;
            __nv_bfloat162 l23 = *(__nv_bfloat162*)&ul.y;
            float E0 = __bfloat162float(h01.x) + __bfloat162float(l01.x);
            float E1 = __bfloat162float(h01.y) + __bfloat162float(l01.y);
            float E2 = __bfloat162float(h23.x) + __bfloat162float(l23.x);
            float E3 = __bfloat162float(h23.y) + __bfloat162float(l23.y);
            #pragma unroll
            for (int r = 0; r < 4; r++) {
                acc[r][e] = fmaf(S[r].x, E0, acc[r][e]);
                acc[r][e] = fmaf(S[r].y, E1, acc[r][e]);
                acc[r][e] = fmaf(S[r].z, E2, acc[r][e]);
                acc[r][e] = fmaf(S[r].w, E3, acc[r][e]);
            }
        }
    }
    // fixed-order butterfly reduce over lanes (all lanes end with totals)
    #pragma unroll
    for (int off = 16; off >= 1; off >>= 1)
        #pragma unroll
        for (int r = 0; r < 4; r++)
            #pragma unroll
            for (int e = 0; e < 8; e++)
                acc[r][e] += __shfl_xor_sync(0xffffffffu, acc[r][e], off);

    // softmax over e (lane 0 writes)
    if (lane == 0) {
        #pragma unroll
        for (int r = 0; r < 4; r++) {
            float lg[8];
            float mx = -1e30f;
            #pragma unroll
            for (int e = 0; e < 8; e++) { lg[e] = acc[r][e] * 0.125f; mx = fmaxf(mx, lg[e]); }
            float s = 0.f, ex[8];
            #pragma unroll
            for (int e = 0; e < 8; e++) { ex[e] = expf(lg[e] - mx); s += ex[e]; }
            float inv = 1.f / s;
            #pragma unroll
            for (int e = 0; e < 8; e++) w_s[br][(ha + r) * 8 + e] = ex[e] * inv;
        }
    }
    __syncthreads();

    // combine: threads 0-63 -> row0, 64-127 -> row1
    const int r2 = tid >> 6, j = tid & 63;
    const size_t b2 = (size_t)blockIdx.x * 2 + r2;
    #pragma unroll
    for (int m = 0; m < 8; m++) {
        int c = m * 64 + j;
        float a2 = 0.f;
        #pragma unroll
        for (int ee = 0; ee < 8; ee++)
            a2 = fmaf(w_s[r2][m * 8 + ee], g_vals[((size_t)ee * B_ + b2) * 512 + c], a2);
        actor_in[b2 * 512 + c] = a2;
        unsigned short hh, ll;
        split2(a2, hh, ll);
        g_attn_hi[b2 * 512 + c] = *(__nv_bfloat16*)&hh;
        g_attn_lo[b2 * 512 + c] = *(__nv_bfloat16*)&ll;
    }
}

// ---------------- launch ----------------
#define MMA_SMEM 98304

extern "C" void kernel_launch(void* const* d_in, const int* in_sizes, int n_in,
                              void* d_out, int out_size) {
    const float* states      = (const float*)d_in[0];
    const float* pre_actions = (const float*)d_in[1];
    const float* W_enc       = (const float*)d_in[2];
    const float* b_enc       = (const float*)d_in[3];
    const float* W_pre       = (const float*)d_in[4];
    const float* b_pre       = (const float*)d_in[5];
    const float* Wk          = (const float*)d_in[6];
    const float* Wsel        = (const float*)d_in[7];
    const float* Wv          = (const float*)d_in[8];
    const float* bv          = (const float*)d_in[9];
    const float* W_actor     = (const float*)d_in[10];
    const float* b_actor     = (const float*)d_in[11];
    const float* W_mean      = (const float*)d_in[12];
    const float* b_mean      = (const float*)d_in[13];
    const float* W_logstd    = (const float*)d_in[14];
    const float* b_logstd    = (const float*)d_in[15];

    float* out        = (float*)d_out;
    float* out_mean   = out;
    float* out_logstd = out + (size_t)B_ * NAG;
    float* out_actor  = out + (size_t)2 * B_ * NAG;

    float *vals, *selk, *bias_ml;
    __nv_bfloat16 *encs_hi, *encs_lo, *sn_hi, *sn_lo, *pa_hi, *pa_lo;
    __nv_bfloat16 *pre_hi, *pre_lo, *sel_hi, *sel_lo, *attn_hi, *attn_lo, *x_hi, *x_lo;
    __nv_bfloat16 *WencT_hi, *WencT_lo, *WpreT_hi, *WpreT_lo, *WselT_hi, *WselT_lo;
    __nv_bfloat16 *WvT_hi, *WvT_lo, *WactT_hi, *WactT_lo, *Wk_hi, *Wk_lo, *WmlT_hi, *WmlT_lo;
    cudaGetSymbolAddress((void**)&vals,    g_vals);
    cudaGetSymbolAddress((void**)&selk,    g_selk);
    cudaGetSymbolAddress((void**)&bias_ml, g_bias_ml);
    cudaGetSymbolAddress((void**)&encs_hi, g_encs_hi);
    cudaGetSymbolAddress((void**)&encs_lo, g_encs_lo);
    cudaGetSymbolAddress((void**)&sn_hi,   g_sn_hi);
    cudaGetSymbolAddress((void**)&sn_lo,   g_sn_lo);
    cudaGetSymbolAddress((void**)&pa_hi,   g_pa_hi);
    cudaGetSymbolAddress((void**)&pa_lo,   g_pa_lo);
    cudaGetSymbolAddress((void**)&pre_hi,  g_pre_hi);
    cudaGetSymbolAddress((void**)&pre_lo,  g_pre_lo);
    cudaGetSymbolAddress((void**)&sel_hi,  g_sel_hi);
    cudaGetSymbolAddress((void**)&sel_lo,  g_sel_lo);
    cudaGetSymbolAddress((void**)&attn_hi, g_attn_hi);
    cudaGetSymbolAddress((void**)&attn_lo, g_attn_lo);
    cudaGetSymbolAddress((void**)&x_hi,    g_x_hi);
    cudaGetSymbolAddress((void**)&x_lo,    g_x_lo);
    cudaGetSymbolAddress((void**)&WencT_hi, g_WencT_hi);
    cudaGetSymbolAddress((void**)&WencT_lo, g_WencT_lo);
    cudaGetSymbolAddress((void**)&WpreT_hi, g_WpreT_hi);
    cudaGetSymbolAddress((void**)&WpreT_lo, g_WpreT_lo);
    cudaGetSymbolAddress((void**)&WselT_hi, g_WselT_hi);
    cudaGetSymbolAddress((void**)&WselT_lo, g_WselT_lo);
    cudaGetSymbolAddress((void**)&WvT_hi,  g_WvT_hi);
    cudaGetSymbolAddress((void**)&WvT_lo,  g_WvT_lo);
    cudaGetSymbolAddress((void**)&WactT_hi, g_WactT_hi);
    cudaGetSymbolAddress((void**)&WactT_lo, g_WactT_lo);
    cudaGetSymbolAddress((void**)&Wk_hi,   g_Wk_hi);
    cudaGetSymbolAddress((void**)&Wk_lo,   g_Wk_lo);
    cudaGetSymbolAddress((void**)&WmlT_hi, g_WmlT_hi);
    cudaGetSymbolAddress((void**)&WmlT_lo, g_WmlT_lo);

    auto enc_k  = mma_gemm<1, true,  false, true,  true,  false, false>;
    auto pre_k  = mma_gemm<1, true,  false, true,  false, false, false>;
    auto sel_k  = mma_gemm<0, false, false, true,  false, false, false>;
    auto selk_k = mma_gemm<0, false, true,  false, false, true,  false>;
    auto vals_k = mma_gemm<1, true,  true,  false, false, false, false>;
    auto x_k    = mma_gemm<2, true,  false, true,  false, false, false>;
    auto ml_k   = mma_gemm<0, true,  false, false, false, false, true>;
    cudaFuncSetAttribute(enc_k,  cudaFuncAttributeMaxDynamicSharedMemorySize, MMA_SMEM);
    cudaFuncSetAttribute(pre_k,  cudaFuncAttributeMaxDynamicSharedMemorySize, MMA_SMEM);
    cudaFuncSetAttribute(sel_k,  cudaFuncAttributeMaxDynamicSharedMemorySize, MMA_SMEM);
    cudaFuncSetAttribute(selk_k, cudaFuncAttributeMaxDynamicSharedMemorySize, MMA_SMEM);
    cudaFuncSetAttribute(vals_k, cudaFuncAttributeMaxDynamicSharedMemorySize, MMA_SMEM);
    cudaFuncSetAttribute(x_k,    cudaFuncAttributeMaxDynamicSharedMemorySize, MMA_SMEM);
    cudaFuncSetAttribute(ml_k,   cudaFuncAttributeMaxDynamicSharedMemorySize, MMA_SMEM);

    // stats + repack (launches 1-4)
    bn_part_kernel<<<dim3(E_, 32), dim3(64, 4)>>>(states);
    bn_final_kernel<<<1, 512>>>();
    repack2_kernel<<<1024, 256>>>(Wk, Wv, Wsel, W_pre, W_actor, W_enc,
                                  W_mean, W_logstd, b_mean, b_logstd);
    snorm_kernel<<<8192, 256>>>(states);

    // launch 5: encs = leaky(snorm @ W_enc + b_enc), K=64, per-encoder
    enc_k<<<dim3(4, 1024), 256, MMA_SMEM>>>(sn_hi, sn_lo, WencT_hi, WencT_lo, b_enc,
                                            nullptr, nullptr, encs_hi, encs_lo, 64, 64);
    // launch 6 (ncu target): vals = leaky(encs @ Wv + bv); fp32
    vals_k<<<dim3(4, 1024), 256, MMA_SMEM>>>(encs_hi, encs_lo, WvT_hi, WvT_lo, bv,
                                             vals, nullptr, nullptr, nullptr, 512, 512);
    // pre_actions conversion (needed only by pre_k)
    cvt_pa_kernel<<<8192, 256>>>(pre_actions);
    // pre = leaky(pre_actions @ W_pre + b_pre)
    pre_k<<<dim3(4, 128), 256, MMA_SMEM>>>(pa_hi, pa_lo, WpreT_hi, WpreT_lo, b_pre,
                                           nullptr, nullptr, pre_hi, pre_lo, 512, 512);
    // sel = pre @ Wsel
    sel_k<<<dim3(4, 128), 256, MMA_SMEM>>>(pre_hi, pre_lo, WselT_hi, WselT_lo, nullptr,
                                           nullptr, nullptr, sel_hi, sel_lo, 512, 512);
    // selk[a] = sel[:, a*64:+64] @ Wk[a]^T, K=64, per-head; fp32
    selk_k<<<dim3(4, 128, 8), 256, MMA_SMEM>>>(sel_hi, sel_lo, Wk_hi, Wk_lo, nullptr,
                                               selk, nullptr, nullptr, nullptr, 64, 512);
    // attention -> actor_in (+ hi/lo for actor GEMM)
    attn_kernel<<<B_ / 2, 128>>>(out_actor);
    // x = relu(actor_in @ W_actor + b_actor)
    x_k<<<dim3(4, 128), 256, MMA_SMEM>>>(attn_hi, attn_lo, WactT_hi, WactT_lo, b_actor,
                                         nullptr, nullptr, x_hi, x_lo, 512, 512);
    // mean | log_std fused, N=128, K=512
    ml_k<<<dim3(1, 128), 256, MMA_SMEM>>>(x_hi, x_lo, WmlT_hi, WmlT_lo, bias_ml,
                                          out_mean, out_logstd, nullptr, nullptr, 512, 512);
}

// round 16
// speedup vs baseline: 3.4044x; 1.1397x over previous
#include <cuda_runtime.h>
#include <cuda_bf16.h>
#include <cuda_fp16.h>
#include <math.h>
#include <stdint.h>

#define E_ 8
#define B_ 16384
#define NAG 64
#define H_ 512
#define A_ 8
#define D_ 64
#define EB (E_*B_)

// ---------------- scratch (device globals; no allocation allowed) ----------------
__device__ __half g_encs_hi[(size_t)EB * H_];           // fp16 split (vals A + attn logits)
__device__ __half g_encs_lo[(size_t)EB * H_];
__device__ float g_vals[(size_t)EB * H_];
__device__ float g_selk[(size_t)A_ * B_ * H_];
__device__ __nv_bfloat16 g_x_hi[(size_t)B_ * H_];
__device__ __nv_bfloat16 g_x_lo[(size_t)B_ * H_];
__device__ __nv_bfloat16 g_sn_hi[(size_t)EB * 64];      // normalized states (bf16 split)
__device__ __nv_bfloat16 g_sn_lo[(size_t)EB * 64];
__device__ __nv_bfloat16 g_pa_hi[(size_t)B_ * H_];
__device__ __nv_bfloat16 g_pa_lo[(size_t)B_ * H_];
__device__ __nv_bfloat16 g_pre_hi[(size_t)B_ * H_];
__device__ __nv_bfloat16 g_pre_lo[(size_t)B_ * H_];
__device__ __nv_bfloat16 g_sel_hi[(size_t)B_ * H_];
__device__ __nv_bfloat16 g_sel_lo[(size_t)B_ * H_];
__device__ __nv_bfloat16 g_attn_hi[(size_t)B_ * H_];
__device__ __nv_bfloat16 g_attn_lo[(size_t)B_ * H_];
// weights, [n][k] k-major
__device__ __nv_bfloat16 g_WencT_hi[E_ * H_ * 64];
__device__ __nv_bfloat16 g_WencT_lo[E_ * H_ * 64];
__device__ __nv_bfloat16 g_WpreT_hi[H_ * H_];
__device__ __nv_bfloat16 g_WpreT_lo[H_ * H_];
__device__ __nv_bfloat16 g_WselT_hi[H_ * H_];
__device__ __nv_bfloat16 g_WselT_lo[H_ * H_];
__device__ __half g_WvT_h16[H_ * H_];                   // single fp16 Wv
__device__ __nv_bfloat16 g_WactT_hi[H_ * H_];
__device__ __nv_bfloat16 g_WactT_lo[H_ * H_];
__device__ __nv_bfloat16 g_Wk_hi[A_ * H_ * D_];
__device__ __nv_bfloat16 g_Wk_lo[A_ * H_ * D_];
__device__ __nv_bfloat16 g_WmlT_hi[128 * H_];
__device__ __nv_bfloat16 g_WmlT_lo[128 * H_];
__device__ float g_bias_ml[128];
__device__ float g_part_sum[E_ * 32 * 64];
__device__ float g_part_sq[E_ * 32 * 64];

// ---------------- helpers ----------------
__device__ __forceinline__ uint32_t smem_u32(const void* p) {
    uint32_t a;
    asm("{ .reg .u64 t; cvta.to.shared.u64 t, %1; cvt.u32.u64 %0, t; }" : "=r"(a) : "l"(p));
    return a;
}
__device__ __forceinline__ void split2(float v, unsigned short& h, unsigned short& l) {
    __nv_bfloat16 bh = __float2bfloat16(v);
    __nv_bfloat16 bl = __float2bfloat16(v - __bfloat162float(bh));
    h = *(unsigned short*)&bh;
    l = *(unsigned short*)&bl;
}
__device__ __forceinline__ void split2h(float v, unsigned short& h, unsigned short& l) {
    __half bh = __float2half_rn(v);
    __half bl = __float2half_rn(v - __half2float(bh));
    h = *(unsigned short*)&bh;
    l = *(unsigned short*)&bl;
}
template<int ACT>
__device__ __forceinline__ float act_fn(float v) {
    if constexpr (ACT == 1) return v >= 0.f ? v : 0.01f * v;
    else if constexpr (ACT == 2) return fmaxf(v, 0.f);
    else if constexpr (ACT == 3) return fminf(fmaxf(v, -20.f), 2.f);
    else return v;
}
#define CP16(dst, src) asm volatile("cp.async.cg.shared.global [%0], [%1], 16;" :: "r"(dst), "l"(src))
__device__ __forceinline__ void ldsm4(uint32_t* r, uint32_t a) {
    asm volatile("ldmatrix.sync.aligned.m8n8.x4.shared.b16 {%0,%1,%2,%3}, [%4];"
        : "=r"(r[0]), "=r"(r[1]), "=r"(r[2]), "=r"(r[3]) : "r"(a));
}
__device__ __forceinline__ void mma_bf16(float* d, const uint32_t* a, const uint32_t* b) {
    asm volatile("mma.sync.aligned.m16n8k16.row.col.f32.bf16.bf16.f32 "
        "{%0,%1,%2,%3}, {%4,%5,%6,%7}, {%8,%9}, {%0,%1,%2,%3};"
        : "+f"(d[0]), "+f"(d[1]), "+f"(d[2]), "+f"(d[3])
        : "r"(a[0]), "r"(a[1]), "r"(a[2]), "r"(a[3]), "r"(b[0]), "r"(b[1]));
}
__device__ __forceinline__ void mma_fp16(float* d, const uint32_t* a, const uint32_t* b) {
    asm volatile("mma.sync.aligned.m16n8k16.row.col.f32.f16.f16.f32 "
        "{%0,%1,%2,%3}, {%4,%5,%6,%7}, {%8,%9}, {%0,%1,%2,%3};"
        : "+f"(d[0]), "+f"(d[1]), "+f"(d[2]), "+f"(d[3])
        : "r"(a[0]), "r"(a[1]), "r"(a[2]), "r"(a[3]), "r"(b[0]), "r"(b[1]));
}
__device__ __forceinline__ uint32_t swz(int row, int g) {
    int l = row >> 1;
    int c = (g | ((row & 1) << 2)) ^ (l & 7);
    return (uint32_t)((l << 7) + (c << 4));
}

// ---------------- prep: bn partials + weight repack (one launch) ----------------
__global__ void prep_kernel(const float* __restrict__ states,
                            const float* __restrict__ Wk, const float* __restrict__ Wv,
                            const float* __restrict__ Wsel, const float* __restrict__ W_pre,
                            const float* __restrict__ W_actor, const float* __restrict__ W_enc,
                            const float* __restrict__ W_mean, const float* __restrict__ W_logstd,
                            const float* __restrict__ b_mean, const float* __restrict__ b_logstd) {
    int blk = blockIdx.x;
    int tid = threadIdx.x;
    if (blk < 256) {
        // bn_part for (e, ch)
        int e = blk >> 5, ch = blk & 31;
        int n = tid & 63, ty = tid >> 6;
        const float* base = states + ((size_t)e * B_ + (size_t)ch * 512) * 64;
        float s = 0.f, q = 0.f;
        for (int r = ty; r < 512; r += 4) {
            float v = base[(size_t)r * 64 + n];
            s += v; q += v * v;
        }
        __shared__ float ss[4][64], sq[4][64];
        ss[ty][n] = s; sq[ty][n] = q;
        __syncthreads();
        if (ty == 0) {
            s = ss[0][n] + ss[1][n] + ss[2][n] + ss[3][n];
            q = sq[0][n] + sq[1][n] + sq[2][n] + sq[3][n];
            g_part_sum[(e * 32 + ch) * 64 + n] = s;
            g_part_sq [(e * 32 + ch) * 64 + n] = q;
        }
    } else {
        // repack, i over 512*512
        int i = (blk - 256) * 256 + tid;
        int k = i >> 9, n = i & 511;
        unsigned short h, l;
        int dst = n * 512 + k;
        split2(W_pre[i], h, l);   g_WpreT_hi[dst] = *(__nv_bfloat16*)&h; g_WpreT_lo[dst] = *(__nv_bfloat16*)&l;
        split2(W_actor[i], h, l); g_WactT_hi[dst] = *(__nv_bfloat16*)&h; g_WactT_lo[dst] = *(__nv_bfloat16*)&l;
        int a = n >> 6, dd = n & 63;
        int srcv = a * 32768 + k * 64 + dd;
        g_WvT_h16[dst] = __float2half_rn(Wv[srcv]);
        split2(Wsel[srcv], h, l); g_WselT_hi[dst] = *(__nv_bfloat16*)&h; g_WselT_lo[dst] = *(__nv_bfloat16*)&l;
        split2(Wk[i], h, l);      g_Wk_hi[i] = *(__nv_bfloat16*)&h;      g_Wk_lo[i] = *(__nv_bfloat16*)&l;
        int e2 = i >> 15, rem = i & 32767, ne = rem >> 6, ke = rem & 63;
        split2(W_enc[e2 * 32768 + ke * 512 + ne], h, l);
        g_WencT_hi[i] = *(__nv_bfloat16*)&h; g_WencT_lo[i] = *(__nv_bfloat16*)&l;
        if (i < 128 * 512) {
            int n2 = i & 127, k2 = i >> 7;
            float v = (n2 < 64) ? W_mean[k2 * 64 + n2] : W_logstd[k2 * 64 + (n2 - 64)];
            split2(v, h, l);
            g_WmlT_hi[n2 * 512 + k2] = *(__nv_bfloat16*)&h;
            g_WmlT_lo[n2 * 512 + k2] = *(__nv_bfloat16*)&l;
        }
        if (i < 128) g_bias_ml[i] = (i < 64) ? b_mean[i] : b_logstd[i - 64];
    }
}

// ---------------- snorm: fused BN finalize + normalize + bf16 split ----------------
__global__ void snorm_kernel(const float* __restrict__ states) {
    __shared__ float smu[64], srs[64];
    int e = blockIdx.x >> 10;                // 1024 blocks per encoder
    int tid = threadIdx.x;
    if (tid < 64) {
        float s = 0.f, q = 0.f;
        #pragma unroll 8
        for (int j = 0; j < 32; j++) {
            s += g_part_sum[(e * 32 + j) * 64 + tid];
            q += g_part_sq [(e * 32 + j) * 64 + tid];
        }
        float mean = s * (1.f / B_);
        float var  = q * (1.f / B_) - mean * mean;
        smu[tid] = mean;
        srs[tid] = 1.f / sqrtf(var + 1e-5f);
    }
    __syncthreads();
    size_t i = (size_t)blockIdx.x * 256 + tid;   // over EB*64/4
    float4 v = ((const float4*)states)[i];
    int n = (int)(i & 15) * 4;
    v.x = (v.x - smu[n + 0]) * srs[n + 0];
    v.y = (v.y - smu[n + 1]) * srs[n + 1];
    v.z = (v.z - smu[n + 2]) * srs[n + 2];
    v.w = (v.w - smu[n + 3]) * srs[n + 3];
    unsigned short hh[4], ll[4];
    split2(v.x, hh[0], ll[0]); split2(v.y, hh[1], ll[1]);
    split2(v.z, hh[2], ll[2]); split2(v.w, hh[3], ll[3]);
    *(uint2*)&g_sn_hi[i * 4] = *(uint2*)hh;
    *(uint2*)&g_sn_lo[i * 4] = *(uint2*)ll;
}

__global__ void cvt_pa_kernel(const float* __restrict__ src) {
    size_t i = (size_t)blockIdx.x * 256 + threadIdx.x;
    float4 v = ((const float4*)src)[i];
    unsigned short hh[4], ll[4];
    split2(v.x, hh[0], ll[0]); split2(v.y, hh[1], ll[1]);
    split2(v.z, hh[2], ll[2]); split2(v.w, hh[3], ll[3]);
    *(uint2*)&g_pa_hi[i * 4] = *(uint2*)hh;
    *(uint2*)&g_pa_lo[i * 4] = *(uint2*)ll;
}

// ---------------- mma GEMM: C[M,512] = act(A[M,K] @ B^T + bias) ----------------
// F16MODE: A fp16 hi/lo, B single fp16 -> 2 mma terms. Else bf16x3.
// EMITH: epilogue hi/lo emission in fp16 (else bf16).
template<int ACT, bool HAS_BIAS, bool WRITE_F32, bool EMIT, bool PERENC, bool PERHEAD,
         bool HEADOUT, bool EMITH, bool F16MODE>
__global__ __launch_bounds__(256, 2) void mma_gemm(
    const __nv_bfloat16* __restrict__ Ahi, const __nv_bfloat16* __restrict__ Alo,
    const __nv_bfloat16* __restrict__ Bhi, const __nv_bfloat16* __restrict__ Blo,
    const float* __restrict__ bias,
    float* __restrict__ C, float* __restrict__ C2,
    __nv_bfloat16* __restrict__ Chi, __nv_bfloat16* __restrict__ Clo,
    int K, int lda)
{
    extern __shared__ char smem[];
    const int tid = threadIdx.x;
    const int lane = tid & 31, wid = tid >> 5;
    const int m0 = blockIdx.y * 128, n0 = blockIdx.x * 128;
    const int wm = (wid & 3) * 32, wn = (wid >> 2) * 64;

    if constexpr (PERENC) {
        int e = m0 >> 14;
        Bhi += (size_t)e * 512 * K;
        Blo += (size_t)e * 512 * K;
        if constexpr (HAS_BIAS) bias += e * 512;
    }
    if constexpr (PERHEAD) {
        int z = blockIdx.z;
        Ahi += z * 64; Alo += z * 64;
        Bhi += (size_t)z * 512 * K;
        Blo += (size_t)z * 512 * K;
        size_t co = (size_t)z * B_ * 512;
        if constexpr (WRITE_F32) C += co;
        if constexpr (EMIT) { Chi += co; Clo += co; }
    }

    uint32_t sb = smem_u32(smem);
    const int prow = tid >> 1, ph = tid & 1;
    const __nv_bfloat16* pA0 = Ahi + (size_t)(m0 + prow) * lda + ph * 16;
    const __nv_bfloat16* pA1 = Alo + (size_t)(m0 + prow) * lda + ph * 16;
    const __nv_bfloat16* pB0 = Bhi + (size_t)(n0 + prow) * K + ph * 16;
    const __nv_bfloat16* pB1 = Blo + (size_t)(n0 + prow) * K + ph * 16;
    const uint32_t d0 = swz(prow, ph * 2), d1 = swz(prow, ph * 2 + 1);

    auto prefetch = [&](int buf, int kc) {
        uint32_t base = sb + buf * 32768;
        CP16(base + d0,          (const char*)(pA0 + kc * 32));
        CP16(base + d1,          (const char*)(pA0 + kc * 32 + 8));
        CP16(base + 8192 + d0,   (const char*)(pA1 + kc * 32));
        CP16(base + 8192 + d1,   (const char*)(pA1 + kc * 32 + 8));
        CP16(base + 16384 + d0,  (const char*)(pB0 + kc * 32));
        CP16(base + 16384 + d1,  (const char*)(pB0 + kc * 32 + 8));
        if constexpr (!F16MODE) {
            CP16(base + 24576 + d0,  (const char*)(pB1 + kc * 32));
            CP16(base + 24576 + d1,  (const char*)(pB1 + kc * 32 + 8));
        }
        asm volatile("cp.async.commit_group;");
    };

    float d[2][8][4] = {};
    const int lrow = lane & 7, grp = lane >> 3;

    auto compute = [&](int buf) {
        uint32_t base = sb + buf * 32768;
        #pragma unroll
        for (int s = 0; s < 2; s++) {
            uint32_t ahi[2][4], alo[2][4];
            #pragma unroll
            for (int i = 0; i < 2; i++) {
                int row = wm + i * 16 + (grp & 1) * 8 + lrow;
                int g = s * 2 + (grp >> 1);
                uint32_t off = swz(row, g);
                ldsm4(ahi[i], base + off);
                ldsm4(alo[i], base + 8192 + off);
            }
            #pragma unroll
            for (int j = 0; j < 4; j++) {
                int row = wn + j * 16 + (grp >> 1) * 8 + lrow;
                int g = s * 2 + (grp & 1);
                uint32_t off = swz(row, g);
                uint32_t bh[4];
                ldsm4(bh, base + 16384 + off);
                if constexpr (F16MODE) {
                    #pragma unroll
                    for (int i = 0; i < 2; i++) {
                        mma_fp16(d[i][j*2],     ahi[i], bh);
                        mma_fp16(d[i][j*2 + 1], ahi[i], bh + 2);
                        mma_fp16(d[i][j*2],     alo[i], bh);
                        mma_fp16(d[i][j*2 + 1], alo[i], bh + 2);
                    }
                } else {
                    #pragma unroll
                    for (int i = 0; i < 2; i++) {
                        mma_bf16(d[i][j*2],     ahi[i], bh);
                        mma_bf16(d[i][j*2 + 1], ahi[i], bh + 2);
                        mma_bf16(d[i][j*2],     alo[i], bh);
                        mma_bf16(d[i][j*2 + 1], alo[i], bh + 2);
                    }
                    uint32_t bl[4];
                    ldsm4(bl, base + 24576 + off);
                    #pragma unroll
                    for (int i = 0; i < 2; i++) {
                        mma_bf16(d[i][j*2],     ahi[i], bl);
                        mma_bf16(d[i][j*2 + 1], ahi[i], bl + 2);
                    }
                }
            }
        }
    };

    // 3-stage ring: prefetch distance 2, one barrier per chunk.
    const int NCH = K >> 5;
    prefetch(0, 0);
    if (NCH > 1) prefetch(1, 1);
    for (int kc = 0; kc < NCH; kc++) {
        if (kc + 1 < NCH) asm volatile("cp.async.wait_group 1;");
        else              asm volatile("cp.async.wait_group 0;");
        __syncthreads();
        if (kc + 2 < NCH) prefetch((kc + 2) % 3, kc + 2);
        compute(kc % 3);
    }
    __syncthreads();

    // epilogue
    float* stage = (float*)smem;   // [128][132]
    #pragma unroll
    for (int i = 0; i < 2; i++)
        #pragma unroll
        for (int j = 0; j < 8; j++) {
            int r = wm + i * 16 + (lane >> 2);
            int cc = wn + j * 8 + (lane & 3) * 2;
            stage[r * 132 + cc]       = d[i][j][0];
            stage[r * 132 + cc + 1]   = d[i][j][1];
            stage[(r + 8) * 132 + cc]     = d[i][j][2];
            stage[(r + 8) * 132 + cc + 1] = d[i][j][3];
        }
    __syncthreads();
    #pragma unroll
    for (int k2 = 0; k2 < 16; k2++) {
        int s = tid + k2 * 256;
        int row = s >> 5, q = s & 31;
        float4 v = *(const float4*)&stage[row * 132 + q * 4];
        int col = n0 + q * 4;
        float o[4] = {v.x, v.y, v.z, v.w};
        if constexpr (HAS_BIAS) {
            o[0] += bias[col]; o[1] += bias[col + 1];
            o[2] += bias[col + 2]; o[3] += bias[col + 3];
        }
        if constexpr (HEADOUT) {
            size_t r = (size_t)(m0 + row);
            if (col < 64) {
                *(float4*)&C[r * 64 + col] = make_float4(o[0], o[1], o[2], o[3]);
            } else {
                #pragma unroll
                for (int c2 = 0; c2 < 4; c2++) o[c2] = fminf(fmaxf(o[c2], -20.f), 2.f);
                *(float4*)&C2[r * 64 + col - 64] = make_float4(o[0], o[1], o[2], o[3]);
            }
        } else {
            #pragma unroll
            for (int c2 = 0; c2 < 4; c2++) o[c2] = act_fn<ACT>(o[c2]);
            size_t idx = (size_t)(m0 + row) * 512 + col;
            if constexpr (WRITE_F32)
                *(float4*)&C[idx] = make_float4(o[0], o[1], o[2], o[3]);
            if constexpr (EMIT) {
                unsigned short hh[4], ll[4];
                if constexpr (EMITH) {
                    split2h(o[0], hh[0], ll[0]); split2h(o[1], hh[1], ll[1]);
                    split2h(o[2], hh[2], ll[2]); split2h(o[3], hh[3], ll[3]);
                } else {
                    split2(o[0], hh[0], ll[0]); split2(o[1], hh[1], ll[1]);
                    split2(o[2], hh[2], ll[2]); split2(o[3], hh[3], ll[3]);
                }
                *(uint2*)&Chi[idx] = *(uint2*)hh;
                *(uint2*)&Clo[idx] = *(uint2*)ll;
            }
        }
    }
}

// ---------------- attention: register-blocked logits + softmax + weighted vals ----------------
__global__ __launch_bounds__(128) void attn_kernel(float* __restrict__ actor_in) {
    __shared__ float w_s[2][64];
    const int tid = threadIdx.x;
    const int wid = tid >> 5, lane = tid & 31;
    const int br = wid >> 1;
    const int ha = (wid & 1) * 4;
    const size_t b = (size_t)blockIdx.x * 2 + br;

    float acc[4][8];
    #pragma unroll
    for (int r = 0; r < 4; r++)
        #pragma unroll
        for (int e = 0; e < 8; e++) acc[r][e] = 0.f;

    #pragma unroll
    for (int it = 0; it < 4; it++) {
        const int h0 = it * 128 + lane * 4;
        float4 S[4];
        #pragma unroll
        for (int r = 0; r < 4; r++)
            S[r] = *(const float4*)&g_selk[((size_t)(ha + r) * B_ + b) * 512 + h0];
        #pragma unroll
        for (int e = 0; e < 8; e++) {
            size_t idx = ((size_t)e * B_ + b) * 512 + h0;
            uint2 uh = *(const uint2*)&g_encs_hi[idx];
            uint2 ul = *(const uint2*)&g_encs_lo[idx];
            __half2 h01 = *(__half2*)&uh.x;
            __half2 h23 = *(__half2*)&uh.y;
            __half2 l01 = *(__half2*)&ul.x;
            __half2 l23 = *(__half2*)&ul.y;
            float E0 = __half2float(h01.x) + __half2float(l01.x);
            float E1 = __half2float(h01.y) + __half2float(l01.y);
            float E2 = __half2float(h23.x) + __half2float(l23.x);
            float E3 = __half2float(h23.y) + __half2float(l23.y);
            #pragma unroll
            for (int r = 0; r < 4; r++) {
                acc[r][e] = fmaf(S[r].x, E0, acc[r][e]);
                acc[r][e] = fmaf(S[r].y, E1, acc[r][e]);
                acc[r][e] = fmaf(S[r].z, E2, acc[r][e]);
                acc[r][e] = fmaf(S[r].w, E3, acc[r][e]);
            }
        }
    }
    #pragma unroll
    for (int off = 16; off >= 1; off >>= 1)
        #pragma unroll
        for (int r = 0; r < 4; r++)
            #pragma unroll
            for (int e = 0; e < 8; e++)
                acc[r][e] += __shfl_xor_sync(0xffffffffu, acc[r][e], off);

    if (lane == 0) {
        #pragma unroll
        for (int r = 0; r < 4; r++) {
            float lg[8];
            float mx = -1e30f;
            #pragma unroll
            for (int e = 0; e < 8; e++) { lg[e] = acc[r][e] * 0.125f; mx = fmaxf(mx, lg[e]); }
            float s = 0.f, ex[8];
            #pragma unroll
            for (int e = 0; e < 8; e++) { ex[e] = expf(lg[e] - mx); s += ex[e]; }
            float inv = 1.f / s;
            #pragma unroll
            for (int e = 0; e < 8; e++) w_s[br][(ha + r) * 8 + e] = ex[e] * inv;
        }
    }
    __syncthreads();

    const int r2 = tid >> 6, j = tid & 63;
    const size_t b2 = (size_t)blockIdx.x * 2 + r2;
    #pragma unroll
    for (int m = 0; m < 8; m++) {
        int c = m * 64 + j;
        float a2 = 0.f;
        #pragma unroll
        for (int ee = 0; ee < 8; ee++)
            a2 = fmaf(w_s[r2][m * 8 + ee], g_vals[((size_t)ee * B_ + b2) * 512 + c], a2);
        actor_in[b2 * 512 + c] = a2;
        unsigned short hh, ll;
        split2(a2, hh, ll);
        g_attn_hi[b2 * 512 + c] = *(__nv_bfloat16*)&hh;
        g_attn_lo[b2 * 512 + c] = *(__nv_bfloat16*)&ll;
    }
}

// ---------------- launch ----------------
#define MMA_SMEM 98304

extern "C" void kernel_launch(void* const* d_in, const int* in_sizes, int n_in,
                              void* d_out, int out_size) {
    const float* states      = (const float*)d_in[0];
    const float* pre_actions = (const float*)d_in[1];
    const float* W_enc       = (const float*)d_in[2];
    const float* b_enc       = (const float*)d_in[3];
    const float* W_pre       = (const float*)d_in[4];
    const float* b_pre       = (const float*)d_in[5];
    const float* Wk          = (const float*)d_in[6];
    const float* Wsel        = (const float*)d_in[7];
    const float* Wv          = (const float*)d_in[8];
    const float* bv          = (const float*)d_in[9];
    const float* W_actor     = (const float*)d_in[10];
    const float* b_actor     = (const float*)d_in[11];
    const float* W_mean      = (const float*)d_in[12];
    const float* b_mean      = (const float*)d_in[13];
    const float* W_logstd    = (const float*)d_in[14];
    const float* b_logstd    = (const float*)d_in[15];

    float* out        = (float*)d_out;
    float* out_mean   = out;
    float* out_logstd = out + (size_t)B_ * NAG;
    float* out_actor  = out + (size_t)2 * B_ * NAG;

    float *vals, *selk, *bias_ml;
    __half *encs_hi, *encs_lo, *WvT_h16;
    __nv_bfloat16 *sn_hi, *sn_lo, *pa_hi, *pa_lo;
    __nv_bfloat16 *pre_hi, *pre_lo, *sel_hi, *sel_lo, *attn_hi, *attn_lo, *x_hi, *x_lo;
    __nv_bfloat16 *WencT_hi, *WencT_lo, *WpreT_hi, *WpreT_lo, *WselT_hi, *WselT_lo;
    __nv_bfloat16 *WactT_hi, *WactT_lo, *Wk_hi, *Wk_lo, *WmlT_hi, *WmlT_lo;
    cudaGetSymbolAddress((void**)&vals,    g_vals);
    cudaGetSymbolAddress((void**)&selk,    g_selk);
    cudaGetSymbolAddress((void**)&bias_ml, g_bias_ml);
    cudaGetSymbolAddress((void**)&encs_hi, g_encs_hi);
    cudaGetSymbolAddress((void**)&encs_lo, g_encs_lo);
    cudaGetSymbolAddress((void**)&WvT_h16, g_WvT_h16);
    cudaGetSymbolAddress((void**)&sn_hi,   g_sn_hi);
    cudaGetSymbolAddress((void**)&sn_lo,   g_sn_lo);
    cudaGetSymbolAddress((void**)&pa_hi,   g_pa_hi);
    cudaGetSymbolAddress((void**)&pa_lo,   g_pa_lo);
    cudaGetSymbolAddress((void**)&pre_hi,  g_pre_hi);
    cudaGetSymbolAddress((void**)&pre_lo,  g_pre_lo);
    cudaGetSymbolAddress((void**)&sel_hi,  g_sel_hi);
    cudaGetSymbolAddress((void**)&sel_lo,  g_sel_lo);
    cudaGetSymbolAddress((void**)&attn_hi, g_attn_hi);
    cudaGetSymbolAddress((void**)&attn_lo, g_attn_lo);
    cudaGetSymbolAddress((void**)&x_hi,    g_x_hi);
    cudaGetSymbolAddress((void**)&x_lo,    g_x_lo);
    cudaGetSymbolAddress((void**)&WencT_hi, g_WencT_hi);
    cudaGetSymbolAddress((void**)&WencT_lo, g_WencT_lo);
    cudaGetSymbolAddress((void**)&WpreT_hi, g_WpreT_hi);
    cudaGetSymbolAddress((void**)&WpreT_lo, g_WpreT_lo);
    cudaGetSymbolAddress((void**)&WselT_hi, g_WselT_hi);
    cudaGetSymbolAddress((void**)&WselT_lo, g_WselT_lo);
    cudaGetSymbolAddress((void**)&WactT_hi, g_WactT_hi);
    cudaGetSymbolAddress((void**)&WactT_lo, g_WactT_lo);
    cudaGetSymbolAddress((void**)&Wk_hi,   g_Wk_hi);
    cudaGetSymbolAddress((void**)&Wk_lo,   g_Wk_lo);
    cudaGetSymbolAddress((void**)&WmlT_hi, g_WmlT_hi);
    cudaGetSymbolAddress((void**)&WmlT_lo, g_WmlT_lo);

    auto enc_k  = mma_gemm<1, true,  false, true,  true,  false, false, true,  false>;
    auto vals_k = mma_gemm<1, true,  true,  false, false, false, false, false, true>;
    auto pre_k  = mma_gemm<1, true,  false, true,  false, false, false, false, false>;
    auto sel_k  = mma_gemm<0, false, false, true,  false, false, false, false, false>;
    auto selk_k = mma_gemm<0, false, true,  false, false, true,  false, false, false>;
    auto x_k    = mma_gemm<2, true,  false, true,  false, false, false, false, false>;
    auto ml_k   = mma_gemm<0, true,  false, false, false, false, true,  false, false>;
    cudaFuncSetAttribute(enc_k,  cudaFuncAttributeMaxDynamicSharedMemorySize, MMA_SMEM);
    cudaFuncSetAttribute(vals_k, cudaFuncAttributeMaxDynamicSharedMemorySize, MMA_SMEM);
    cudaFuncSetAttribute(pre_k,  cudaFuncAttributeMaxDynamicSharedMemorySize, MMA_SMEM);
    cudaFuncSetAttribute(sel_k,  cudaFuncAttributeMaxDynamicSharedMemorySize, MMA_SMEM);
    cudaFuncSetAttribute(selk_k, cudaFuncAttributeMaxDynamicSharedMemorySize, MMA_SMEM);
    cudaFuncSetAttribute(x_k,    cudaFuncAttributeMaxDynamicSharedMemorySize, MMA_SMEM);
    cudaFuncSetAttribute(ml_k,   cudaFuncAttributeMaxDynamicSharedMemorySize, MMA_SMEM);

    // launch 1: bn partials + weight repack (fused)
    prep_kernel<<<1280, 256>>>(states, Wk, Wv, Wsel, W_pre, W_actor, W_enc,
                               W_mean, W_logstd, b_mean, b_logstd);
    // launch 2: BN finalize + normalize + split
    snorm_kernel<<<8192, 256>>>(states);
    // launch 3: encs = leaky(snorm @ W_enc + b_enc), K=64, per-encoder; emit fp16 hi/lo
    enc_k<<<dim3(4, 1024), 256, MMA_SMEM>>>(sn_hi, sn_lo, WencT_hi, WencT_lo, b_enc,
                                            nullptr, nullptr,
                                            (__nv_bfloat16*)encs_hi, (__nv_bfloat16*)encs_lo, 64, 64);
    // launch 4 (profiled slot): vals = leaky(encs @ Wv + bv); fp16 2-term split
    vals_k<<<dim3(4, 1024), 256, MMA_SMEM>>>((const __nv_bfloat16*)encs_hi, (const __nv_bfloat16*)encs_lo,
                                             (const __nv_bfloat16*)WvT_h16, nullptr, bv,
                                             vals, nullptr, nullptr, nullptr, 512, 512);
    // pre_actions conversion
    cvt_pa_kernel<<<8192, 256>>>(pre_actions);
    // pre = leaky(pre_actions @ W_pre + b_pre)
    pre_k<<<dim3(4, 128), 256, MMA_SMEM>>>(pa_hi, pa_lo, WpreT_hi, WpreT_lo, b_pre,
                                           nullptr, nullptr, pre_hi, pre_lo, 512, 512);
    // sel = pre @ Wsel
    sel_k<<<dim3(4, 128), 256, MMA_SMEM>>>(pre_hi, pre_lo, WselT_hi, WselT_lo, nullptr,
                                           nullptr, nullptr, sel_hi, sel_lo, 512, 512);
    // selk[a] = sel[:, a*64:+64] @ Wk[a]^T, K=64, per-head; fp32
    selk_k<<<dim3(4, 128, 8), 256, MMA_SMEM>>>(sel_hi, sel_lo, Wk_hi, Wk_lo, nullptr,
                                               selk, nullptr, nullptr, nullptr, 64, 512);
    // attention -> actor_in
    attn_kernel<<<B_ / 2, 128>>>(out_actor);
    // x = relu(actor_in @ W_actor + b_actor)
    x_k<<<dim3(4, 128), 256, MMA_SMEM>>>(attn_hi, attn_lo, WactT_hi, WactT_lo, b_actor,
                                         nullptr, nullptr, x_hi, x_lo, 512, 512);
    // mean | log_std fused
    ml_k<<<dim3(1, 128), 256, MMA_SMEM>>>(x_hi, x_lo, WmlT_hi, WmlT_lo, bias_ml,
                                          out_mean, out_logstd, nullptr, nullptr, 512, 512);
}

// round 17
// speedup vs baseline: 3.6920x; 1.0845x over previous
#include <cuda_runtime.h>
#include <cuda_bf16.h>
#include <cuda_fp16.h>
#include <math.h>
#include <stdint.h>

#define E_ 8
#define B_ 16384
#define NAG 64
#define H_ 512
#define A_ 8
#define D_ 64
#define EB (E_*B_)

// ---------------- scratch (device globals; no allocation allowed) ----------------
__device__ __half g_encs_hi[(size_t)EB * H_];           // fp16 split
__device__ __half g_encs_lo[(size_t)EB * H_];
__device__ float g_vals[(size_t)EB * H_];
__device__ float g_selk[(size_t)A_ * B_ * H_];
__device__ __half g_x_hi[(size_t)B_ * H_];
__device__ __half g_x_lo[(size_t)B_ * H_];
__device__ __nv_bfloat16 g_sn_hi[(size_t)EB * 64];      // normalized states (bf16 split)
__device__ __nv_bfloat16 g_sn_lo[(size_t)EB * 64];
__device__ __half g_pa_hi[(size_t)B_ * H_];             // pre_actions fp16 split
__device__ __half g_pa_lo[(size_t)B_ * H_];
__device__ __half g_pre_hi[(size_t)B_ * H_];
__device__ __half g_pre_lo[(size_t)B_ * H_];
__device__ __nv_bfloat16 g_sel_hi[(size_t)B_ * H_];     // bf16 (selk stays bf16x3)
__device__ __nv_bfloat16 g_sel_lo[(size_t)B_ * H_];
__device__ __half g_attn_hi[(size_t)B_ * H_];
__device__ __half g_attn_lo[(size_t)B_ * H_];
// weights, [n][k] k-major
__device__ __nv_bfloat16 g_WencT_hi[E_ * H_ * 64];
__device__ __nv_bfloat16 g_WencT_lo[E_ * H_ * 64];
__device__ __half g_WpreT_h16[H_ * H_];
__device__ __half g_WselT_h16[H_ * H_];
__device__ __half g_WvT_h16[H_ * H_];
__device__ __half g_WactT_h16[H_ * H_];
__device__ __nv_bfloat16 g_Wk_hi[A_ * H_ * D_];
__device__ __nv_bfloat16 g_Wk_lo[A_ * H_ * D_];
__device__ __half g_WmlT_h16[128 * H_];
__device__ float g_bias_ml[128];
__device__ float g_part_sum[E_ * 32 * 64];
__device__ float g_part_sq[E_ * 32 * 64];

// ---------------- helpers ----------------
__device__ __forceinline__ uint32_t smem_u32(const void* p) {
    uint32_t a;
    asm("{ .reg .u64 t; cvta.to.shared.u64 t, %1; cvt.u32.u64 %0, t; }" : "=r"(a) : "l"(p));
    return a;
}
__device__ __forceinline__ void split2(float v, unsigned short& h, unsigned short& l) {
    __nv_bfloat16 bh = __float2bfloat16(v);
    __nv_bfloat16 bl = __float2bfloat16(v - __bfloat162float(bh));
    h = *(unsigned short*)&bh;
    l = *(unsigned short*)&bl;
}
__device__ __forceinline__ void split2h(float v, unsigned short& h, unsigned short& l) {
    __half bh = __float2half_rn(v);
    __half bl = __float2half_rn(v - __half2float(bh));
    h = *(unsigned short*)&bh;
    l = *(unsigned short*)&bl;
}
template<int ACT>
__device__ __forceinline__ float act_fn(float v) {
    if constexpr (ACT == 1) return v >= 0.f ? v : 0.01f * v;
    else if constexpr (ACT == 2) return fmaxf(v, 0.f);
    else if constexpr (ACT == 3) return fminf(fmaxf(v, -20.f), 2.f);
    else return v;
}
#define CP16(dst, src) asm volatile("cp.async.cg.shared.global [%0], [%1], 16;" :: "r"(dst), "l"(src))
__device__ __forceinline__ void ldsm4(uint32_t* r, uint32_t a) {
    asm volatile("ldmatrix.sync.aligned.m8n8.x4.shared.b16 {%0,%1,%2,%3}, [%4];"
        : "=r"(r[0]), "=r"(r[1]), "=r"(r[2]), "=r"(r[3]) : "r"(a));
}
__device__ __forceinline__ void mma_bf16(float* d, const uint32_t* a, const uint32_t* b) {
    asm volatile("mma.sync.aligned.m16n8k16.row.col.f32.bf16.bf16.f32 "
        "{%0,%1,%2,%3}, {%4,%5,%6,%7}, {%8,%9}, {%0,%1,%2,%3};"
        : "+f"(d[0]), "+f"(d[1]), "+f"(d[2]), "+f"(d[3])
        : "r"(a[0]), "r"(a[1]), "r"(a[2]), "r"(a[3]), "r"(b[0]), "r"(b[1]));
}
__device__ __forceinline__ void mma_fp16(float* d, const uint32_t* a, const uint32_t* b) {
    asm volatile("mma.sync.aligned.m16n8k16.row.col.f32.f16.f16.f32 "
        "{%0,%1,%2,%3}, {%4,%5,%6,%7}, {%8,%9}, {%0,%1,%2,%3};"
        : "+f"(d[0]), "+f"(d[1]), "+f"(d[2]), "+f"(d[3])
        : "r"(a[0]), "r"(a[1]), "r"(a[2]), "r"(a[3]), "r"(b[0]), "r"(b[1]));
}
__device__ __forceinline__ uint32_t swz(int row, int g) {
    int l = row >> 1;
    int c = (g | ((row & 1) << 2)) ^ (l & 7);
    return (uint32_t)((l << 7) + (c << 4));
}

// ---------------- prep: bn partials + weight repack (one launch) ----------------
__global__ void prep_kernel(const float* __restrict__ states,
                            const float* __restrict__ Wk, const float* __restrict__ Wv,
                            const float* __restrict__ Wsel, const float* __restrict__ W_pre,
                            const float* __restrict__ W_actor, const float* __restrict__ W_enc,
                            const float* __restrict__ W_mean, const float* __restrict__ W_logstd,
                            const float* __restrict__ b_mean, const float* __restrict__ b_logstd) {
    int blk = blockIdx.x;
    int tid = threadIdx.x;
    if (blk < 256) {
        int e = blk >> 5, ch = blk & 31;
        int n = tid & 63, ty = tid >> 6;
        const float* base = states + ((size_t)e * B_ + (size_t)ch * 512) * 64;
        float s = 0.f, q = 0.f;
        for (int r = ty; r < 512; r += 4) {
            float v = base[(size_t)r * 64 + n];
            s += v; q += v * v;
        }
        __shared__ float ss[4][64], sq[4][64];
        ss[ty][n] = s; sq[ty][n] = q;
        __syncthreads();
        if (ty == 0) {
            s = ss[0][n] + ss[1][n] + ss[2][n] + ss[3][n];
            q = sq[0][n] + sq[1][n] + sq[2][n] + sq[3][n];
            g_part_sum[(e * 32 + ch) * 64 + n] = s;
            g_part_sq [(e * 32 + ch) * 64 + n] = q;
        }
    } else {
        int i = (blk - 256) * 256 + tid;     // over 512*512
        int k = i >> 9, n = i & 511;
        unsigned short h, l;
        int dst = n * 512 + k;
        g_WpreT_h16[dst] = __float2half_rn(W_pre[i]);
        g_WactT_h16[dst] = __float2half_rn(W_actor[i]);
        int a = n >> 6, dd = n & 63;
        int srcv = a * 32768 + k * 64 + dd;
        g_WvT_h16[dst]   = __float2half_rn(Wv[srcv]);
        g_WselT_h16[dst] = __float2half_rn(Wsel[srcv]);
        split2(Wk[i], h, l);
        g_Wk_hi[i] = *(__nv_bfloat16*)&h; g_Wk_lo[i] = *(__nv_bfloat16*)&l;
        int e2 = i >> 15, rem = i & 32767, ne = rem >> 6, ke = rem & 63;
        split2(W_enc[e2 * 32768 + ke * 512 + ne], h, l);
        g_WencT_hi[i] = *(__nv_bfloat16*)&h; g_WencT_lo[i] = *(__nv_bfloat16*)&l;
        if (i < 128 * 512) {
            int n2 = i & 127, k2 = i >> 7;
            float v = (n2 < 64) ? W_mean[k2 * 64 + n2] : W_logstd[k2 * 64 + (n2 - 64)];
            g_WmlT_h16[n2 * 512 + k2] = __float2half_rn(v);
        }
        if (i < 128) g_bias_ml[i] = (i < 64) ? b_mean[i] : b_logstd[i - 64];
    }
}

// ---------------- snorm: fused BN finalize + normalize + bf16 split ----------------
__global__ void snorm_kernel(const float* __restrict__ states) {
    __shared__ float smu[64], srs[64];
    int e = blockIdx.x >> 10;
    int tid = threadIdx.x;
    if (tid < 64) {
        float s = 0.f, q = 0.f;
        #pragma unroll 8
        for (int j = 0; j < 32; j++) {
            s += g_part_sum[(e * 32 + j) * 64 + tid];
            q += g_part_sq [(e * 32 + j) * 64 + tid];
        }
        float mean = s * (1.f / B_);
        float var  = q * (1.f / B_) - mean * mean;
        smu[tid] = mean;
        srs[tid] = 1.f / sqrtf(var + 1e-5f);
    }
    __syncthreads();
    size_t i = (size_t)blockIdx.x * 256 + tid;
    float4 v = ((const float4*)states)[i];
    int n = (int)(i & 15) * 4;
    v.x = (v.x - smu[n + 0]) * srs[n + 0];
    v.y = (v.y - smu[n + 1]) * srs[n + 1];
    v.z = (v.z - smu[n + 2]) * srs[n + 2];
    v.w = (v.w - smu[n + 3]) * srs[n + 3];
    unsigned short hh[4], ll[4];
    split2(v.x, hh[0], ll[0]); split2(v.y, hh[1], ll[1]);
    split2(v.z, hh[2], ll[2]); split2(v.w, hh[3], ll[3]);
    *(uint2*)&g_sn_hi[i * 4] = *(uint2*)hh;
    *(uint2*)&g_sn_lo[i * 4] = *(uint2*)ll;
}

__global__ void cvt_pa_kernel(const float* __restrict__ src) {
    size_t i = (size_t)blockIdx.x * 256 + threadIdx.x;
    float4 v = ((const float4*)src)[i];
    unsigned short hh[4], ll[4];
    split2h(v.x, hh[0], ll[0]); split2h(v.y, hh[1], ll[1]);
    split2h(v.z, hh[2], ll[2]); split2h(v.w, hh[3], ll[3]);
    *(uint2*)&g_pa_hi[i * 4] = *(uint2*)hh;
    *(uint2*)&g_pa_lo[i * 4] = *(uint2*)ll;
}

// ---------------- mma GEMM: C[M,512] = act(A[M,K] @ B^T + bias) ----------------
// F16MODE: A fp16 hi/lo, B single fp16 -> 2 mma terms. Else bf16x3.
// Compute restructured: j processed in pairs; full ahi sweep then alo sweep (dep distance 8).
template<int ACT, bool HAS_BIAS, bool WRITE_F32, bool EMIT, bool PERENC, bool PERHEAD,
         bool HEADOUT, bool EMITH, bool F16MODE>
__global__ __launch_bounds__(256, 2) void mma_gemm(
    const __nv_bfloat16* __restrict__ Ahi, const __nv_bfloat16* __restrict__ Alo,
    const __nv_bfloat16* __restrict__ Bhi, const __nv_bfloat16* __restrict__ Blo,
    const float* __restrict__ bias,
    float* __restrict__ C, float* __restrict__ C2,
    __nv_bfloat16* __restrict__ Chi, __nv_bfloat16* __restrict__ Clo,
    int K, int lda)
{
    extern __shared__ char smem[];
    const int tid = threadIdx.x;
    const int lane = tid & 31, wid = tid >> 5;
    const int m0 = blockIdx.y * 128, n0 = blockIdx.x * 128;
    const int wm = (wid & 3) * 32, wn = (wid >> 2) * 64;

    if constexpr (PERENC) {
        int e = m0 >> 14;
        Bhi += (size_t)e * 512 * K;
        Blo += (size_t)e * 512 * K;
        if constexpr (HAS_BIAS) bias += e * 512;
    }
    if constexpr (PERHEAD) {
        int z = blockIdx.z;
        Ahi += z * 64; Alo += z * 64;
        Bhi += (size_t)z * 512 * K;
        Blo += (size_t)z * 512 * K;
        size_t co = (size_t)z * B_ * 512;
        if constexpr (WRITE_F32) C += co;
        if constexpr (EMIT) { Chi += co; Clo += co; }
    }

    uint32_t sb = smem_u32(smem);
    const int prow = tid >> 1, ph = tid & 1;
    const __nv_bfloat16* pA0 = Ahi + (size_t)(m0 + prow) * lda + ph * 16;
    const __nv_bfloat16* pA1 = Alo + (size_t)(m0 + prow) * lda + ph * 16;
    const __nv_bfloat16* pB0 = Bhi + (size_t)(n0 + prow) * K + ph * 16;
    const __nv_bfloat16* pB1 = Blo + (size_t)(n0 + prow) * K + ph * 16;
    const uint32_t d0 = swz(prow, ph * 2), d1 = swz(prow, ph * 2 + 1);

    auto prefetch = [&](int buf, int kc) {
        uint32_t base = sb + buf * 32768;
        CP16(base + d0,          (const char*)(pA0 + kc * 32));
        CP16(base + d1,          (const char*)(pA0 + kc * 32 + 8));
        CP16(base + 8192 + d0,   (const char*)(pA1 + kc * 32));
        CP16(base + 8192 + d1,   (const char*)(pA1 + kc * 32 + 8));
        CP16(base + 16384 + d0,  (const char*)(pB0 + kc * 32));
        CP16(base + 16384 + d1,  (const char*)(pB0 + kc * 32 + 8));
        if constexpr (!F16MODE) {
            CP16(base + 24576 + d0,  (const char*)(pB1 + kc * 32));
            CP16(base + 24576 + d1,  (const char*)(pB1 + kc * 32 + 8));
        }
        asm volatile("cp.async.commit_group;");
    };

    float d[2][8][4] = {};
    const int lrow = lane & 7, grp = lane >> 3;

    auto compute = [&](int buf) {
        uint32_t base = sb + buf * 32768;
        #pragma unroll
        for (int s = 0; s < 2; s++) {
            uint32_t ahi[2][4], alo[2][4];
            #pragma unroll
            for (int i = 0; i < 2; i++) {
                int row = wm + i * 16 + (grp & 1) * 8 + lrow;
                int g = s * 2 + (grp >> 1);
                uint32_t off = swz(row, g);
                ldsm4(ahi[i], base + off);
                ldsm4(alo[i], base + 8192 + off);
            }
            #pragma unroll
            for (int jj = 0; jj < 2; jj++) {
                const int row0 = wn + (jj * 2) * 16 + (grp >> 1) * 8 + lrow;
                const int gB = s * 2 + (grp & 1);
                uint32_t b0[4], b1[4];
                ldsm4(b0, base + 16384 + swz(row0, gB));
                ldsm4(b1, base + 16384 + swz(row0 + 16, gB));
                if constexpr (F16MODE) {
                    #pragma unroll
                    for (int i = 0; i < 2; i++) {
                        mma_fp16(d[i][jj*4+0], ahi[i], b0);
                        mma_fp16(d[i][jj*4+1], ahi[i], b0 + 2);
                        mma_fp16(d[i][jj*4+2], ahi[i], b1);
                        mma_fp16(d[i][jj*4+3], ahi[i], b1 + 2);
                    }
                    #pragma unroll
                    for (int i = 0; i < 2; i++) {
                        mma_fp16(d[i][jj*4+0], alo[i], b0);
                        mma_fp16(d[i][jj*4+1], alo[i], b0 + 2);
                        mma_fp16(d[i][jj*4+2], alo[i], b1);
                        mma_fp16(d[i][jj*4+3], alo[i], b1 + 2);
                    }
                } else {
                    #pragma unroll
                    for (int i = 0; i < 2; i++) {
                        mma_bf16(d[i][jj*4+0], ahi[i], b0);
                        mma_bf16(d[i][jj*4+1], ahi[i], b0 + 2);
                        mma_bf16(d[i][jj*4+2], ahi[i], b1);
                        mma_bf16(d[i][jj*4+3], ahi[i], b1 + 2);
                    }
                    #pragma unroll
                    for (int i = 0; i < 2; i++) {
                        mma_bf16(d[i][jj*4+0], alo[i], b0);
                        mma_bf16(d[i][jj*4+1], alo[i], b0 + 2);
                        mma_bf16(d[i][jj*4+2], alo[i], b1);
                        mma_bf16(d[i][jj*4+3], alo[i], b1 + 2);
                    }
                    uint32_t c0[4], c1[4];
                    ldsm4(c0, base + 24576 + swz(row0, gB));
                    ldsm4(c1, base + 24576 + swz(row0 + 16, gB));
                    #pragma unroll
                    for (int i = 0; i < 2; i++) {
                        mma_bf16(d[i][jj*4+0], ahi[i], c0);
                        mma_bf16(d[i][jj*4+1], ahi[i], c0 + 2);
                        mma_bf16(d[i][jj*4+2], ahi[i], c1);
                        mma_bf16(d[i][jj*4+3], ahi[i], c1 + 2);
                    }
                }
            }
        }
    };

    // 3-stage ring: prefetch distance 2, one barrier per chunk.
    const int NCH = K >> 5;
    prefetch(0, 0);
    if (NCH > 1) prefetch(1, 1);
    for (int kc = 0; kc < NCH; kc++) {
        if (kc + 1 < NCH) asm volatile("cp.async.wait_group 1;");
        else              asm volatile("cp.async.wait_group 0;");
        __syncthreads();
        if (kc + 2 < NCH) prefetch((kc + 2) % 3, kc + 2);
        compute(kc % 3);
    }
    __syncthreads();

    // epilogue
    float* stage = (float*)smem;   // [128][132]
    #pragma unroll
    for (int i = 0; i < 2; i++)
        #pragma unroll
        for (int j = 0; j < 8; j++) {
            int r = wm + i * 16 + (lane >> 2);
            int cc = wn + j * 8 + (lane & 3) * 2;
            stage[r * 132 + cc]       = d[i][j][0];
            stage[r * 132 + cc + 1]   = d[i][j][1];
            stage[(r + 8) * 132 + cc]     = d[i][j][2];
            stage[(r + 8) * 132 + cc + 1] = d[i][j][3];
        }
    __syncthreads();
    #pragma unroll
    for (int k2 = 0; k2 < 16; k2++) {
        int s = tid + k2 * 256;
        int row = s >> 5, q = s & 31;
        float4 v = *(const float4*)&stage[row * 132 + q * 4];
        int col = n0 + q * 4;
        float o[4] = {v.x, v.y, v.z, v.w};
        if constexpr (HAS_BIAS) {
            o[0] += bias[col]; o[1] += bias[col + 1];
            o[2] += bias[col + 2]; o[3] += bias[col + 3];
        }
        if constexpr (HEADOUT) {
            size_t r = (size_t)(m0 + row);
            if (col < 64) {
                *(float4*)&C[r * 64 + col] = make_float4(o[0], o[1], o[2], o[3]);
            } else {
                #pragma unroll
                for (int c2 = 0; c2 < 4; c2++) o[c2] = fminf(fmaxf(o[c2], -20.f), 2.f);
                *(float4*)&C2[r * 64 + col - 64] = make_float4(o[0], o[1], o[2], o[3]);
            }
        } else {
            #pragma unroll
            for (int c2 = 0; c2 < 4; c2++) o[c2] = act_fn<ACT>(o[c2]);
            size_t idx = (size_t)(m0 + row) * 512 + col;
            if constexpr (WRITE_F32)
                *(float4*)&C[idx] = make_float4(o[0], o[1], o[2], o[3]);
            if constexpr (EMIT) {
                unsigned short hh[4], ll[4];
                if constexpr (EMITH) {
                    split2h(o[0], hh[0], ll[0]); split2h(o[1], hh[1], ll[1]);
                    split2h(o[2], hh[2], ll[2]); split2h(o[3], hh[3], ll[3]);
                } else {
                    split2(o[0], hh[0], ll[0]); split2(o[1], hh[1], ll[1]);
                    split2(o[2], hh[2], ll[2]); split2(o[3], hh[3], ll[3]);
                }
                *(uint2*)&Chi[idx] = *(uint2*)hh;
                *(uint2*)&Clo[idx] = *(uint2*)ll;
            }
        }
    }
}

// ---------------- attention: register-blocked logits + softmax + weighted vals ----------------
__global__ __launch_bounds__(128) void attn_kernel(float* __restrict__ actor_in) {
    __shared__ float w_s[2][64];
    const int tid = threadIdx.x;
    const int wid = tid >> 5, lane = tid & 31;
    const int br = wid >> 1;
    const int ha = (wid & 1) * 4;
    const size_t b = (size_t)blockIdx.x * 2 + br;

    float acc[4][8];
    #pragma unroll
    for (int r = 0; r < 4; r++)
        #pragma unroll
        for (int e = 0; e < 8; e++) acc[r][e] = 0.f;

    #pragma unroll
    for (int it = 0; it < 4; it++) {
        const int h0 = it * 128 + lane * 4;
        float4 S[4];
        #pragma unroll
        for (int r = 0; r < 4; r++)
            S[r] = *(const float4*)&g_selk[((size_t)(ha + r) * B_ + b) * 512 + h0];
        #pragma unroll
        for (int e = 0; e < 8; e++) {
            size_t idx = ((size_t)e * B_ + b) * 512 + h0;
            uint2 uh = *(const uint2*)&g_encs_hi[idx];
            uint2 ul = *(const uint2*)&g_encs_lo[idx];
            __half2 h01 = *(__half2*)&uh.x;
            __half2 h23 = *(__half2*)&uh.y;
            __half2 l01 = *(__half2*)&ul.x;
            __half2 l23 = *(__half2*)&ul.y;
            float E0 = __half2float(h01.x) + __half2float(l01.x);
            float E1 = __half2float(h01.y) + __half2float(l01.y);
            float E2 = __half2float(h23.x) + __half2float(l23.x);
            float E3 = __half2float(h23.y) + __half2float(l23.y);
            #pragma unroll
            for (int r = 0; r < 4; r++) {
                acc[r][e] = fmaf(S[r].x, E0, acc[r][e]);
                acc[r][e] = fmaf(S[r].y, E1, acc[r][e]);
                acc[r][e] = fmaf(S[r].z, E2, acc[r][e]);
                acc[r][e] = fmaf(S[r].w, E3, acc[r][e]);
            }
        }
    }
    #pragma unroll
    for (int off = 16; off >= 1; off >>= 1)
        #pragma unroll
        for (int r = 0; r < 4; r++)
            #pragma unroll
            for (int e = 0; e < 8; e++)
                acc[r][e] += __shfl_xor_sync(0xffffffffu, acc[r][e], off);

    if (lane == 0) {
        #pragma unroll
        for (int r = 0; r < 4; r++) {
            float lg[8];
            float mx = -1e30f;
            #pragma unroll
            for (int e = 0; e < 8; e++) { lg[e] = acc[r][e] * 0.125f; mx = fmaxf(mx, lg[e]); }
            float s = 0.f, ex[8];
            #pragma unroll
            for (int e = 0; e < 8; e++) { ex[e] = expf(lg[e] - mx); s += ex[e]; }
            float inv = 1.f / s;
            #pragma unroll
            for (int e = 0; e < 8; e++) w_s[br][(ha + r) * 8 + e] = ex[e] * inv;
        }
    }
    __syncthreads();

    const int r2 = tid >> 6, j = tid & 63;
    const size_t b2 = (size_t)blockIdx.x * 2 + r2;
    #pragma unroll
    for (int m = 0; m < 8; m++) {
        int c = m * 64 + j;
        float a2 = 0.f;
        #pragma unroll
        for (int ee = 0; ee < 8; ee++)
            a2 = fmaf(w_s[r2][m * 8 + ee], g_vals[((size_t)ee * B_ + b2) * 512 + c], a2);
        actor_in[b2 * 512 + c] = a2;
        unsigned short hh, ll;
        split2h(a2, hh, ll);
        g_attn_hi[b2 * 512 + c] = *(__half*)&hh;
        g_attn_lo[b2 * 512 + c] = *(__half*)&ll;
    }
}

// ---------------- launch ----------------
#define MMA_SMEM 98304

extern "C" void kernel_launch(void* const* d_in, const int* in_sizes, int n_in,
                              void* d_out, int out_size) {
    const float* states      = (const float*)d_in[0];
    const float* pre_actions = (const float*)d_in[1];
    const float* W_enc       = (const float*)d_in[2];
    const float* b_enc       = (const float*)d_in[3];
    const float* W_pre       = (const float*)d_in[4];
    const float* b_pre       = (const float*)d_in[5];
    const float* Wk          = (const float*)d_in[6];
    const float* Wsel        = (const float*)d_in[7];
    const float* Wv          = (const float*)d_in[8];
    const float* bv          = (const float*)d_in[9];
    const float* W_actor     = (const float*)d_in[10];
    const float* b_actor     = (const float*)d_in[11];
    const float* W_mean      = (const float*)d_in[12];
    const float* b_mean      = (const float*)d_in[13];
    const float* W_logstd    = (const float*)d_in[14];
    const float* b_logstd    = (const float*)d_in[15];

    float* out        = (float*)d_out;
    float* out_mean   = out;
    float* out_logstd = out + (size_t)B_ * NAG;
    float* out_actor  = out + (size_t)2 * B_ * NAG;

    float *vals, *selk, *bias_ml;
    __half *encs_hi, *encs_lo, *WvT_h16, *WpreT_h16, *WselT_h16, *WactT_h16, *WmlT_h16;
    __half *pa_hi, *pa_lo, *pre_hi, *pre_lo, *attn_hi, *attn_lo, *x_hi, *x_lo;
    __nv_bfloat16 *sn_hi, *sn_lo, *sel_hi, *sel_lo;
    __nv_bfloat16 *WencT_hi, *WencT_lo, *Wk_hi, *Wk_lo;
    cudaGetSymbolAddress((void**)&vals,    g_vals);
    cudaGetSymbolAddress((void**)&selk,    g_selk);
    cudaGetSymbolAddress((void**)&bias_ml, g_bias_ml);
    cudaGetSymbolAddress((void**)&encs_hi, g_encs_hi);
    cudaGetSymbolAddress((void**)&encs_lo, g_encs_lo);
    cudaGetSymbolAddress((void**)&WvT_h16, g_WvT_h16);
    cudaGetSymbolAddress((void**)&WpreT_h16, g_WpreT_h16);
    cudaGetSymbolAddress((void**)&WselT_h16, g_WselT_h16);
    cudaGetSymbolAddress((void**)&WactT_h16, g_WactT_h16);
    cudaGetSymbolAddress((void**)&WmlT_h16, g_WmlT_h16);
    cudaGetSymbolAddress((void**)&sn_hi,   g_sn_hi);
    cudaGetSymbolAddress((void**)&sn_lo,   g_sn_lo);
    cudaGetSymbolAddress((void**)&pa_hi,   g_pa_hi);
    cudaGetSymbolAddress((void**)&pa_lo,   g_pa_lo);
    cudaGetSymbolAddress((void**)&pre_hi,  g_pre_hi);
    cudaGetSymbolAddress((void**)&pre_lo,  g_pre_lo);
    cudaGetSymbolAddress((void**)&sel_hi,  g_sel_hi);
    cudaGetSymbolAddress((void**)&sel_lo,  g_sel_lo);
    cudaGetSymbolAddress((void**)&attn_hi, g_attn_hi);
    cudaGetSymbolAddress((void**)&attn_lo, g_attn_lo);
    cudaGetSymbolAddress((void**)&x_hi,    g_x_hi);
    cudaGetSymbolAddress((void**)&x_lo,    g_x_lo);
    cudaGetSymbolAddress((void**)&WencT_hi, g_WencT_hi);
    cudaGetSymbolAddress((void**)&WencT_lo, g_WencT_lo);
    cudaGetSymbolAddress((void**)&Wk_hi,   g_Wk_hi);
    cudaGetSymbolAddress((void**)&Wk_lo,   g_Wk_lo);

    // ACT, BIAS, WF32, EMIT, PERENC, PERHEAD, HEADOUT, EMITH, F16MODE
    auto enc_k  = mma_gemm<1, true,  false, true,  true,  false, false, true,  false>;
    auto vals_k = mma_gemm<1, true,  true,  false, false, false, false, false, true>;
    auto pre_k  = mma_gemm<1, true,  false, true,  false, false, false, true,  true>;
    auto sel_k  = mma_gemm<0, false, false, true,  false, false, false, false, true>;
    auto selk_k = mma_gemm<0, false, true,  false, false, true,  false, false, false>;
    auto x_k    = mma_gemm<2, true,  false, true,  false, false, false, true,  true>;
    auto ml_k   = mma_gemm<0, true,  false, false, false, false, true,  false, true>;
    cudaFuncSetAttribute(enc_k,  cudaFuncAttributeMaxDynamicSharedMemorySize, MMA_SMEM);
    cudaFuncSetAttribute(vals_k, cudaFuncAttributeMaxDynamicSharedMemorySize, MMA_SMEM);
    cudaFuncSetAttribute(pre_k,  cudaFuncAttributeMaxDynamicSharedMemorySize, MMA_SMEM);
    cudaFuncSetAttribute(sel_k,  cudaFuncAttributeMaxDynamicSharedMemorySize, MMA_SMEM);
    cudaFuncSetAttribute(selk_k, cudaFuncAttributeMaxDynamicSharedMemorySize, MMA_SMEM);
    cudaFuncSetAttribute(x_k,    cudaFuncAttributeMaxDynamicSharedMemorySize, MMA_SMEM);
    cudaFuncSetAttribute(ml_k,   cudaFuncAttributeMaxDynamicSharedMemorySize, MMA_SMEM);

    // launch 1: bn partials + weight repack (fused)
    prep_kernel<<<1280, 256>>>(states, Wk, Wv, Wsel, W_pre, W_actor, W_enc,
                               W_mean, W_logstd, b_mean, b_logstd);
    // launch 2: BN finalize + normalize + split
    snorm_kernel<<<8192, 256>>>(states);
    // launch 3: encs = leaky(snorm @ W_enc + b_enc), bf16x3, emit fp16 hi/lo
    enc_k<<<dim3(4, 1024), 256, MMA_SMEM>>>(sn_hi, sn_lo, WencT_hi, WencT_lo, b_enc,
                                            nullptr, nullptr,
                                            (__nv_bfloat16*)encs_hi, (__nv_bfloat16*)encs_lo, 64, 64);
    // launch 4 (profiled slot): vals = leaky(encs @ Wv + bv); fp16 2-term
    vals_k<<<dim3(4, 1024), 256, MMA_SMEM>>>((const __nv_bfloat16*)encs_hi, (const __nv_bfloat16*)encs_lo,
                                             (const __nv_bfloat16*)WvT_h16, nullptr, bv,
                                             vals, nullptr, nullptr, nullptr, 512, 512);
    // pre_actions conversion (fp16 split)
    cvt_pa_kernel<<<8192, 256>>>(pre_actions);
    // pre = leaky(pre_actions @ W_pre + b_pre); fp16 2-term, emit fp16
    pre_k<<<dim3(4, 128), 256, MMA_SMEM>>>((const __nv_bfloat16*)pa_hi, (const __nv_bfloat16*)pa_lo,
                                           (const __nv_bfloat16*)WpreT_h16, nullptr, b_pre,
                                           nullptr, nullptr,
                                           (__nv_bfloat16*)pre_hi, (__nv_bfloat16*)pre_lo, 512, 512);
    // sel = pre @ Wsel; fp16 2-term, emit bf16 (selk consumes bf16)
    sel_k<<<dim3(4, 128), 256, MMA_SMEM>>>((const __nv_bfloat16*)pre_hi, (const __nv_bfloat16*)pre_lo,
                                           (const __nv_bfloat16*)WselT_h16, nullptr, nullptr,
                                           nullptr, nullptr, sel_hi, sel_lo, 512, 512);
    // selk[a] = sel[:, a*64:+64] @ Wk[a]^T; bf16x3, K=64, per-head; fp32
    selk_k<<<dim3(4, 128, 8), 256, MMA_SMEM>>>(sel_hi, sel_lo, Wk_hi, Wk_lo, nullptr,
                                               selk, nullptr, nullptr, nullptr, 64, 512);
    // attention -> actor_in (+ fp16 hi/lo for actor GEMM)
    attn_kernel<<<B_ / 2, 128>>>(out_actor);
    // x = relu(actor_in @ W_actor + b_actor); fp16 2-term, emit fp16
    x_k<<<dim3(4, 128), 256, MMA_SMEM>>>((const __nv_bfloat16*)attn_hi, (const __nv_bfloat16*)attn_lo,
                                         (const __nv_bfloat16*)WactT_h16, nullptr, b_actor,
                                         nullptr, nullptr,
                                         (__nv_bfloat16*)x_hi, (__nv_bfloat16*)x_lo, 512, 512);
    // mean | log_std fused; fp16 2-term
    ml_k<<<dim3(1, 128), 256, MMA_SMEM>>>((const __nv_bfloat16*)x_hi, (const __nv_bfloat16*)x_lo,
                                          (const __nv_bfloat16*)WmlT_h16, nullptr, bias_ml,
                                          out_mean, out_logstd, nullptr, nullptr, 512, 512);
}